// round 1
// baseline (speedup 1.0000x reference)
#include <cuda_runtime.h>
#include <math.h>

#define Nn 100000
#define Ee 1600000
#define EPt (Ee + Nn)          // edges incl. self loops = 1,700,000
#define OFF_EI (Nn * 32)       // 3,200,000
#define OFF_ALPHA (OFF_EI + 2 * EPt)  // 6,600,000

// ---------------- scratch (no allocations allowed) ----------------
__device__ float    g_h[Nn * 128];     // layer1 features h, later reused for h1 (post-ELU)
__device__ float    g_out1[Nn * 128];  // unnormalized aggregate layer1
__device__ float    g_als1[Nn * 4];
__device__ float    g_ald1[Nn * 4];
__device__ float    g_deg[Nn];
__device__ float    g_ns1[Nn * 4];     // per-node sum of s1 (for self-loop mean attr)
__device__ float    g_ns2[Nn];
__device__ float    g_s1[Ee * 4];      // edge_attr . v1e  per head
__device__ float    g_s2[Ee];
__device__ float    g_e1[EPt * 4];     // layer1 logits, then reused as-is (p computed on the fly)
__device__ unsigned g_m1[Nn * 4];      // encoded segment max
__device__ float    g_z1[Nn * 4];
__device__ float    g_h2f[Nn * 32];    // layer2 transformed features
__device__ float    g_als2[Nn];
__device__ float    g_ald2[Nn];
__device__ float    g_e2[EPt];
__device__ unsigned g_m2[Nn];
__device__ float    g_z2[Nn];
__device__ float    g_out2[Nn * 32];
__device__ float    g_v1e[16 * 4];     // [ed][h]
__device__ float    g_v2e[16];

// monotone float <-> uint encoding for atomicMax on floats (handles negatives)
__device__ __forceinline__ unsigned enc_f(float f) {
    int i = __float_as_int(f);
    return (i >= 0) ? ((unsigned)i | 0x80000000u) : ~(unsigned)i;
}
__device__ __forceinline__ float dec_f(unsigned u) {
    int i = (u & 0x80000000u) ? (int)(u & 0x7FFFFFFFu) : (int)(~u);
    return __int_as_float(i);
}
__device__ __forceinline__ float elu_f(float v) { return v > 0.f ? v : expm1f(v); }
__device__ __forceinline__ float lrelu_f(float v) { return v > 0.f ? v : 0.2f * v; }

// ---------------- kernels ----------------

// v1e[ed][h] = sum_c W1e[ed, h*32+c] * a1_edge[h, c];  v2e[ed] = sum_c W2e[ed, c] * a2_edge[c]
__global__ void prep_v(const float* __restrict__ W1e, const float* __restrict__ a1e,
                       const float* __restrict__ W2e, const float* __restrict__ a2e) {
    int t = threadIdx.x;
    if (t < 64) {
        int ed = t >> 2, h = t & 3;
        float s = 0.f;
        #pragma unroll
        for (int c = 0; c < 32; c++) s += W1e[ed * 128 + h * 32 + c] * a1e[h * 32 + c];
        g_v1e[t] = s;
    }
    if (t < 16) {
        float s = 0.f;
        #pragma unroll
        for (int c = 0; c < 32; c++) s += W2e[t * 32 + c] * a2e[c];
        g_v2e[t] = s;
    }
}

// per-edge: s1, s2, deg, node sums for self-loop mean attr
__global__ void edge_prep(const int* __restrict__ ei, const float* __restrict__ eattr) {
    int e = blockIdx.x * blockDim.x + threadIdx.x;
    if (e >= Ee) return;
    int dst = ei[Ee + e];
    float a[16];
    const float4* p = (const float4*)(eattr + (size_t)e * 16);
    #pragma unroll
    for (int q = 0; q < 4; q++) {
        float4 v = p[q];
        a[q * 4 + 0] = v.x; a[q * 4 + 1] = v.y; a[q * 4 + 2] = v.z; a[q * 4 + 3] = v.w;
    }
    float s[4] = {0.f, 0.f, 0.f, 0.f};
    float s2v = 0.f;
    #pragma unroll
    for (int ed = 0; ed < 16; ed++) {
        float av = a[ed];
        #pragma unroll
        for (int h = 0; h < 4; h++) s[h] += av * g_v1e[ed * 4 + h];
        s2v += av * g_v2e[ed];
    }
    *(float4*)(g_s1 + (size_t)e * 4) = make_float4(s[0], s[1], s[2], s[3]);
    g_s2[e] = s2v;
    atomicAdd(&g_deg[dst], 1.f);
    #pragma unroll
    for (int h = 0; h < 4; h++) atomicAdd(&g_ns1[dst * 4 + h], s[h]);
    atomicAdd(&g_ns2[dst], s2v);
}

// h = x @ W1 ; als1/ald1 per head. 16 nodes per 128-thread block.
__global__ void gemm1(const float* __restrict__ x, const float* __restrict__ W1,
                      const float* __restrict__ a_src, const float* __restrict__ a_dst) {
    __shared__ float xs[16][128];
    int n0 = blockIdx.x * 16;
    int tid = threadIdx.x;
    #pragma unroll
    for (int i = 0; i < 16; i++) {
        int n = n0 + i;
        xs[i][tid] = (n < Nn) ? x[(size_t)n * 128 + tid] : 0.f;
    }
    __syncthreads();
    float acc[16];
    #pragma unroll
    for (int i = 0; i < 16; i++) acc[i] = 0.f;
    for (int k = 0; k < 128; k++) {
        float w = W1[k * 128 + tid];
        #pragma unroll
        for (int i = 0; i < 16; i++) acc[i] += w * xs[i][k];
    }
    float as = a_src[tid], ad = a_dst[tid];
    int head = tid >> 5;
    for (int i = 0; i < 16; i++) {
        int n = n0 + i;
        if (n >= Nn) break;
        g_h[(size_t)n * 128 + tid] = acc[i];
        float s = acc[i] * as, d = acc[i] * ad;
        #pragma unroll
        for (int off = 16; off; off >>= 1) {
            s += __shfl_down_sync(0xffffffffu, s, off);
            d += __shfl_down_sync(0xffffffffu, d, off);
        }
        if ((tid & 31) == 0) { g_als1[n * 4 + head] = s; g_ald1[n * 4 + head] = d; }
    }
}

__global__ void logits1(const int* __restrict__ ei) {
    int e = blockIdx.x * blockDim.x + threadIdx.x;
    if (e >= EPt) return;
    int src, dst;
    float base[4];
    if (e < Ee) {
        src = ei[e]; dst = ei[Ee + e];
        float4 sv = *(const float4*)(g_s1 + (size_t)e * 4);
        base[0] = sv.x; base[1] = sv.y; base[2] = sv.z; base[3] = sv.w;
    } else {
        int n = e - Ee;
        src = dst = n;
        float invd = 1.f / fmaxf(g_deg[n], 1.f);
        #pragma unroll
        for (int h = 0; h < 4; h++) base[h] = g_ns1[n * 4 + h] * invd;
    }
    float4 as = *(const float4*)(g_als1 + src * 4);
    float4 ad = *(const float4*)(g_ald1 + dst * 4);
    float sa[4] = {as.x, as.y, as.z, as.w};
    float da[4] = {ad.x, ad.y, ad.z, ad.w};
    #pragma unroll
    for (int h = 0; h < 4; h++) {
        float v = lrelu_f(sa[h] + da[h] + base[h]);
        g_e1[(size_t)e * 4 + h] = v;
        atomicMax(&g_m1[dst * 4 + h], enc_f(v));
    }
}

// warp-per-edge: p = exp(e - m[dst]); z += p; out1[dst] += p * h[src] (unnormalized)
__global__ void agg1(const int* __restrict__ ei) {
    int w = (blockIdx.x * blockDim.x + threadIdx.x) >> 5;
    int lane = threadIdx.x & 31;
    if (w >= EPt) return;
    int e = w, src, dst;
    if (e < Ee) { src = ei[e]; dst = ei[Ee + e]; }
    else { src = dst = e - Ee; }
    int hh = lane & 3;
    float ev = g_e1[(size_t)e * 4 + hh];
    float mv = dec_f(g_m1[dst * 4 + hh]);
    float p = __expf(ev - mv);
    if (lane < 4) atomicAdd(&g_z1[dst * 4 + lane], p);
    const float* hsrc = g_h + (size_t)src * 128;
    float* od = g_out1 + (size_t)dst * 128;
    #pragma unroll
    for (int t = 0; t < 4; t++) {
        float pt = __shfl_sync(0xffffffffu, p, t);
        atomicAdd(&od[t * 32 + lane], pt * hsrc[t * 32 + lane]);
    }
}

// h1 = elu(out1 / z1 + b1), written back into g_h
__global__ void node1(const float* __restrict__ b1) {
    int idx = blockIdx.x * blockDim.x + threadIdx.x;
    if (idx >= Nn * 128) return;
    int n = idx >> 7, j = idx & 127;
    float v = g_out1[idx] / g_z1[(n << 2) + (j >> 5)] + b1[j];
    g_h[idx] = elu_f(v);
}

// h2f = h1 @ W2 ; als2/ald2 scalars. 8 nodes per 256-thread block, W2 in smem.
__global__ void gemm2(const float* __restrict__ W2, const float* __restrict__ a2s,
                      const float* __restrict__ a2d) {
    __shared__ float hs[8][128];
    __shared__ float ws[128 * 32];
    int tid = threadIdx.x;
    int n0 = blockIdx.x * 8;
    for (int i = tid; i < 128 * 32; i += 256) ws[i] = W2[i];
    for (int i = tid; i < 8 * 128; i += 256) {
        int n = n0 + (i >> 7);
        hs[i >> 7][i & 127] = (n < Nn) ? g_h[(size_t)n * 128 + (i & 127)] : 0.f;
    }
    __syncthreads();
    int ni = tid >> 5, c = tid & 31;
    float acc = 0.f;
    #pragma unroll 8
    for (int k = 0; k < 128; k++) acc += ws[k * 32 + c] * hs[ni][k];
    int n = n0 + ni;
    if (n < Nn) {
        g_h2f[(size_t)n * 32 + c] = acc;
        float s = acc * a2s[c], d = acc * a2d[c];
        #pragma unroll
        for (int off = 16; off; off >>= 1) {
            s += __shfl_down_sync(0xffffffffu, s, off);
            d += __shfl_down_sync(0xffffffffu, d, off);
        }
        if (c == 0) { g_als2[n] = s; g_ald2[n] = d; }
    }
}

__global__ void logits2(const int* __restrict__ ei) {
    int e = blockIdx.x * blockDim.x + threadIdx.x;
    if (e >= EPt) return;
    int src, dst;
    float base;
    if (e < Ee) { src = ei[e]; dst = ei[Ee + e]; base = g_s2[e]; }
    else {
        int n = e - Ee; src = dst = n;
        base = g_ns2[n] / fmaxf(g_deg[n], 1.f);
    }
    float v = lrelu_f(g_als2[src] + g_ald2[dst] + base);
    g_e2[e] = v;
    atomicMax(&g_m2[dst], enc_f(v));
}

// warp-per-edge layer2 aggregation; writes unnormalized p to alpha output
__global__ void agg2(const int* __restrict__ ei, float* __restrict__ alpha_out) {
    int w = (blockIdx.x * blockDim.x + threadIdx.x) >> 5;
    int lane = threadIdx.x & 31;
    if (w >= EPt) return;
    int e = w, src, dst;
    if (e < Ee) { src = ei[e]; dst = ei[Ee + e]; }
    else { src = dst = e - Ee; }
    float p = __expf(g_e2[e] - dec_f(g_m2[dst]));
    if (lane == 0) { atomicAdd(&g_z2[dst], p); alpha_out[e] = p; }
    atomicAdd(&g_out2[(size_t)dst * 32 + lane], p * g_h2f[(size_t)src * 32 + lane]);
}

// h2 = elu(out2 / z2 + b2) -> d_out
__global__ void node2(const float* __restrict__ b2, float* __restrict__ out) {
    int idx = blockIdx.x * blockDim.x + threadIdx.x;
    if (idx >= Nn * 32) return;
    int n = idx >> 5, c = idx & 31;
    float v = g_out2[idx] / g_z2[n] + b2[c];
    out[idx] = elu_f(v);
}

// edge_index_sl (as float) + normalize alpha2
__global__ void finalize(const int* __restrict__ ei, float* __restrict__ out) {
    int e = blockIdx.x * blockDim.x + threadIdx.x;
    if (e >= EPt) return;
    int s, d;
    if (e < Ee) { s = ei[e]; d = ei[Ee + e]; }
    else { s = d = e - Ee; }
    out[OFF_EI + e] = (float)s;
    out[OFF_EI + EPt + e] = (float)d;
    out[OFF_ALPHA + e] = out[OFF_ALPHA + e] / g_z2[d];
}

extern "C" void kernel_launch(void* const* d_in, const int* in_sizes, int n_in,
                              void* d_out, int out_size) {
    const float* x    = (const float*)d_in[0];
    const int*   ei   = (const int*)  d_in[1];
    const float* eat  = (const float*)d_in[2];
    const float* W1   = (const float*)d_in[3];
    const float* W1e  = (const float*)d_in[4];
    const float* a1s  = (const float*)d_in[5];
    const float* a1d  = (const float*)d_in[6];
    const float* a1e  = (const float*)d_in[7];
    const float* b1   = (const float*)d_in[8];
    const float* W2   = (const float*)d_in[9];
    const float* W2e  = (const float*)d_in[10];
    const float* a2s  = (const float*)d_in[11];
    const float* a2d  = (const float*)d_in[12];
    const float* a2e  = (const float*)d_in[13];
    const float* b2   = (const float*)d_in[14];
    float* out = (float*)d_out;
    (void)in_sizes; (void)n_in; (void)out_size;

    void *p_deg, *p_ns1, *p_ns2, *p_z1, *p_z2, *p_out1, *p_out2, *p_m1, *p_m2;
    cudaGetSymbolAddress(&p_deg,  g_deg);
    cudaGetSymbolAddress(&p_ns1,  g_ns1);
    cudaGetSymbolAddress(&p_ns2,  g_ns2);
    cudaGetSymbolAddress(&p_z1,   g_z1);
    cudaGetSymbolAddress(&p_z2,   g_z2);
    cudaGetSymbolAddress(&p_out1, g_out1);
    cudaGetSymbolAddress(&p_out2, g_out2);
    cudaGetSymbolAddress(&p_m1,   g_m1);
    cudaGetSymbolAddress(&p_m2,   g_m2);

    cudaMemsetAsync(p_deg,  0, (size_t)Nn * 4);
    cudaMemsetAsync(p_ns1,  0, (size_t)Nn * 16);
    cudaMemsetAsync(p_ns2,  0, (size_t)Nn * 4);
    cudaMemsetAsync(p_z1,   0, (size_t)Nn * 16);
    cudaMemsetAsync(p_z2,   0, (size_t)Nn * 4);
    cudaMemsetAsync(p_out1, 0, (size_t)Nn * 512);
    cudaMemsetAsync(p_out2, 0, (size_t)Nn * 128);
    cudaMemsetAsync(p_m1,   0, (size_t)Nn * 16);   // encoded(-inf) > 0, every node has a self loop
    cudaMemsetAsync(p_m2,   0, (size_t)Nn * 4);

    prep_v<<<1, 64>>>(W1e, a1e, W2e, a2e);
    edge_prep<<<(Ee + 255) / 256, 256>>>(ei, eat);
    gemm1<<<(Nn + 15) / 16, 128>>>(x, W1, a1s, a1d);
    logits1<<<(EPt + 255) / 256, 256>>>(ei);
    agg1<<<(EPt + 7) / 8, 256>>>(ei);
    node1<<<(Nn * 128 + 255) / 256, 256>>>(b1);
    gemm2<<<(Nn + 7) / 8, 256>>>(W2, a2s, a2d);
    logits2<<<(EPt + 255) / 256, 256>>>(ei);
    agg2<<<(EPt + 7) / 8, 256>>>(ei, out + OFF_ALPHA);
    node2<<<(Nn * 32 + 255) / 256, 256>>>(b2, out);
    finalize<<<(EPt + 255) / 256, 256>>>(ei, out);
}

// round 2
// speedup vs baseline: 1.3334x; 1.3334x over previous
#include <cuda_runtime.h>
#include <math.h>

#define Nn 100000
#define Ee 1600000
#define EPt (Ee + Nn)                 // 1,700,000 edges incl. self loops
#define OFF_EI (Nn * 32)              // 3,200,000
#define OFF_ALPHA (OFF_EI + 2 * EPt)  // 6,600,000

// ---------------- scratch (no allocations allowed) ----------------
__device__ float    g_h[Nn * 128];     // layer1 transformed features h = x@W1
__device__ float    g_h1[Nn * 128];    // layer1 output (post softmax-agg + ELU)
__device__ float    g_als1[Nn * 4];
__device__ float    g_ald1[Nn * 4];
__device__ float    g_deg[Nn];
__device__ float    g_ns1[Nn * 4];     // per-node sum of s1 (self-loop mean attr)
__device__ float    g_ns2[Nn];
__device__ float    g_s1[Ee * 4];      // edge_attr . v1e per head
__device__ float    g_s2[Ee];
__device__ float    g_h2f[Nn * 32];    // layer2 transformed features
__device__ float    g_als2[Nn];
__device__ float    g_ald2[Nn];
__device__ float    g_z2[Nn];
__device__ float    g_v1e[16 * 4];
__device__ float    g_v2e[16];
// CSR structures
__device__ int      g_off[Nn + 1];
__device__ int      g_cursor[Nn];
__device__ int      g_csrc[EPt];       // src node per CSR slot
__device__ int      g_ceid[EPt];       // original edge id per CSR slot
__device__ float    g_ce1[EPt * 4];    // layer1 logits in CSR order

__device__ __forceinline__ float elu_f(float v) { return v > 0.f ? v : expm1f(v); }
__device__ __forceinline__ float lrelu_f(float v) { return v > 0.f ? v : 0.2f * v; }

// ---------------- kernels ----------------

__global__ void prep_v(const float* __restrict__ W1e, const float* __restrict__ a1e,
                       const float* __restrict__ W2e, const float* __restrict__ a2e) {
    int t = threadIdx.x;
    if (t < 64) {
        int ed = t >> 2, h = t & 3;
        float s = 0.f;
        #pragma unroll
        for (int c = 0; c < 32; c++) s += W1e[ed * 128 + h * 32 + c] * a1e[h * 32 + c];
        g_v1e[t] = s;
    }
    if (t < 16) {
        float s = 0.f;
        #pragma unroll
        for (int c = 0; c < 32; c++) s += W2e[t * 32 + c] * a2e[c];
        g_v2e[t] = s;
    }
}

// per-edge: s1, s2, deg, node sums for self-loop mean attr
__global__ void edge_prep(const int* __restrict__ ei, const float* __restrict__ eattr) {
    int e = blockIdx.x * blockDim.x + threadIdx.x;
    if (e >= Ee) return;
    int dst = ei[Ee + e];
    float a[16];
    const float4* p = (const float4*)(eattr + (size_t)e * 16);
    #pragma unroll
    for (int q = 0; q < 4; q++) {
        float4 v = p[q];
        a[q * 4 + 0] = v.x; a[q * 4 + 1] = v.y; a[q * 4 + 2] = v.z; a[q * 4 + 3] = v.w;
    }
    float s[4] = {0.f, 0.f, 0.f, 0.f};
    float s2v = 0.f;
    #pragma unroll
    for (int ed = 0; ed < 16; ed++) {
        float av = a[ed];
        #pragma unroll
        for (int h = 0; h < 4; h++) s[h] += av * g_v1e[ed * 4 + h];
        s2v += av * g_v2e[ed];
    }
    *(float4*)(g_s1 + (size_t)e * 4) = make_float4(s[0], s[1], s[2], s[3]);
    g_s2[e] = s2v;
    atomicAdd(&g_deg[dst], 1.f);
    #pragma unroll
    for (int h = 0; h < 4; h++) atomicAdd(&g_ns1[dst * 4 + h], s[h]);
    atomicAdd(&g_ns2[dst], s2v);
}

// h = x @ W1 ; als1/ald1 per head. 16 nodes per 128-thread block.
__global__ void gemm1(const float* __restrict__ x, const float* __restrict__ W1,
                      const float* __restrict__ a_src, const float* __restrict__ a_dst) {
    __shared__ float xs[16][128];
    int n0 = blockIdx.x * 16;
    int tid = threadIdx.x;
    #pragma unroll
    for (int i = 0; i < 16; i++) {
        int n = n0 + i;
        xs[i][tid] = (n < Nn) ? x[(size_t)n * 128 + tid] : 0.f;
    }
    __syncthreads();
    float acc[16];
    #pragma unroll
    for (int i = 0; i < 16; i++) acc[i] = 0.f;
    for (int k = 0; k < 128; k++) {
        float w = W1[k * 128 + tid];
        #pragma unroll
        for (int i = 0; i < 16; i++) acc[i] += w * xs[i][k];
    }
    float as = a_src[tid], ad = a_dst[tid];
    int head = tid >> 5;
    for (int i = 0; i < 16; i++) {
        int n = n0 + i;
        if (n >= Nn) break;
        g_h[(size_t)n * 128 + tid] = acc[i];
        float s = acc[i] * as, d = acc[i] * ad;
        #pragma unroll
        for (int off = 16; off; off >>= 1) {
            s += __shfl_down_sync(0xffffffffu, s, off);
            d += __shfl_down_sync(0xffffffffu, d, off);
        }
        if ((tid & 31) == 0) { g_als1[n * 4 + head] = s; g_ald1[n * 4 + head] = d; }
    }
}

// single-block exclusive scan of (deg+1) over all nodes -> g_off, g_cursor
__global__ void scan_k() {
    __shared__ int sh[1024];
    const int CH = 98;  // 1024*98 >= Nn
    int t = threadIdx.x;
    int base = t * CH;
    int s = 0;
    for (int i = 0; i < CH; i++) {
        int n = base + i;
        if (n < Nn) s += (int)g_deg[n] + 1;
    }
    sh[t] = s;
    __syncthreads();
    for (int off = 1; off < 1024; off <<= 1) {
        int v = (t >= off) ? sh[t - off] : 0;
        __syncthreads();
        sh[t] += v;
        __syncthreads();
    }
    int run = (t == 0) ? 0 : sh[t - 1];
    for (int i = 0; i < CH; i++) {
        int n = base + i;
        if (n < Nn) {
            g_off[n] = run;
            g_cursor[n] = run;
            run += (int)g_deg[n] + 1;
        }
    }
    if (t == 1023) g_off[Nn] = EPt;
}

// scatter edges into CSR slots + compute layer-1 logits in CSR order
__global__ void scatter_k(const int* __restrict__ ei) {
    int e = blockIdx.x * blockDim.x + threadIdx.x;
    if (e >= EPt) return;
    int src, dst;
    float b0, b1v, b2v, b3v;
    if (e < Ee) {
        src = ei[e]; dst = ei[Ee + e];
        float4 sv = *(const float4*)(g_s1 + (size_t)e * 4);
        b0 = sv.x; b1v = sv.y; b2v = sv.z; b3v = sv.w;
    } else {
        int n = e - Ee;
        src = dst = n;
        float invd = 1.f / fmaxf(g_deg[n], 1.f);
        b0 = g_ns1[n * 4 + 0] * invd;
        b1v = g_ns1[n * 4 + 1] * invd;
        b2v = g_ns1[n * 4 + 2] * invd;
        b3v = g_ns1[n * 4 + 3] * invd;
    }
    float4 as = *(const float4*)(g_als1 + (size_t)src * 4);
    float4 ad = *(const float4*)(g_ald1 + (size_t)dst * 4);
    int pos = atomicAdd(&g_cursor[dst], 1);
    float4 ev;
    ev.x = lrelu_f(as.x + ad.x + b0);
    ev.y = lrelu_f(as.y + ad.y + b1v);
    ev.z = lrelu_f(as.z + ad.z + b2v);
    ev.w = lrelu_f(as.w + ad.w + b3v);
    *(float4*)(g_ce1 + (size_t)pos * 4) = ev;
    g_csrc[pos] = src;
    g_ceid[pos] = e;
}

// warp-per-node layer1: softmax over neighbor logits + aggregate + bias + ELU
__global__ void agg1_csr(const float* __restrict__ b1) {
    int n = (blockIdx.x * blockDim.x + threadIdx.x) >> 5;
    if (n >= Nn) return;
    int lane = threadIdx.x & 31;
    int hh = lane & 3;       // head this lane evaluates logits for
    int sub = lane >> 2;     // edge sub-slot 0..7
    int beg = g_off[n], end = g_off[n + 1];

    // pass1: per-head max (coalesced: addr = i*4+hh == beg*4 + lane + 8k*4)
    float m = -1e30f;
    for (int i = beg + sub; i < end; i += 8)
        m = fmaxf(m, g_ce1[(size_t)i * 4 + hh]);
    m = fmaxf(m, __shfl_xor_sync(0xffffffffu, m, 4));
    m = fmaxf(m, __shfl_xor_sync(0xffffffffu, m, 8));
    m = fmaxf(m, __shfl_xor_sync(0xffffffffu, m, 16));

    // pass2: p = exp(e-m); z; acc[h] over channels (lane owns channel `lane` of each head)
    float acc0 = 0.f, acc1 = 0.f, acc2 = 0.f, acc3 = 0.f, zl = 0.f;
    for (int g = beg; g < end; g += 8) {
        int idx = g + sub;
        float p = 0.f;
        int src = 0;
        if (idx < end) {
            p = __expf(g_ce1[(size_t)idx * 4 + hh] - m);
            src = g_csrc[idx];
        }
        zl += p;
        int lim = min(8, end - g);
        for (int t = 0; t < lim; t++) {
            int   st = __shfl_sync(0xffffffffu, src, t * 4);
            float p0 = __shfl_sync(0xffffffffu, p, t * 4 + 0);
            float p1 = __shfl_sync(0xffffffffu, p, t * 4 + 1);
            float p2 = __shfl_sync(0xffffffffu, p, t * 4 + 2);
            float p3 = __shfl_sync(0xffffffffu, p, t * 4 + 3);
            const float* hs = g_h + (size_t)st * 128;
            acc0 += p0 * hs[lane];
            acc1 += p1 * hs[32 + lane];
            acc2 += p2 * hs[64 + lane];
            acc3 += p3 * hs[96 + lane];
        }
    }
    zl += __shfl_xor_sync(0xffffffffu, zl, 4);
    zl += __shfl_xor_sync(0xffffffffu, zl, 8);
    zl += __shfl_xor_sync(0xffffffffu, zl, 16);
    float z0 = __shfl_sync(0xffffffffu, zl, 0);
    float z1 = __shfl_sync(0xffffffffu, zl, 1);
    float z2 = __shfl_sync(0xffffffffu, zl, 2);
    float z3 = __shfl_sync(0xffffffffu, zl, 3);
    size_t o = (size_t)n * 128;
    g_h1[o + lane]      = elu_f(acc0 / z0 + b1[lane]);
    g_h1[o + 32 + lane] = elu_f(acc1 / z1 + b1[32 + lane]);
    g_h1[o + 64 + lane] = elu_f(acc2 / z2 + b1[64 + lane]);
    g_h1[o + 96 + lane] = elu_f(acc3 / z3 + b1[96 + lane]);
}

// h2f = h1 @ W2 ; als2/ald2 scalars. 8 nodes per 256-thread block, W2 in smem.
__global__ void gemm2(const float* __restrict__ W2, const float* __restrict__ a2s,
                      const float* __restrict__ a2d) {
    __shared__ float hs[8][128];
    __shared__ float ws[128 * 32];
    int tid = threadIdx.x;
    int n0 = blockIdx.x * 8;
    for (int i = tid; i < 128 * 32; i += 256) ws[i] = W2[i];
    for (int i = tid; i < 8 * 128; i += 256) {
        int n = n0 + (i >> 7);
        hs[i >> 7][i & 127] = (n < Nn) ? g_h1[(size_t)n * 128 + (i & 127)] : 0.f;
    }
    __syncthreads();
    int ni = tid >> 5, c = tid & 31;
    float acc = 0.f;
    #pragma unroll 8
    for (int k = 0; k < 128; k++) acc += ws[k * 32 + c] * hs[ni][k];
    int n = n0 + ni;
    if (n < Nn) {
        g_h2f[(size_t)n * 32 + c] = acc;
        float s = acc * a2s[c], d = acc * a2d[c];
        #pragma unroll
        for (int off = 16; off; off >>= 1) {
            s += __shfl_down_sync(0xffffffffu, s, off);
            d += __shfl_down_sync(0xffffffffu, d, off);
        }
        if (c == 0) { g_als2[n] = s; g_ald2[n] = d; }
    }
}

__device__ __forceinline__ float e2_of(int idx, int n, float ald2n, float invd) {
    int eid = g_ceid[idx];
    int src = g_csrc[idx];
    float base = (eid < Ee) ? g_s2[eid] : g_ns2[n] * invd;
    return lrelu_f(g_als2[src] + ald2n + base);
}

// warp-per-node layer2: logits + softmax + aggregate + outputs (h2 channels, alpha p, z2)
__global__ void agg2_csr(const float* __restrict__ b2, float* __restrict__ out) {
    int n = (blockIdx.x * blockDim.x + threadIdx.x) >> 5;
    if (n >= Nn) return;
    int lane = threadIdx.x & 31;
    int beg = g_off[n], end = g_off[n + 1];
    float ald2n = g_ald2[n];
    float invd = 1.f / fmaxf(g_deg[n], 1.f);

    // pass1: max
    float m = -1e30f;
    for (int i = beg + lane; i < end; i += 32)
        m = fmaxf(m, e2_of(i, n, ald2n, invd));
    #pragma unroll
    for (int off = 16; off; off >>= 1)
        m = fmaxf(m, __shfl_xor_sync(0xffffffffu, m, off));

    // pass2: p, z, aggregate, write unnormalized alpha
    float acc = 0.f, zl = 0.f;
    for (int g = beg; g < end; g += 32) {
        int idx = g + lane;
        float p = 0.f;
        int src = 0;
        if (idx < end) {
            p = __expf(e2_of(idx, n, ald2n, invd) - m);
            src = g_csrc[idx];
            out[OFF_ALPHA + g_ceid[idx]] = p;   // normalized later in finalize
        }
        zl += p;
        int lim = min(32, end - g);
        for (int t = 0; t < lim; t++) {
            float pt = __shfl_sync(0xffffffffu, p, t);
            int   st = __shfl_sync(0xffffffffu, src, t);
            acc += pt * g_h2f[(size_t)st * 32 + lane];
        }
    }
    #pragma unroll
    for (int off = 16; off; off >>= 1)
        zl += __shfl_xor_sync(0xffffffffu, zl, off);
    if (lane == 0) g_z2[n] = zl;
    out[(size_t)n * 32 + lane] = elu_f(acc / zl + b2[lane]);
}

// edge_index_sl (as float) + normalize alpha2
__global__ void finalize(const int* __restrict__ ei, float* __restrict__ out) {
    int e = blockIdx.x * blockDim.x + threadIdx.x;
    if (e >= EPt) return;
    int s, d;
    if (e < Ee) { s = ei[e]; d = ei[Ee + e]; }
    else { s = d = e - Ee; }
    out[OFF_EI + e] = (float)s;
    out[OFF_EI + EPt + e] = (float)d;
    out[OFF_ALPHA + e] = out[OFF_ALPHA + e] / g_z2[d];
}

extern "C" void kernel_launch(void* const* d_in, const int* in_sizes, int n_in,
                              void* d_out, int out_size) {
    const float* x    = (const float*)d_in[0];
    const int*   ei   = (const int*)  d_in[1];
    const float* eat  = (const float*)d_in[2];
    const float* W1   = (const float*)d_in[3];
    const float* W1e  = (const float*)d_in[4];
    const float* a1s  = (const float*)d_in[5];
    const float* a1d  = (const float*)d_in[6];
    const float* a1e  = (const float*)d_in[7];
    const float* b1   = (const float*)d_in[8];
    const float* W2   = (const float*)d_in[9];
    const float* W2e  = (const float*)d_in[10];
    const float* a2s  = (const float*)d_in[11];
    const float* a2d  = (const float*)d_in[12];
    const float* a2e  = (const float*)d_in[13];
    const float* b2   = (const float*)d_in[14];
    float* out = (float*)d_out;
    (void)in_sizes; (void)n_in; (void)out_size;

    void *p_deg, *p_ns1, *p_ns2;
    cudaGetSymbolAddress(&p_deg, g_deg);
    cudaGetSymbolAddress(&p_ns1, g_ns1);
    cudaGetSymbolAddress(&p_ns2, g_ns2);
    cudaMemsetAsync(p_deg, 0, (size_t)Nn * 4);
    cudaMemsetAsync(p_ns1, 0, (size_t)Nn * 16);
    cudaMemsetAsync(p_ns2, 0, (size_t)Nn * 4);

    prep_v<<<1, 64>>>(W1e, a1e, W2e, a2e);
    edge_prep<<<(Ee + 255) / 256, 256>>>(ei, eat);
    gemm1<<<(Nn + 15) / 16, 128>>>(x, W1, a1s, a1d);
    scan_k<<<1, 1024>>>();
    scatter_k<<<(EPt + 255) / 256, 256>>>(ei);
    agg1_csr<<<(Nn + 7) / 8, 256>>>(b1);
    gemm2<<<(Nn + 7) / 8, 256>>>(W2, a2s, a2d);
    agg2_csr<<<(Nn + 7) / 8, 256>>>(b2, out);
    finalize<<<(EPt + 255) / 256, 256>>>(ei, out);
}

// round 3
// speedup vs baseline: 1.6236x; 1.2177x over previous
#include <cuda_runtime.h>
#include <math.h>

#define Nn 100000
#define Ee 1600000
#define EPt (Ee + Nn)                 // 1,700,000 edges incl. self loops
#define OFF_EI (Nn * 32)              // 3,200,000
#define OFF_ALPHA (OFF_EI + 2 * EPt)  // 6,600,000
#define NB_SCAN ((Nn + 255) / 256)    // 391

// ---------------- scratch (no allocations allowed) ----------------
__device__ float    g_h[Nn * 128];     // layer1 transformed features h = x@W1
__device__ float    g_h1[Nn * 128];    // layer1 output (post softmax-agg + ELU)
__device__ float    g_als1[Nn * 4];
__device__ float    g_ald1[Nn * 4];
__device__ float    g_deg[Nn];
__device__ float    g_ns1[Nn * 4];     // per-node sum of s1 (self-loop mean attr)
__device__ float    g_ns2[Nn];
__device__ float    g_s1[Ee * 4];      // edge_attr . v1e per head
__device__ float    g_s2[Ee];
__device__ float    g_h2f[Nn * 32];    // layer2 transformed features
__device__ float    g_als2[Nn];
__device__ float    g_ald2[Nn];
__device__ float    g_m2[Nn];
__device__ float    g_z2[Nn];
__device__ float    g_v1e[16 * 4];
__device__ float    g_v2e[16];
// CSR structures
__device__ int      g_off[Nn + 1];
__device__ int      g_cursor[Nn];
__device__ int      g_csrc[EPt];       // src node per CSR slot
__device__ int      g_ceid[EPt];       // original edge id per CSR slot
__device__ float    g_ce1[EPt * 4];    // layer1 logits in CSR order; reused for layer2 logits
// scan scratch
__device__ int      g_pre[Nn];
__device__ int      g_bsum[512];
__device__ int      g_boff[512];

__device__ __forceinline__ float elu_f(float v) { return v > 0.f ? v : expm1f(v); }
__device__ __forceinline__ float lrelu_f(float v) { return v > 0.f ? v : 0.2f * v; }

// ---------------- kernels ----------------

__global__ void prep_v(const float* __restrict__ W1e, const float* __restrict__ a1e,
                       const float* __restrict__ W2e, const float* __restrict__ a2e) {
    int t = threadIdx.x;
    if (t < 64) {
        int ed = t >> 2, h = t & 3;
        float s = 0.f;
        #pragma unroll
        for (int c = 0; c < 32; c++) s += W1e[ed * 128 + h * 32 + c] * a1e[h * 32 + c];
        g_v1e[t] = s;
    }
    if (t < 16) {
        float s = 0.f;
        #pragma unroll
        for (int c = 0; c < 32; c++) s += W2e[t * 32 + c] * a2e[c];
        g_v2e[t] = s;
    }
}

// per-edge: s1, s2, deg, node sums for self-loop mean attr
__global__ void edge_prep(const int* __restrict__ ei, const float* __restrict__ eattr) {
    int e = blockIdx.x * blockDim.x + threadIdx.x;
    if (e >= Ee) return;
    int dst = ei[Ee + e];
    float a[16];
    const float4* p = (const float4*)(eattr + (size_t)e * 16);
    #pragma unroll
    for (int q = 0; q < 4; q++) {
        float4 v = p[q];
        a[q * 4 + 0] = v.x; a[q * 4 + 1] = v.y; a[q * 4 + 2] = v.z; a[q * 4 + 3] = v.w;
    }
    float s[4] = {0.f, 0.f, 0.f, 0.f};
    float s2v = 0.f;
    #pragma unroll
    for (int ed = 0; ed < 16; ed++) {
        float av = a[ed];
        #pragma unroll
        for (int h = 0; h < 4; h++) s[h] += av * g_v1e[ed * 4 + h];
        s2v += av * g_v2e[ed];
    }
    *(float4*)(g_s1 + (size_t)e * 4) = make_float4(s[0], s[1], s[2], s[3]);
    g_s2[e] = s2v;
    atomicAdd(&g_deg[dst], 1.f);
    #pragma unroll
    for (int h = 0; h < 4; h++) atomicAdd(&g_ns1[dst * 4 + h], s[h]);
    atomicAdd(&g_ns2[dst], s2v);
}

// h = x @ W1 ; als1/ald1 per head. 16 nodes per 128-thread block.
__global__ void gemm1(const float* __restrict__ x, const float* __restrict__ W1,
                      const float* __restrict__ a_src, const float* __restrict__ a_dst) {
    __shared__ float xs[16][128];
    int n0 = blockIdx.x * 16;
    int tid = threadIdx.x;
    #pragma unroll
    for (int i = 0; i < 16; i++) {
        int n = n0 + i;
        xs[i][tid] = (n < Nn) ? x[(size_t)n * 128 + tid] : 0.f;
    }
    __syncthreads();
    float acc[16];
    #pragma unroll
    for (int i = 0; i < 16; i++) acc[i] = 0.f;
    for (int k = 0; k < 128; k++) {
        float w = W1[k * 128 + tid];
        #pragma unroll
        for (int i = 0; i < 16; i++) acc[i] += w * xs[i][k];
    }
    float as = a_src[tid], ad = a_dst[tid];
    int head = tid >> 5;
    for (int i = 0; i < 16; i++) {
        int n = n0 + i;
        if (n >= Nn) break;
        g_h[(size_t)n * 128 + tid] = acc[i];
        float s = acc[i] * as, d = acc[i] * ad;
        #pragma unroll
        for (int off = 16; off; off >>= 1) {
            s += __shfl_down_sync(0xffffffffu, s, off);
            d += __shfl_down_sync(0xffffffffu, d, off);
        }
        if ((tid & 31) == 0) { g_als1[n * 4 + head] = s; g_ald1[n * 4 + head] = d; }
    }
}

// ---- parallel exclusive scan of (deg+1): 3 tiny kernels ----
__global__ void scan1() {
    __shared__ int sh[256];
    int t = threadIdx.x;
    int n = blockIdx.x * 256 + t;
    int val = (n < Nn) ? (int)g_deg[n] + 1 : 0;
    sh[t] = val;
    __syncthreads();
    for (int off = 1; off < 256; off <<= 1) {
        int v = (t >= off) ? sh[t - off] : 0;
        __syncthreads();
        sh[t] += v;
        __syncthreads();
    }
    if (n < Nn) g_pre[n] = sh[t] - val;
    if (t == 255) g_bsum[blockIdx.x] = sh[255];
}

__global__ void scan2() {
    __shared__ int sh[512];
    int t = threadIdx.x;
    int val = (t < NB_SCAN) ? g_bsum[t] : 0;
    sh[t] = val;
    __syncthreads();
    for (int off = 1; off < 512; off <<= 1) {
        int v = (t >= off) ? sh[t - off] : 0;
        __syncthreads();
        sh[t] += v;
        __syncthreads();
    }
    g_boff[t] = sh[t] - val;
}

__global__ void scan3() {
    int n = blockIdx.x * 256 + threadIdx.x;
    if (n >= Nn) return;
    int off = g_boff[blockIdx.x] + g_pre[n];
    g_off[n] = off;
    g_cursor[n] = off;
    if (n == 0) g_off[Nn] = EPt;
}

// scatter edges into CSR slots + compute layer-1 logits in CSR order
__global__ void scatter_k(const int* __restrict__ ei) {
    int e = blockIdx.x * blockDim.x + threadIdx.x;
    if (e >= EPt) return;
    int src, dst;
    float b0, b1v, b2v, b3v;
    if (e < Ee) {
        src = ei[e]; dst = ei[Ee + e];
        float4 sv = *(const float4*)(g_s1 + (size_t)e * 4);
        b0 = sv.x; b1v = sv.y; b2v = sv.z; b3v = sv.w;
    } else {
        int n = e - Ee;
        src = dst = n;
        float invd = 1.f / fmaxf(g_deg[n], 1.f);
        b0 = g_ns1[n * 4 + 0] * invd;
        b1v = g_ns1[n * 4 + 1] * invd;
        b2v = g_ns1[n * 4 + 2] * invd;
        b3v = g_ns1[n * 4 + 3] * invd;
    }
    float4 as = *(const float4*)(g_als1 + (size_t)src * 4);
    float4 ad = *(const float4*)(g_ald1 + (size_t)dst * 4);
    int pos = atomicAdd(&g_cursor[dst], 1);
    float4 ev;
    ev.x = lrelu_f(as.x + ad.x + b0);
    ev.y = lrelu_f(as.y + ad.y + b1v);
    ev.z = lrelu_f(as.z + ad.z + b2v);
    ev.w = lrelu_f(as.w + ad.w + b3v);
    *(float4*)(g_ce1 + (size_t)pos * 4) = ev;
    g_csrc[pos] = src;
    g_ceid[pos] = e;
}

// warp-per-node layer1: softmax over neighbor logits + aggregate + bias + ELU
__global__ void agg1_csr(const float* __restrict__ b1) {
    int n = (blockIdx.x * blockDim.x + threadIdx.x) >> 5;
    if (n >= Nn) return;
    int lane = threadIdx.x & 31;
    int hh = lane & 3;       // head this lane evaluates logits for
    int sub = lane >> 2;     // edge sub-slot 0..7
    int beg = g_off[n], end = g_off[n + 1];

    // pass1: per-head max (coalesced: addr = i*4+hh == beg*4 + lane + 8k*4)
    float m = -1e30f;
    for (int i = beg + sub; i < end; i += 8)
        m = fmaxf(m, g_ce1[(size_t)i * 4 + hh]);
    m = fmaxf(m, __shfl_xor_sync(0xffffffffu, m, 4));
    m = fmaxf(m, __shfl_xor_sync(0xffffffffu, m, 8));
    m = fmaxf(m, __shfl_xor_sync(0xffffffffu, m, 16));

    // pass2: p = exp(e-m); z; acc[h] over channels (lane owns channel `lane` of each head)
    float acc0 = 0.f, acc1 = 0.f, acc2 = 0.f, acc3 = 0.f, zl = 0.f;
    for (int g = beg; g < end; g += 8) {
        int idx = g + sub;
        float p = 0.f;
        int src = 0;
        if (idx < end) {
            p = __expf(g_ce1[(size_t)idx * 4 + hh] - m);
            src = g_csrc[idx];
        }
        zl += p;
        int lim = min(8, end - g);
        for (int t = 0; t < lim; t++) {
            int   st = __shfl_sync(0xffffffffu, src, t * 4);
            float p0 = __shfl_sync(0xffffffffu, p, t * 4 + 0);
            float p1 = __shfl_sync(0xffffffffu, p, t * 4 + 1);
            float p2 = __shfl_sync(0xffffffffu, p, t * 4 + 2);
            float p3 = __shfl_sync(0xffffffffu, p, t * 4 + 3);
            const float* hs = g_h + (size_t)st * 128;
            acc0 += p0 * hs[lane];
            acc1 += p1 * hs[32 + lane];
            acc2 += p2 * hs[64 + lane];
            acc3 += p3 * hs[96 + lane];
        }
    }
    zl += __shfl_xor_sync(0xffffffffu, zl, 4);
    zl += __shfl_xor_sync(0xffffffffu, zl, 8);
    zl += __shfl_xor_sync(0xffffffffu, zl, 16);
    float z0 = __shfl_sync(0xffffffffu, zl, 0);
    float z1 = __shfl_sync(0xffffffffu, zl, 1);
    float z2 = __shfl_sync(0xffffffffu, zl, 2);
    float z3 = __shfl_sync(0xffffffffu, zl, 3);
    size_t o = (size_t)n * 128;
    g_h1[o + lane]      = elu_f(acc0 / z0 + b1[lane]);
    g_h1[o + 32 + lane] = elu_f(acc1 / z1 + b1[32 + lane]);
    g_h1[o + 64 + lane] = elu_f(acc2 / z2 + b1[64 + lane]);
    g_h1[o + 96 + lane] = elu_f(acc3 / z3 + b1[96 + lane]);
}

// h2f = h1 @ W2 ; als2/ald2 scalars. 8 nodes per 256-thread block, W2 in smem.
__global__ void gemm2(const float* __restrict__ W2, const float* __restrict__ a2s,
                      const float* __restrict__ a2d) {
    __shared__ float hs[8][128];
    __shared__ float ws[128 * 32];
    int tid = threadIdx.x;
    int n0 = blockIdx.x * 8;
    for (int i = tid; i < 128 * 32; i += 256) ws[i] = W2[i];
    for (int i = tid; i < 8 * 128; i += 256) {
        int n = n0 + (i >> 7);
        hs[i >> 7][i & 127] = (n < Nn) ? g_h1[(size_t)n * 128 + (i & 127)] : 0.f;
    }
    __syncthreads();
    int ni = tid >> 5, c = tid & 31;
    float acc = 0.f;
    #pragma unroll 8
    for (int k = 0; k < 128; k++) acc += ws[k * 32 + c] * hs[ni][k];
    int n = n0 + ni;
    if (n < Nn) {
        g_h2f[(size_t)n * 32 + c] = acc;
        float s = acc * a2s[c], d = acc * a2d[c];
        #pragma unroll
        for (int off = 16; off; off >>= 1) {
            s += __shfl_down_sync(0xffffffffu, s, off);
            d += __shfl_down_sync(0xffffffffu, d, off);
        }
        if (c == 0) { g_als2[n] = s; g_ald2[n] = d; }
    }
}

// warp-per-node layer2: logits (computed once, cached in CSR buffer) + softmax + aggregate
__global__ void agg2_csr(const float* __restrict__ b2, float* __restrict__ out) {
    int n = (blockIdx.x * blockDim.x + threadIdx.x) >> 5;
    if (n >= Nn) return;
    int lane = threadIdx.x & 31;
    int beg = g_off[n], end = g_off[n + 1];
    float ald2n = g_ald2[n];
    float invd = 1.f / fmaxf(g_deg[n], 1.f);
    float slbase = g_ns2[n] * invd;

    // pass1: compute logits once, cache in CSR order (reuse g_ce1), track max
    float m = -1e30f;
    for (int i = beg + lane; i < end; i += 32) {
        int eid = g_ceid[i];
        int src = g_csrc[i];
        float base = (eid < Ee) ? g_s2[eid] : slbase;
        float v = lrelu_f(g_als2[src] + ald2n + base);
        g_ce1[i] = v;   // lane-private slot; re-read by the same lane in pass2
        m = fmaxf(m, v);
    }
    #pragma unroll
    for (int off = 16; off; off >>= 1)
        m = fmaxf(m, __shfl_xor_sync(0xffffffffu, m, off));

    // pass2: p, z, aggregate
    float acc = 0.f, zl = 0.f;
    for (int g = beg; g < end; g += 32) {
        int idx = g + lane;
        float p = 0.f;
        int src = 0;
        if (idx < end) {
            p = __expf(g_ce1[idx] - m);
            src = g_csrc[idx];
        }
        zl += p;
        int lim = min(32, end - g);
        for (int t = 0; t < lim; t++) {
            float pt = __shfl_sync(0xffffffffu, p, t);
            int   st = __shfl_sync(0xffffffffu, src, t);
            acc += pt * g_h2f[(size_t)st * 32 + lane];
        }
    }
    #pragma unroll
    for (int off = 16; off; off >>= 1)
        zl += __shfl_xor_sync(0xffffffffu, zl, off);
    if (lane == 0) { g_z2[n] = zl; g_m2[n] = m; }
    out[(size_t)n * 32 + lane] = elu_f(acc / zl + b2[lane]);
}

// edge_index_sl (as float) + alpha2 computed directly in original edge order
__global__ void finalize(const int* __restrict__ ei, float* __restrict__ out) {
    int e = blockIdx.x * blockDim.x + threadIdx.x;
    if (e >= EPt) return;
    int s, d;
    float base;
    if (e < Ee) {
        s = ei[e]; d = ei[Ee + e];
        base = g_s2[e];
    } else {
        s = d = e - Ee;
        base = g_ns2[d] / fmaxf(g_deg[d], 1.f);
    }
    float v = lrelu_f(g_als2[s] + g_ald2[d] + base);
    out[OFF_EI + e] = (float)s;
    out[OFF_EI + EPt + e] = (float)d;
    out[OFF_ALPHA + e] = __expf(v - g_m2[d]) / g_z2[d];
}

extern "C" void kernel_launch(void* const* d_in, const int* in_sizes, int n_in,
                              void* d_out, int out_size) {
    const float* x    = (const float*)d_in[0];
    const int*   ei   = (const int*)  d_in[1];
    const float* eat  = (const float*)d_in[2];
    const float* W1   = (const float*)d_in[3];
    const float* W1e  = (const float*)d_in[4];
    const float* a1s  = (const float*)d_in[5];
    const float* a1d  = (const float*)d_in[6];
    const float* a1e  = (const float*)d_in[7];
    const float* b1   = (const float*)d_in[8];
    const float* W2   = (const float*)d_in[9];
    const float* W2e  = (const float*)d_in[10];
    const float* a2s  = (const float*)d_in[11];
    const float* a2d  = (const float*)d_in[12];
    const float* a2e  = (const float*)d_in[13];
    const float* b2   = (const float*)d_in[14];
    float* out = (float*)d_out;
    (void)in_sizes; (void)n_in; (void)out_size;

    void *p_deg, *p_ns1, *p_ns2;
    cudaGetSymbolAddress(&p_deg, g_deg);
    cudaGetSymbolAddress(&p_ns1, g_ns1);
    cudaGetSymbolAddress(&p_ns2, g_ns2);
    cudaMemsetAsync(p_deg, 0, (size_t)Nn * 4);
    cudaMemsetAsync(p_ns1, 0, (size_t)Nn * 16);
    cudaMemsetAsync(p_ns2, 0, (size_t)Nn * 4);

    prep_v<<<1, 64>>>(W1e, a1e, W2e, a2e);
    edge_prep<<<(Ee + 255) / 256, 256>>>(ei, eat);
    gemm1<<<(Nn + 15) / 16, 128>>>(x, W1, a1s, a1d);
    scan1<<<NB_SCAN, 256>>>();
    scan2<<<1, 512>>>();
    scan3<<<NB_SCAN, 256>>>();
    scatter_k<<<(EPt + 255) / 256, 256>>>(ei);
    agg1_csr<<<(Nn + 7) / 8, 256>>>(b1);
    gemm2<<<(Nn + 7) / 8, 256>>>(W2, a2s, a2d);
    agg2_csr<<<(Nn + 7) / 8, 256>>>(b2, out);
    finalize<<<(EPt + 255) / 256, 256>>>(ei, out);
}

// round 4
// speedup vs baseline: 2.0522x; 1.2640x over previous
#include <cuda_runtime.h>
#include <cuda_fp16.h>
#include <math.h>

#define Nn 100000
#define Ee 1600000
#define EPt (Ee + Nn)                 // 1,700,000 edges incl. self loops
#define OFF_EI (Nn * 32)              // 3,200,000
#define OFF_ALPHA (OFF_EI + 2 * EPt)  // 6,600,000
#define NB_SCAN ((Nn + 255) / 256)    // 391

// ---------------- scratch (no allocations allowed) ----------------
__device__ __half2 g_hh[Nn * 64];      // layer1 features h = x@W1 (fp16, channel pairs)
__device__ __half2 g_h1h[Nn * 64];     // layer1 output h1 (fp16)
__device__ __half2 g_h2fh[Nn * 16];    // layer2 transformed features (fp16)
__device__ __align__(16) float g_als1[Nn * 4];
__device__ __align__(16) float g_ald1[Nn * 4];
__device__ float g_deg[Nn];
__device__ __align__(16) float g_ns1[Nn * 4];
__device__ float g_ns2[Nn];
__device__ __align__(16) float g_s1[Ee * 4];
__device__ float g_s2[Ee];
__device__ float g_als2[Nn];
__device__ float g_ald2[Nn];
__device__ float g_z2[Nn];
__device__ float g_v1e[64];
__device__ float g_v2e[16];
__device__ __align__(16) float g_A1s[128 * 4];  // (W1 . a1_src) per [k][h]
__device__ __align__(16) float g_A1d[128 * 4];
__device__ __align__(16) float g_A2s[128];
__device__ __align__(16) float g_A2d[128];
// CSR structures
__device__ int   g_off[Nn + 1];
__device__ int   g_cursor[Nn];
__device__ int   g_csrc[EPt];
__device__ __align__(16) float g_cp1[EPt * 4];  // exp(lrelu(logit1)) per head, CSR order
__device__ float g_cs2[EPt];                    // layer2 logit base, CSR order
// scan scratch
__device__ int g_pre[Nn];
__device__ int g_bsum[512];
__device__ int g_boff[512];

__device__ __forceinline__ float elu_f(float v) { return v > 0.f ? v : expm1f(v); }
__device__ __forceinline__ float lrelu_f(float v) { return v > 0.f ? v : 0.2f * v; }

// ---- packed fp32x2 helpers (sm_100+) ----
__device__ __forceinline__ unsigned long long pack2(float lo, float hi) {
    unsigned long long d;
    asm("mov.b64 %0, {%1, %2};" : "=l"(d) : "f"(lo), "f"(hi));
    return d;
}
__device__ __forceinline__ float2 unpack2(unsigned long long v) {
    float2 r;
    asm("mov.b64 {%0, %1}, %2;" : "=f"(r.x), "=f"(r.y) : "l"(v));
    return r;
}
__device__ __forceinline__ unsigned long long ffma2(unsigned long long a, unsigned long long b,
                                                    unsigned long long c) {
    unsigned long long d;
    asm("fma.rn.f32x2 %0, %1, %2, %3;" : "=l"(d) : "l"(a), "l"(b), "l"(c));
    return d;
}

// ---------------- kernels ----------------

// small precomputes: v1e/v2e (edge-attr logit vectors), A1s/A1d = W1 . a1, A2s/A2d = W2 . a2
__global__ void prep_all(const float* __restrict__ W1e, const float* __restrict__ a1e,
                         const float* __restrict__ W2e, const float* __restrict__ a2e,
                         const float* __restrict__ W1, const float* __restrict__ a1s,
                         const float* __restrict__ a1d, const float* __restrict__ W2,
                         const float* __restrict__ a2s, const float* __restrict__ a2d) {
    int t = threadIdx.x;  // 512 threads
    if (t < 64) {
        int ed = t >> 2, h = t & 3;
        float s = 0.f;
        #pragma unroll
        for (int c = 0; c < 32; c++) s += W1e[ed * 128 + h * 32 + c] * a1e[h * 32 + c];
        g_v1e[t] = s;
    }
    if (t < 16) {
        float s = 0.f;
        #pragma unroll
        for (int c = 0; c < 32; c++) s += W2e[t * 32 + c] * a2e[c];
        g_v2e[t] = s;
    }
    {
        int k = t >> 2, h = t & 3;
        float s = 0.f, d = 0.f;
        #pragma unroll
        for (int c = 0; c < 32; c++) {
            float w = W1[k * 128 + h * 32 + c];
            s += w * a1s[h * 32 + c];
            d += w * a1d[h * 32 + c];
        }
        g_A1s[t] = s;
        g_A1d[t] = d;
    }
    if (t < 128) {
        float s = 0.f, d = 0.f;
        #pragma unroll
        for (int c = 0; c < 32; c++) {
            float w = W2[t * 32 + c];
            s += w * a2s[c];
            d += w * a2d[c];
        }
        g_A2s[t] = s;
        g_A2d[t] = d;
    }
}

// per-edge: s1, s2, deg, node sums for self-loop mean attr
__global__ void edge_prep(const int* __restrict__ ei, const float* __restrict__ eattr) {
    int e = blockIdx.x * blockDim.x + threadIdx.x;
    if (e >= Ee) return;
    int dst = ei[Ee + e];
    float a[16];
    const float4* p = (const float4*)(eattr + (size_t)e * 16);
    #pragma unroll
    for (int q = 0; q < 4; q++) {
        float4 v = p[q];
        a[q * 4 + 0] = v.x; a[q * 4 + 1] = v.y; a[q * 4 + 2] = v.z; a[q * 4 + 3] = v.w;
    }
    float s[4] = {0.f, 0.f, 0.f, 0.f};
    float s2v = 0.f;
    #pragma unroll
    for (int ed = 0; ed < 16; ed++) {
        float av = a[ed];
        #pragma unroll
        for (int h = 0; h < 4; h++) s[h] += av * g_v1e[ed * 4 + h];
        s2v += av * g_v2e[ed];
    }
    *(float4*)(g_s1 + (size_t)e * 4) = make_float4(s[0], s[1], s[2], s[3]);
    g_s2[e] = s2v;
    atomicAdd(&g_deg[dst], 1.f);
    #pragma unroll
    for (int h = 0; h < 4; h++) atomicAdd(&g_ns1[dst * 4 + h], s[h]);
    atomicAdd(&g_ns2[dst], s2v);
}

// h = x @ W1 (fp32x2 packed math, fp16 output) + als1/ald1 via precomputed A1s/A1d.
// 32 nodes per 128-thread block, node pairs packed in f32x2 accumulators.
__global__ void gemm1(const float* __restrict__ x, const float* __restrict__ W1) {
    __shared__ unsigned long long xs2[16][128];  // [node pair][k] = (x[2i][k], x[2i+1][k])
    int n0 = blockIdx.x * 32;
    int tid = threadIdx.x;  // = output column c, 0..127
    for (int idx = tid; idx < 2048; idx += 128) {
        int pr = idx >> 7, k = idx & 127;
        float lo = x[(size_t)(n0 + 2 * pr) * 128 + k];
        float hi = x[(size_t)(n0 + 2 * pr + 1) * 128 + k];
        xs2[pr][k] = pack2(lo, hi);
    }
    __syncthreads();

    unsigned long long acc[16];
    #pragma unroll
    for (int i = 0; i < 16; i++) acc[i] = 0ull;
    for (int k = 0; k < 128; k += 2) {
        float w0 = W1[k * 128 + tid];
        float w1 = W1[(k + 1) * 128 + tid];
        unsigned long long w20 = pack2(w0, w0);
        unsigned long long w21 = pack2(w1, w1);
        #pragma unroll
        for (int i = 0; i < 16; i++) {
            ulonglong2 xv = *(const ulonglong2*)&xs2[i][k];
            acc[i] = ffma2(w20, xv.x, acc[i]);
            acc[i] = ffma2(w21, xv.y, acc[i]);
        }
    }

    // store h as half2 (channel pairs): pair adjacent columns via shfl
    #pragma unroll
    for (int i = 0; i < 16; i++) {
        unsigned long long other = __shfl_xor_sync(0xffffffffu, acc[i], 1);
        if ((tid & 1) == 0) {
            float2 mine = unpack2(acc[i]);
            float2 oth = unpack2(other);
            g_hh[(size_t)(n0 + 2 * i) * 64 + (tid >> 1)]     = __floats2half2_rn(mine.x, oth.x);
            g_hh[(size_t)(n0 + 2 * i + 1) * 64 + (tid >> 1)] = __floats2half2_rn(mine.y, oth.y);
        }
    }

    // epilogue: als1/ald1 = x . A1 (per head), warp per 8 nodes, xs2 still valid
    int w = tid >> 5, l = tid & 31;
    float4 As[4], Ad[4];
    #pragma unroll
    for (int j = 0; j < 4; j++) {
        As[j] = *(const float4*)&g_A1s[(l + 32 * j) * 4];
        Ad[j] = *(const float4*)&g_A1d[(l + 32 * j) * 4];
    }
    for (int q = 0; q < 8; q++) {
        int nd = w * 8 + q;
        int pr = nd >> 1, sel = nd & 1;
        float s0 = 0.f, s1 = 0.f, s2 = 0.f, s3 = 0.f;
        float d0 = 0.f, d1 = 0.f, d2 = 0.f, d3 = 0.f;
        #pragma unroll
        for (int j = 0; j < 4; j++) {
            float2 f = unpack2(xs2[pr][l + 32 * j]);
            float xv = sel ? f.y : f.x;
            s0 += xv * As[j].x; s1 += xv * As[j].y; s2 += xv * As[j].z; s3 += xv * As[j].w;
            d0 += xv * Ad[j].x; d1 += xv * Ad[j].y; d2 += xv * Ad[j].z; d3 += xv * Ad[j].w;
        }
        #pragma unroll
        for (int off = 16; off; off >>= 1) {
            s0 += __shfl_xor_sync(0xffffffffu, s0, off);
            s1 += __shfl_xor_sync(0xffffffffu, s1, off);
            s2 += __shfl_xor_sync(0xffffffffu, s2, off);
            s3 += __shfl_xor_sync(0xffffffffu, s3, off);
            d0 += __shfl_xor_sync(0xffffffffu, d0, off);
            d1 += __shfl_xor_sync(0xffffffffu, d1, off);
            d2 += __shfl_xor_sync(0xffffffffu, d2, off);
            d3 += __shfl_xor_sync(0xffffffffu, d3, off);
        }
        if (l == 0) {
            *(float4*)&g_als1[(size_t)(n0 + nd) * 4] = make_float4(s0, s1, s2, s3);
            *(float4*)&g_ald1[(size_t)(n0 + nd) * 4] = make_float4(d0, d1, d2, d3);
        }
    }
}

// ---- parallel exclusive scan of (deg+1) ----
__global__ void scan1() {
    __shared__ int sh[256];
    int t = threadIdx.x;
    int n = blockIdx.x * 256 + t;
    int val = (n < Nn) ? (int)g_deg[n] + 1 : 0;
    sh[t] = val;
    __syncthreads();
    for (int off = 1; off < 256; off <<= 1) {
        int v = (t >= off) ? sh[t - off] : 0;
        __syncthreads();
        sh[t] += v;
        __syncthreads();
    }
    if (n < Nn) g_pre[n] = sh[t] - val;
    if (t == 255) g_bsum[blockIdx.x] = sh[255];
}
__global__ void scan2() {
    __shared__ int sh[512];
    int t = threadIdx.x;
    int val = (t < NB_SCAN) ? g_bsum[t] : 0;
    sh[t] = val;
    __syncthreads();
    for (int off = 1; off < 512; off <<= 1) {
        int v = (t >= off) ? sh[t - off] : 0;
        __syncthreads();
        sh[t] += v;
        __syncthreads();
    }
    g_boff[t] = sh[t] - val;
}
__global__ void scan3() {
    int n = blockIdx.x * 256 + threadIdx.x;
    if (n >= Nn) return;
    int off = g_boff[blockIdx.x] + g_pre[n];
    g_off[n] = off;
    g_cursor[n] = off;
    if (n == 0) g_off[Nn] = EPt;
}

// scatter edges into CSR slots; store p1 = exp(lrelu(logit)) (no max subtraction needed:
// logits are O(1), softmax is shift-invariant) + src + layer2 logit base
__global__ void scatter_k(const int* __restrict__ ei) {
    int e = blockIdx.x * blockDim.x + threadIdx.x;
    if (e >= EPt) return;
    int src, dst;
    float b0, b1v, b2v, b3v, s2v;
    if (e < Ee) {
        src = ei[e]; dst = ei[Ee + e];
        float4 sv = *(const float4*)(g_s1 + (size_t)e * 4);
        b0 = sv.x; b1v = sv.y; b2v = sv.z; b3v = sv.w;
        s2v = g_s2[e];
    } else {
        int n = e - Ee;
        src = dst = n;
        float invd = 1.f / fmaxf(g_deg[n], 1.f);
        b0 = g_ns1[n * 4 + 0] * invd;
        b1v = g_ns1[n * 4 + 1] * invd;
        b2v = g_ns1[n * 4 + 2] * invd;
        b3v = g_ns1[n * 4 + 3] * invd;
        s2v = g_ns2[n] * invd;
    }
    float4 as = *(const float4*)(g_als1 + (size_t)src * 4);
    float4 ad = *(const float4*)(g_ald1 + (size_t)dst * 4);
    int pos = atomicAdd(&g_cursor[dst], 1);
    float4 pv;
    pv.x = __expf(lrelu_f(as.x + ad.x + b0));
    pv.y = __expf(lrelu_f(as.y + ad.y + b1v));
    pv.z = __expf(lrelu_f(as.z + ad.z + b2v));
    pv.w = __expf(lrelu_f(as.w + ad.w + b3v));
    *(float4*)(g_cp1 + (size_t)pos * 4) = pv;
    g_csrc[pos] = src;
    g_cs2[pos] = s2v;
}

// warp-per-node layer1: single-pass weighted aggregate + bias + ELU + als2/ald2 epilogue
__global__ void agg1_csr(const float* __restrict__ b1) {
    int n = (blockIdx.x * blockDim.x + threadIdx.x) >> 5;
    if (n >= Nn) return;
    int lane = threadIdx.x & 31;
    int hh = lane & 3;       // head whose p this lane fetches
    int sub = lane >> 2;     // edge sub-slot 0..7
    int la = lane >> 4;      // 0: heads 0/2, 1: heads 1/3
    int beg = g_off[n], end = g_off[n + 1];

    float accAx = 0.f, accAy = 0.f, accBx = 0.f, accBy = 0.f, zl = 0.f;
    for (int g = beg; g < end; g += 8) {
        int idx = g + sub;
        float p = 0.f;
        int src = 0;
        if (idx < end) {
            p = g_cp1[(size_t)idx * 4 + hh];
            src = g_csrc[idx];
        }
        zl += p;
        int lim = min(8, end - g);
        for (int t = 0; t < lim; t++) {
            float pa = __shfl_sync(0xffffffffu, p, t * 4 + la);
            float pb = __shfl_sync(0xffffffffu, p, t * 4 + 2 + la);
            int   st = __shfl_sync(0xffffffffu, src, t * 4);
            const __half2* hp = g_hh + (size_t)st * 64;
            float2 fa = __half22float2(hp[lane]);
            float2 fb = __half22float2(hp[32 + lane]);
            accAx += pa * fa.x; accAy += pa * fa.y;
            accBx += pb * fb.x; accBy += pb * fb.y;
        }
    }
    zl += __shfl_xor_sync(0xffffffffu, zl, 4);
    zl += __shfl_xor_sync(0xffffffffu, zl, 8);
    zl += __shfl_xor_sync(0xffffffffu, zl, 16);
    float za = __shfl_sync(0xffffffffu, zl, la);       // z of head la
    float zb = __shfl_sync(0xffffffffu, zl, 2 + la);   // z of head 2+la
    float2 b1a = ((const float2*)b1)[lane];
    float2 b1b = ((const float2*)b1)[32 + lane];
    float h1ax = elu_f(accAx / za + b1a.x);
    float h1ay = elu_f(accAy / za + b1a.y);
    float h1bx = elu_f(accBx / zb + b1b.x);
    float h1by = elu_f(accBy / zb + b1b.y);
    g_h1h[(size_t)n * 64 + lane]      = __floats2half2_rn(h1ax, h1ay);
    g_h1h[(size_t)n * 64 + 32 + lane] = __floats2half2_rn(h1bx, h1by);

    // als2/ald2 = h1 . A2
    float2 A2sa = ((const float2*)g_A2s)[lane];
    float2 A2sb = ((const float2*)g_A2s)[32 + lane];
    float2 A2da = ((const float2*)g_A2d)[lane];
    float2 A2db = ((const float2*)g_A2d)[32 + lane];
    float s = h1ax * A2sa.x + h1ay * A2sa.y + h1bx * A2sb.x + h1by * A2sb.y;
    float d = h1ax * A2da.x + h1ay * A2da.y + h1bx * A2db.x + h1by * A2db.y;
    #pragma unroll
    for (int off = 16; off; off >>= 1) {
        s += __shfl_xor_sync(0xffffffffu, s, off);
        d += __shfl_xor_sync(0xffffffffu, d, off);
    }
    if (lane == 0) { g_als2[n] = s; g_ald2[n] = d; }
}

// h2f = h1 @ W2 (fp16 in/out). 32 nodes per 256-thread block.
__global__ void gemm2(const float* __restrict__ W2) {
    __shared__ float ws[128 * 32];   // 16KB
    __shared__ float xs[32][128];    // 16KB
    int tid = threadIdx.x;
    int n0 = blockIdx.x * 32;
    for (int i = tid; i < 128 * 32; i += 256) ws[i] = W2[i];
    for (int idx = tid; idx < 2048; idx += 256) {
        int node = idx >> 6, j = idx & 63;
        float2 f = __half22float2(g_h1h[(size_t)(n0 + node) * 64 + j]);
        xs[node][2 * j] = f.x;
        xs[node][2 * j + 1] = f.y;
    }
    __syncthreads();
    int c = tid & 31, grp = tid >> 5;   // 8 groups x 4 nodes
    float acc[4] = {0.f, 0.f, 0.f, 0.f};
    for (int k = 0; k < 128; k++) {
        float w = ws[k * 32 + c];
        #pragma unroll
        for (int q = 0; q < 4; q++) acc[q] += w * xs[grp * 4 + q][k];
    }
    #pragma unroll
    for (int q = 0; q < 4; q++) {
        int node = n0 + grp * 4 + q;
        float other = __shfl_down_sync(0xffffffffu, acc[q], 1);
        if ((c & 1) == 0)
            g_h2fh[(size_t)node * 16 + (c >> 1)] = __floats2half2_rn(acc[q], other);
    }
}

// warp-per-node layer2: single-pass (logits on the fly, m=0), 2 edges per inner step
__global__ void agg2_csr(const float* __restrict__ b2, float* __restrict__ out) {
    int n = (blockIdx.x * blockDim.x + threadIdx.x) >> 5;
    if (n >= Nn) return;
    int lane = threadIdx.x & 31;
    int hs = lane >> 4;  // half-warp: 0 handles even inner edge, 1 odd
    int beg = g_off[n], end = g_off[n + 1];
    float ald2n = g_ald2[n];

    float accx = 0.f, accy = 0.f, zl = 0.f;
    for (int g = beg; g < end; g += 32) {
        int idx = g + lane;
        float p = 0.f;
        int src = 0;
        if (idx < end) {
            src = g_csrc[idx];
            p = __expf(lrelu_f(g_als2[src] + ald2n + g_cs2[idx]));
        }
        zl += p;
        int lim = min(32, end - g);
        for (int t = 0; t < lim; t += 2) {
            int tt = t + hs;  // if tt==lim (odd lim), that lane has p=0 -> no-op
            float pt = __shfl_sync(0xffffffffu, p, tt);
            int   st = __shfl_sync(0xffffffffu, src, tt);
            float2 f = __half22float2(g_h2fh[(size_t)st * 16 + (lane & 15)]);
            accx += pt * f.x;
            accy += pt * f.y;
        }
    }
    #pragma unroll
    for (int off = 16; off; off >>= 1)
        zl += __shfl_xor_sync(0xffffffffu, zl, off);
    accx += __shfl_xor_sync(0xffffffffu, accx, 16);
    accy += __shfl_xor_sync(0xffffffffu, accy, 16);
    if (lane == 0) g_z2[n] = zl;
    if (lane < 16) {
        float2 b2v = ((const float2*)b2)[lane];
        float2 o;
        o.x = elu_f(accx / zl + b2v.x);
        o.y = elu_f(accy / zl + b2v.y);
        *(float2*)(out + (size_t)n * 32 + 2 * lane) = o;
    }
}

// edge_index_sl (as float) + alpha2 recomputed in original edge order (m=0, same exp as agg2)
__global__ void finalize(const int* __restrict__ ei, float* __restrict__ out) {
    int e = blockIdx.x * blockDim.x + threadIdx.x;
    if (e >= EPt) return;
    int s, d;
    float base;
    if (e < Ee) {
        s = ei[e]; d = ei[Ee + e];
        base = g_s2[e];
    } else {
        s = d = e - Ee;
        base = g_ns2[d] / fmaxf(g_deg[d], 1.f);
    }
    float v = lrelu_f(g_als2[s] + g_ald2[d] + base);
    out[OFF_EI + e] = (float)s;
    out[OFF_EI + EPt + e] = (float)d;
    out[OFF_ALPHA + e] = __expf(v) / g_z2[d];
}

extern "C" void kernel_launch(void* const* d_in, const int* in_sizes, int n_in,
                              void* d_out, int out_size) {
    const float* x    = (const float*)d_in[0];
    const int*   ei   = (const int*)  d_in[1];
    const float* eat  = (const float*)d_in[2];
    const float* W1   = (const float*)d_in[3];
    const float* W1e  = (const float*)d_in[4];
    const float* a1s  = (const float*)d_in[5];
    const float* a1d  = (const float*)d_in[6];
    const float* a1e  = (const float*)d_in[7];
    const float* b1   = (const float*)d_in[8];
    const float* W2   = (const float*)d_in[9];
    const float* W2e  = (const float*)d_in[10];
    const float* a2s  = (const float*)d_in[11];
    const float* a2d  = (const float*)d_in[12];
    const float* a2e  = (const float*)d_in[13];
    const float* b2   = (const float*)d_in[14];
    float* out = (float*)d_out;
    (void)in_sizes; (void)n_in; (void)out_size;

    void *p_deg, *p_ns1, *p_ns2;
    cudaGetSymbolAddress(&p_deg, g_deg);
    cudaGetSymbolAddress(&p_ns1, g_ns1);
    cudaGetSymbolAddress(&p_ns2, g_ns2);
    cudaMemsetAsync(p_deg, 0, (size_t)Nn * 4);
    cudaMemsetAsync(p_ns1, 0, (size_t)Nn * 16);
    cudaMemsetAsync(p_ns2, 0, (size_t)Nn * 4);

    prep_all<<<1, 512>>>(W1e, a1e, W2e, a2e, W1, a1s, a1d, W2, a2s, a2d);
    edge_prep<<<(Ee + 255) / 256, 256>>>(ei, eat);
    gemm1<<<Nn / 32, 128>>>(x, W1);
    scan1<<<NB_SCAN, 256>>>();
    scan2<<<1, 512>>>();
    scan3<<<NB_SCAN, 256>>>();
    scatter_k<<<(EPt + 255) / 256, 256>>>(ei);
    agg1_csr<<<(Nn + 7) / 8, 256>>>(b1);
    gemm2<<<Nn / 32, 256>>>(W2);
    agg2_csr<<<(Nn + 7) / 8, 256>>>(b2, out);
    finalize<<<(EPt + 255) / 256, 256>>>(ei, out);
}

// round 7
// speedup vs baseline: 2.2016x; 1.0728x over previous
#include <cuda_runtime.h>
#include <cuda_fp16.h>
#include <math.h>

#define Nn 100000
#define Ee 1600000
#define EPt (Ee + Nn)                 // 1,700,000 edges incl. self loops
#define OFF_EI (Nn * 32)              // 3,200,000
#define OFF_ALPHA (OFF_EI + 2 * EPt)  // 6,600,000
#define NB_SCAN ((Nn + 255) / 256)    // 391

// ---------------- scratch (no allocations allowed) ----------------
__device__ __half2 g_hh[Nn * 64];      // layer1 features h = x@W1 (fp16, channel pairs)
__device__ __half2 g_h1h[Nn * 64];     // layer1 output h1 (fp16)
__device__ __half2 g_h2fh[Nn * 16];    // layer2 transformed features (fp16)
__device__ __align__(16) float g_als1[Nn * 4];
__device__ __align__(16) float g_ald1[Nn * 4];
__device__ float g_deg[Nn];
__device__ __align__(16) float g_ns1[Nn * 4];
__device__ float g_ns2[Nn];
__device__ __align__(16) float g_s1[Ee * 4];
__device__ float g_s2[Ee];
__device__ float g_als2[Nn];
__device__ float g_ald2[Nn];
__device__ float g_z2[Nn];
__device__ float g_v1e[64];
__device__ float g_v2e[16];
__device__ __align__(16) float g_A1s[128 * 4];  // (W1 . a1_src) per [k][h]
__device__ __align__(16) float g_A1d[128 * 4];
__device__ __align__(16) float g_A2s[128];
__device__ __align__(16) float g_A2d[128];
// CSR structures
__device__ int   g_off[Nn + 1];
__device__ int   g_cursor[Nn];
__device__ int   g_csrc[EPt];
__device__ __align__(16) float g_cp1[EPt * 4];  // exp(lrelu(logit1)) per head, CSR order
__device__ float g_cs2[EPt];                    // layer2 logit base, CSR order
// scan scratch
__device__ int g_pre[Nn];
__device__ int g_bsum[512];
__device__ int g_boff[512];

__device__ __forceinline__ float elu_f(float v) { return v > 0.f ? v : expm1f(v); }
__device__ __forceinline__ float lrelu_f(float v) { return v > 0.f ? v : 0.2f * v; }

// ---- packed fp32x2 helpers (sm_100+) ----
__device__ __forceinline__ unsigned long long pack2(float lo, float hi) {
    unsigned long long d;
    asm("mov.b64 %0, {%1, %2};" : "=l"(d) : "f"(lo), "f"(hi));
    return d;
}
__device__ __forceinline__ float2 unpack2(unsigned long long v) {
    float2 r;
    asm("mov.b64 {%0, %1}, %2;" : "=f"(r.x), "=f"(r.y) : "l"(v));
    return r;
}
__device__ __forceinline__ unsigned long long ffma2(unsigned long long a, unsigned long long b,
                                                    unsigned long long c) {
    unsigned long long d;
    asm("fma.rn.f32x2 %0, %1, %2, %3;" : "=l"(d) : "l"(a), "l"(b), "l"(c));
    return d;
}

// ---------------- kernels ----------------

__global__ void prep_all(const float* __restrict__ W1e, const float* __restrict__ a1e,
                         const float* __restrict__ W2e, const float* __restrict__ a2e,
                         const float* __restrict__ W1, const float* __restrict__ a1s,
                         const float* __restrict__ a1d, const float* __restrict__ W2,
                         const float* __restrict__ a2s, const float* __restrict__ a2d) {
    int t = threadIdx.x;  // 512 threads
    if (t < 64) {
        int ed = t >> 2, h = t & 3;
        float s = 0.f;
        #pragma unroll
        for (int c = 0; c < 32; c++) s += W1e[ed * 128 + h * 32 + c] * a1e[h * 32 + c];
        g_v1e[t] = s;
    }
    if (t < 16) {
        float s = 0.f;
        #pragma unroll
        for (int c = 0; c < 32; c++) s += W2e[t * 32 + c] * a2e[c];
        g_v2e[t] = s;
    }
    {
        int k = t >> 2, h = t & 3;
        float s = 0.f, d = 0.f;
        #pragma unroll
        for (int c = 0; c < 32; c++) {
            float w = W1[k * 128 + h * 32 + c];
            s += w * a1s[h * 32 + c];
            d += w * a1d[h * 32 + c];
        }
        g_A1s[t] = s;
        g_A1d[t] = d;
    }
    if (t < 128) {
        float s = 0.f, d = 0.f;
        #pragma unroll
        for (int c = 0; c < 32; c++) {
            float w = W2[t * 32 + c];
            s += w * a2s[c];
            d += w * a2d[c];
        }
        g_A2s[t] = s;
        g_A2d[t] = d;
    }
}

// per-edge: s1, s2, deg, node sums for self-loop mean attr
__global__ void edge_prep(const int* __restrict__ ei, const float* __restrict__ eattr) {
    int e = blockIdx.x * blockDim.x + threadIdx.x;
    if (e >= Ee) return;
    int dst = ei[Ee + e];
    float a[16];
    const float4* p = (const float4*)(eattr + (size_t)e * 16);
    #pragma unroll
    for (int q = 0; q < 4; q++) {
        float4 v = p[q];
        a[q * 4 + 0] = v.x; a[q * 4 + 1] = v.y; a[q * 4 + 2] = v.z; a[q * 4 + 3] = v.w;
    }
    float s[4] = {0.f, 0.f, 0.f, 0.f};
    float s2v = 0.f;
    #pragma unroll
    for (int ed = 0; ed < 16; ed++) {
        float av = a[ed];
        #pragma unroll
        for (int h = 0; h < 4; h++) s[h] += av * g_v1e[ed * 4 + h];
        s2v += av * g_v2e[ed];
    }
    *(float4*)(g_s1 + (size_t)e * 4) = make_float4(s[0], s[1], s[2], s[3]);
    g_s2[e] = s2v;
    atomicAdd(&g_deg[dst], 1.f);
    #pragma unroll
    for (int h = 0; h < 4; h++) atomicAdd(&g_ns1[dst * 4 + h], s[h]);
    atomicAdd(&g_ns2[dst], s2v);
}

// h = x @ W1 (fp32x2 packed math, fp16 output) + als1/ald1 via precomputed A1s/A1d.
__global__ void gemm1(const float* __restrict__ x, const float* __restrict__ W1) {
    __shared__ unsigned long long xs2[16][128];  // [node pair][k]
    int n0 = blockIdx.x * 32;
    int tid = threadIdx.x;  // output column, 0..127
    for (int idx = tid; idx < 2048; idx += 128) {
        int pr = idx >> 7, k = idx & 127;
        float lo = x[(size_t)(n0 + 2 * pr) * 128 + k];
        float hi = x[(size_t)(n0 + 2 * pr + 1) * 128 + k];
        xs2[pr][k] = pack2(lo, hi);
    }
    __syncthreads();

    unsigned long long acc[16];
    #pragma unroll
    for (int i = 0; i < 16; i++) acc[i] = 0ull;
    for (int k = 0; k < 128; k += 2) {
        float w0 = W1[k * 128 + tid];
        float w1 = W1[(k + 1) * 128 + tid];
        unsigned long long w20 = pack2(w0, w0);
        unsigned long long w21 = pack2(w1, w1);
        #pragma unroll
        for (int i = 0; i < 16; i++) {
            ulonglong2 xv = *(const ulonglong2*)&xs2[i][k];
            acc[i] = ffma2(w20, xv.x, acc[i]);
            acc[i] = ffma2(w21, xv.y, acc[i]);
        }
    }
    #pragma unroll
    for (int i = 0; i < 16; i++) {
        unsigned long long other = __shfl_xor_sync(0xffffffffu, acc[i], 1);
        if ((tid & 1) == 0) {
            float2 mine = unpack2(acc[i]);
            float2 oth = unpack2(other);
            g_hh[(size_t)(n0 + 2 * i) * 64 + (tid >> 1)]     = __floats2half2_rn(mine.x, oth.x);
            g_hh[(size_t)(n0 + 2 * i + 1) * 64 + (tid >> 1)] = __floats2half2_rn(mine.y, oth.y);
        }
    }

    int w = tid >> 5, l = tid & 31;
    float4 As[4], Ad[4];
    #pragma unroll
    for (int j = 0; j < 4; j++) {
        As[j] = *(const float4*)&g_A1s[(l + 32 * j) * 4];
        Ad[j] = *(const float4*)&g_A1d[(l + 32 * j) * 4];
    }
    for (int q = 0; q < 8; q++) {
        int nd = w * 8 + q;
        int pr = nd >> 1, sel = nd & 1;
        float s0 = 0.f, s1 = 0.f, s2 = 0.f, s3 = 0.f;
        float d0 = 0.f, d1 = 0.f, d2 = 0.f, d3 = 0.f;
        #pragma unroll
        for (int j = 0; j < 4; j++) {
            float2 f = unpack2(xs2[pr][l + 32 * j]);
            float xv = sel ? f.y : f.x;
            s0 += xv * As[j].x; s1 += xv * As[j].y; s2 += xv * As[j].z; s3 += xv * As[j].w;
            d0 += xv * Ad[j].x; d1 += xv * Ad[j].y; d2 += xv * Ad[j].z; d3 += xv * Ad[j].w;
        }
        #pragma unroll
        for (int off = 16; off; off >>= 1) {
            s0 += __shfl_xor_sync(0xffffffffu, s0, off);
            s1 += __shfl_xor_sync(0xffffffffu, s1, off);
            s2 += __shfl_xor_sync(0xffffffffu, s2, off);
            s3 += __shfl_xor_sync(0xffffffffu, s3, off);
            d0 += __shfl_xor_sync(0xffffffffu, d0, off);
            d1 += __shfl_xor_sync(0xffffffffu, d1, off);
            d2 += __shfl_xor_sync(0xffffffffu, d2, off);
            d3 += __shfl_xor_sync(0xffffffffu, d3, off);
        }
        if (l == 0) {
            *(float4*)&g_als1[(size_t)(n0 + nd) * 4] = make_float4(s0, s1, s2, s3);
            *(float4*)&g_ald1[(size_t)(n0 + nd) * 4] = make_float4(d0, d1, d2, d3);
        }
    }
}

// ---- parallel exclusive scan of (deg+1) ----
__global__ void scan1() {
    __shared__ int sh[256];
    int t = threadIdx.x;
    int n = blockIdx.x * 256 + t;
    int val = (n < Nn) ? (int)g_deg[n] + 1 : 0;
    sh[t] = val;
    __syncthreads();
    for (int off = 1; off < 256; off <<= 1) {
        int v = (t >= off) ? sh[t - off] : 0;
        __syncthreads();
        sh[t] += v;
        __syncthreads();
    }
    if (n < Nn) g_pre[n] = sh[t] - val;
    if (t == 255) g_bsum[blockIdx.x] = sh[255];
}
__global__ void scan2() {
    __shared__ int sh[512];
    int t = threadIdx.x;
    int val = (t < NB_SCAN) ? g_bsum[t] : 0;
    sh[t] = val;
    __syncthreads();
    for (int off = 1; off < 512; off <<= 1) {
        int v = (t >= off) ? sh[t - off] : 0;
        __syncthreads();
        sh[t] += v;
        __syncthreads();
    }
    g_boff[t] = sh[t] - val;
}
__global__ void scan3() {
    int n = blockIdx.x * 256 + threadIdx.x;
    if (n >= Nn) return;
    int off = g_boff[blockIdx.x] + g_pre[n];
    g_off[n] = off;
    g_cursor[n] = off;
    if (n == 0) g_off[Nn] = EPt;
}

// scatter edges into CSR slots; store p1 = exp(lrelu(logit)) per head + src + layer2 base
__global__ void scatter_k(const int* __restrict__ ei) {
    int e = blockIdx.x * blockDim.x + threadIdx.x;
    if (e >= EPt) return;
    int src, dst;
    float b0, b1v, b2v, b3v, s2v;
    if (e < Ee) {
        src = ei[e]; dst = ei[Ee + e];
        float4 sv = *(const float4*)(g_s1 + (size_t)e * 4);
        b0 = sv.x; b1v = sv.y; b2v = sv.z; b3v = sv.w;
        s2v = g_s2[e];
    } else {
        int n = e - Ee;
        src = dst = n;
        float invd = 1.f / fmaxf(g_deg[n], 1.f);
        b0 = g_ns1[n * 4 + 0] * invd;
        b1v = g_ns1[n * 4 + 1] * invd;
        b2v = g_ns1[n * 4 + 2] * invd;
        b3v = g_ns1[n * 4 + 3] * invd;
        s2v = g_ns2[n] * invd;
    }
    float4 as = *(const float4*)(g_als1 + (size_t)src * 4);
    float4 ad = *(const float4*)(g_ald1 + (size_t)dst * 4);
    int pos = atomicAdd(&g_cursor[dst], 1);
    float4 pv;
    pv.x = __expf(lrelu_f(as.x + ad.x + b0));
    pv.y = __expf(lrelu_f(as.y + ad.y + b1v));
    pv.z = __expf(lrelu_f(as.z + ad.z + b2v));
    pv.w = __expf(lrelu_f(as.w + ad.w + b3v));
    *(float4*)(g_cp1 + (size_t)pos * 4) = pv;
    g_csrc[pos] = src;
    g_cs2[pos] = s2v;
}

// warp-per-node layer1: 2 edges per inner step via LDG.128 across half-warps.
// Lane l accumulates channels [ (l&15)*8, (l&15)*8+8 ); lanes 0-15 even-slot edges,
// lanes 16-31 odd-slot edges; combined with shfl_xor(16) at the end.
__global__ void agg1_csr(const float* __restrict__ b1) {
    int n = (blockIdx.x * blockDim.x + threadIdx.x) >> 5;
    if (n >= Nn) return;
    int lane = threadIdx.x & 31;
    int sub = lane >> 2;          // p-load slot 0..7
    int l15 = lane & 15;
    int hl = l15 >> 2;            // head owning this lane's 8 channels
    int half = lane >> 4;         // which edge of the pair
    int beg = g_off[n], end = g_off[n + 1];

    float acc0 = 0.f, acc1 = 0.f, acc2 = 0.f, acc3 = 0.f;
    float acc4 = 0.f, acc5 = 0.f, acc6 = 0.f, acc7 = 0.f;
    float zl = 0.f;

    for (int g = beg; g < end; g += 8) {
        int idx = g + sub;
        float p = 0.f;
        int src = 0;
        if (idx < end) {
            p = g_cp1[(size_t)idx * 4 + (lane & 3)];
            src = g_csrc[idx];
        }
        zl += p;
        int lim = end - g;
        #pragma unroll
        for (int t = 0; t < 8; t += 2) {
            if (t >= lim) break;
            int slot = t + half;   // may equal lim (odd tail) -> p=0 there, harmless
            float pe = __shfl_sync(0xffffffffu, p, slot * 4 + hl);
            int   se = __shfl_sync(0xffffffffu, src, slot * 4);
            uint4 v = *(const uint4*)((const char*)g_hh + (size_t)se * 256 + l15 * 16);
            float2 f0 = __half22float2(*(__half2*)&v.x);
            float2 f1 = __half22float2(*(__half2*)&v.y);
            float2 f2 = __half22float2(*(__half2*)&v.z);
            float2 f3 = __half22float2(*(__half2*)&v.w);
            acc0 += pe * f0.x; acc1 += pe * f0.y;
            acc2 += pe * f1.x; acc3 += pe * f1.y;
            acc4 += pe * f2.x; acc5 += pe * f2.y;
            acc6 += pe * f3.x; acc7 += pe * f3.y;
        }
    }
    // combine the two edge-parity halves
    acc0 += __shfl_xor_sync(0xffffffffu, acc0, 16);
    acc1 += __shfl_xor_sync(0xffffffffu, acc1, 16);
    acc2 += __shfl_xor_sync(0xffffffffu, acc2, 16);
    acc3 += __shfl_xor_sync(0xffffffffu, acc3, 16);
    acc4 += __shfl_xor_sync(0xffffffffu, acc4, 16);
    acc5 += __shfl_xor_sync(0xffffffffu, acc5, 16);
    acc6 += __shfl_xor_sync(0xffffffffu, acc6, 16);
    acc7 += __shfl_xor_sync(0xffffffffu, acc7, 16);
    // z per head
    zl += __shfl_xor_sync(0xffffffffu, zl, 4);
    zl += __shfl_xor_sync(0xffffffffu, zl, 8);
    zl += __shfl_xor_sync(0xffffffffu, zl, 16);
    float inv = 1.f / __shfl_sync(0xffffffffu, zl, hl);

    float4 bA = ((const float4*)b1)[l15 * 2];
    float4 bB = ((const float4*)b1)[l15 * 2 + 1];
    float h0 = elu_f(acc0 * inv + bA.x);
    float h1 = elu_f(acc1 * inv + bA.y);
    float h2 = elu_f(acc2 * inv + bA.z);
    float h3 = elu_f(acc3 * inv + bA.w);
    float h4 = elu_f(acc4 * inv + bB.x);
    float h5 = elu_f(acc5 * inv + bB.y);
    float h6 = elu_f(acc6 * inv + bB.z);
    float h7 = elu_f(acc7 * inv + bB.w);
    if (lane < 16) {
        uint4 o;
        *(__half2*)&o.x = __floats2half2_rn(h0, h1);
        *(__half2*)&o.y = __floats2half2_rn(h2, h3);
        *(__half2*)&o.z = __floats2half2_rn(h4, h5);
        *(__half2*)&o.w = __floats2half2_rn(h6, h7);
        *(uint4*)((char*)g_h1h + (size_t)n * 256 + l15 * 16) = o;
    }
    // als2/ald2 = h1 . A2 (lanes>=16 hold duplicates; reduce within 16-lane groups)
    float4 sA = ((const float4*)g_A2s)[l15 * 2];
    float4 sB = ((const float4*)g_A2s)[l15 * 2 + 1];
    float4 dA = ((const float4*)g_A2d)[l15 * 2];
    float4 dB = ((const float4*)g_A2d)[l15 * 2 + 1];
    float s = h0 * sA.x + h1 * sA.y + h2 * sA.z + h3 * sA.w
            + h4 * sB.x + h5 * sB.y + h6 * sB.z + h7 * sB.w;
    float d = h0 * dA.x + h1 * dA.y + h2 * dA.z + h3 * dA.w
            + h4 * dB.x + h5 * dB.y + h6 * dB.z + h7 * dB.w;
    #pragma unroll
    for (int off = 8; off; off >>= 1) {
        s += __shfl_xor_sync(0xffffffffu, s, off);
        d += __shfl_xor_sync(0xffffffffu, d, off);
    }
    if (lane == 0) { g_als2[n] = s; g_ald2[n] = d; }
}

// h2f = h1 @ W2 (fp16 in/out). 32 nodes per 256-thread block.
__global__ void gemm2(const float* __restrict__ W2) {
    __shared__ float ws[128 * 32];
    __shared__ float xs[32][128];
    int tid = threadIdx.x;
    int n0 = blockIdx.x * 32;
    for (int i = tid; i < 128 * 32; i += 256) ws[i] = W2[i];
    for (int idx = tid; idx < 2048; idx += 256) {
        int node = idx >> 6, j = idx & 63;
        float2 f = __half22float2(g_h1h[(size_t)(n0 + node) * 64 + j]);
        xs[node][2 * j] = f.x;
        xs[node][2 * j + 1] = f.y;
    }
    __syncthreads();
    int c = tid & 31, grp = tid >> 5;
    float acc[4] = {0.f, 0.f, 0.f, 0.f};
    for (int k = 0; k < 128; k++) {
        float w = ws[k * 32 + c];
        #pragma unroll
        for (int q = 0; q < 4; q++) acc[q] += w * xs[grp * 4 + q][k];
    }
    #pragma unroll
    for (int q = 0; q < 4; q++) {
        int node = n0 + grp * 4 + q;
        float other = __shfl_down_sync(0xffffffffu, acc[q], 1);
        if ((c & 1) == 0)
            g_h2fh[(size_t)node * 16 + (c >> 1)] = __floats2half2_rn(acc[q], other);
    }
}

// warp-per-node layer2: 4 edges per inner step via LDG.64 across lane groups of 8.
// Lane l accumulates channels [ (l&7)*4, (l&7)*4+4 ); groups (l>>3) handle edge slots t+grp.
__global__ void agg2_csr(const float* __restrict__ b2, float* __restrict__ out) {
    int n = (blockIdx.x * blockDim.x + threadIdx.x) >> 5;
    if (n >= Nn) return;
    int lane = threadIdx.x & 31;
    int grp = lane >> 3;   // 0..3
    int chp = lane & 7;    // channel quad
    int beg = g_off[n], end = g_off[n + 1];
    float ald2n = g_ald2[n];

    float a0 = 0.f, a1 = 0.f, a2 = 0.f, a3 = 0.f, zl = 0.f;
    for (int g = beg; g < end; g += 32) {
        int idx = g + lane;
        float p = 0.f;
        int src = 0;
        if (idx < end) {
            src = g_csrc[idx];
            p = __expf(lrelu_f(g_als2[src] + ald2n + g_cs2[idx]));
        }
        zl += p;
        int lim = min(32, end - g);
        #pragma unroll 4
        for (int t = 0; t < 32; t += 4) {
            if (t >= lim) break;
            int slot = t + grp;   // slot>=lim lanes carry p=0 -> no-op
            float pe = __shfl_sync(0xffffffffu, p, slot);
            int   se = __shfl_sync(0xffffffffu, src, slot);
            float2 v = *(const float2*)((const char*)g_h2fh + (size_t)se * 64 + chp * 8);
            float2 f0 = __half22float2(*(__half2*)&v.x);
            float2 f1 = __half22float2(*(__half2*)&v.y);
            a0 += pe * f0.x; a1 += pe * f0.y;
            a2 += pe * f1.x; a3 += pe * f1.y;
        }
    }
    // combine 4 edge groups (lanes differing in bits 3,4)
    a0 += __shfl_xor_sync(0xffffffffu, a0, 8);  a0 += __shfl_xor_sync(0xffffffffu, a0, 16);
    a1 += __shfl_xor_sync(0xffffffffu, a1, 8);  a1 += __shfl_xor_sync(0xffffffffu, a1, 16);
    a2 += __shfl_xor_sync(0xffffffffu, a2, 8);  a2 += __shfl_xor_sync(0xffffffffu, a2, 16);
    a3 += __shfl_xor_sync(0xffffffffu, a3, 8);  a3 += __shfl_xor_sync(0xffffffffu, a3, 16);
    #pragma unroll
    for (int off = 16; off; off >>= 1)
        zl += __shfl_xor_sync(0xffffffffu, zl, off);
    if (lane == 0) g_z2[n] = zl;
    if (lane < 8) {
        float inv = 1.f / zl;
        float4 bv = ((const float4*)b2)[chp];
        float4 o;
        o.x = elu_f(a0 * inv + bv.x);
        o.y = elu_f(a1 * inv + bv.y);
        o.z = elu_f(a2 * inv + bv.z);
        o.w = elu_f(a3 * inv + bv.w);
        *(float4*)(out + (size_t)n * 32 + chp * 4) = o;
    }
}

// edge_index_sl (as float) + alpha2 recomputed in original edge order
__global__ void finalize(const int* __restrict__ ei, float* __restrict__ out) {
    int e = blockIdx.x * blockDim.x + threadIdx.x;
    if (e >= EPt) return;
    int s, d;
    float base;
    if (e < Ee) {
        s = ei[e]; d = ei[Ee + e];
        base = g_s2[e];
    } else {
        s = d = e - Ee;
        base = g_ns2[d] / fmaxf(g_deg[d], 1.f);
    }
    float v = lrelu_f(g_als2[s] + g_ald2[d] + base);
    out[OFF_EI + e] = (float)s;
    out[OFF_EI + EPt + e] = (float)d;
    out[OFF_ALPHA + e] = __expf(v) / g_z2[d];
}

extern "C" void kernel_launch(void* const* d_in, const int* in_sizes, int n_in,
                              void* d_out, int out_size) {
    const float* x    = (const float*)d_in[0];
    const int*   ei   = (const int*)  d_in[1];
    const float* eat  = (const float*)d_in[2];
    const float* W1   = (const float*)d_in[3];
    const float* W1e  = (const float*)d_in[4];
    const float* a1s  = (const float*)d_in[5];
    const float* a1d  = (const float*)d_in[6];
    const float* a1e  = (const float*)d_in[7];
    const float* b1   = (const float*)d_in[8];
    const float* W2   = (const float*)d_in[9];
    const float* W2e  = (const float*)d_in[10];
    const float* a2s  = (const float*)d_in[11];
    const float* a2d  = (const float*)d_in[12];
    const float* a2e  = (const float*)d_in[13];
    const float* b2   = (const float*)d_in[14];
    float* out = (float*)d_out;
    (void)in_sizes; (void)n_in; (void)out_size;

    void *p_deg, *p_ns1, *p_ns2;
    cudaGetSymbolAddress(&p_deg, g_deg);
    cudaGetSymbolAddress(&p_ns1, g_ns1);
    cudaGetSymbolAddress(&p_ns2, g_ns2);
    cudaMemsetAsync(p_deg, 0, (size_t)Nn * 4);
    cudaMemsetAsync(p_ns1, 0, (size_t)Nn * 16);
    cudaMemsetAsync(p_ns2, 0, (size_t)Nn * 4);

    prep_all<<<1, 512>>>(W1e, a1e, W2e, a2e, W1, a1s, a1d, W2, a2s, a2d);
    edge_prep<<<(Ee + 255) / 256, 256>>>(ei, eat);
    gemm1<<<Nn / 32, 128>>>(x, W1);
    scan1<<<NB_SCAN, 256>>>();
    scan2<<<1, 512>>>();
    scan3<<<NB_SCAN, 256>>>();
    scatter_k<<<(EPt + 255) / 256, 256>>>(ei);
    agg1_csr<<<(Nn + 7) / 8, 256>>>(b1);
    gemm2<<<Nn / 32, 256>>>(W2);
    agg2_csr<<<(Nn + 7) / 8, 256>>>(b2, out);
    finalize<<<(EPt + 255) / 256, 256>>>(ei, out);
}

// round 9
// speedup vs baseline: 3.0410x; 1.3813x over previous
#include <cuda_runtime.h>
#include <cuda_fp16.h>
#include <cstdint>
#include <math.h>

#define Nn 100000
#define Ee 1600000
#define EPt (Ee + Nn)                 // 1,700,000 edges incl. self loops
#define OFF_EI (Nn * 32)              // 3,200,000
#define OFF_ALPHA (OFF_EI + 2 * EPt)  // 6,600,000
#define NB_SCAN ((Nn + 255) / 256)    // 391
#define W1N 136                       // 128 h cols + 4 als1 + 4 ald1
#define W2N 40                        // 32 h2f cols + als2 + ald2 + 6 pad

// ---------------- scratch (no allocations allowed) ----------------
__device__ __half2 g_hh[Nn * 64];      // layer1 features h = x@W1 (fp16)
__device__ __half2 g_h1h[Nn * 64];     // layer1 output h1 (fp16)
__device__ __half2 g_h2fh[Nn * 16];    // layer2 transformed features (fp16)
__device__ __align__(16) float g_als1[Nn * 4];
__device__ __align__(16) float g_ald1[Nn * 4];
__device__ float g_deg[Nn];
__device__ __align__(16) float g_ns1[Nn * 4];
__device__ float g_ns2[Nn];
__device__ float g_s2[Ee];
__device__ float g_als2[Nn];
__device__ float g_ald2[Nn];
__device__ float g_z2[Nn];
__device__ float g_v1e[64];
__device__ float g_v2e[16];
__device__ __align__(16) float g_A1s[128 * 4];
__device__ __align__(16) float g_A1d[128 * 4];
__device__ __align__(16) float g_A2s[128];
__device__ __align__(16) float g_A2d[128];
__device__ __align__(16) __half g_W1aug[128 * W1N];
__device__ __align__(16) __half g_W2aug[128 * W2N];
// CSR structures
__device__ int   g_off[Nn + 1];
__device__ int   g_cursor[Nn];
__device__ int   g_csrc[EPt];
__device__ __align__(16) float g_cp1[EPt * 4];  // exp(lrelu(logit1)) per head, CSR order
__device__ float g_cs2[EPt];                    // layer2 logit base, CSR order
// scan scratch
__device__ int g_pre[Nn];
__device__ int g_bsum[512];
__device__ int g_boff[512];

__device__ __forceinline__ float elu_f(float v) { return v > 0.f ? v : expm1f(v); }
__device__ __forceinline__ float lrelu_f(float v) { return v > 0.f ? v : 0.2f * v; }

// ---- mma helpers ----
__device__ __forceinline__ unsigned int cvta_s(const void* p) {
    return (unsigned int)__cvta_generic_to_shared(p);
}
__device__ __forceinline__ void ldsm_x4(unsigned int& r0, unsigned int& r1,
                                        unsigned int& r2, unsigned int& r3,
                                        unsigned int addr) {
    asm volatile("ldmatrix.sync.aligned.m8n8.x4.shared.b16 {%0,%1,%2,%3}, [%4];"
                 : "=r"(r0), "=r"(r1), "=r"(r2), "=r"(r3) : "r"(addr));
}
__device__ __forceinline__ void ldsm_x4t(unsigned int& r0, unsigned int& r1,
                                         unsigned int& r2, unsigned int& r3,
                                         unsigned int addr) {
    asm volatile("ldmatrix.sync.aligned.m8n8.x4.trans.shared.b16 {%0,%1,%2,%3}, [%4];"
                 : "=r"(r0), "=r"(r1), "=r"(r2), "=r"(r3) : "r"(addr));
}
__device__ __forceinline__ void ldsm_x2t(unsigned int& r0, unsigned int& r1,
                                         unsigned int addr) {
    asm volatile("ldmatrix.sync.aligned.m8n8.x2.trans.shared.b16 {%0,%1}, [%2];"
                 : "=r"(r0), "=r"(r1) : "r"(addr));
}
__device__ __forceinline__ void mma_16816(float* c, unsigned int a0, unsigned int a1,
                                          unsigned int a2, unsigned int a3,
                                          unsigned int b0, unsigned int b1) {
    asm volatile(
        "mma.sync.aligned.m16n8k16.row.col.f32.f16.f16.f32 "
        "{%0,%1,%2,%3}, {%4,%5,%6,%7}, {%8,%9}, {%0,%1,%2,%3};"
        : "+f"(c[0]), "+f"(c[1]), "+f"(c[2]), "+f"(c[3])
        : "r"(a0), "r"(a1), "r"(a2), "r"(a3), "r"(b0), "r"(b1));
}

// ---------------- kernels ----------------

// precomputes: v1e/v2e, A1s/A1d/A2s/A2d, then augmented fp16 weight matrices
__global__ void prep_all(const float* __restrict__ W1e, const float* __restrict__ a1e,
                         const float* __restrict__ W2e, const float* __restrict__ a2e,
                         const float* __restrict__ W1, const float* __restrict__ a1s,
                         const float* __restrict__ a1d, const float* __restrict__ W2,
                         const float* __restrict__ a2s, const float* __restrict__ a2d) {
    int t = threadIdx.x;  // 512 threads
    if (t < 64) {
        int ed = t >> 2;
        int h = t & 3;
        float s = 0.f;
        #pragma unroll
        for (int c = 0; c < 32; c++) {
            s += W1e[ed * 128 + h * 32 + c] * a1e[h * 32 + c];
        }
        g_v1e[t] = s;
    }
    if (t < 16) {
        float s = 0.f;
        #pragma unroll
        for (int c = 0; c < 32; c++) {
            s += W2e[t * 32 + c] * a2e[c];
        }
        g_v2e[t] = s;
    }
    {
        int k = t >> 2;
        int h = t & 3;
        float s = 0.f;
        float d = 0.f;
        #pragma unroll
        for (int c = 0; c < 32; c++) {
            float w = W1[k * 128 + h * 32 + c];
            s += w * a1s[h * 32 + c];
            d += w * a1d[h * 32 + c];
        }
        g_A1s[t] = s;
        g_A1d[t] = d;
    }
    if (t < 128) {
        float s = 0.f;
        float d = 0.f;
        #pragma unroll
        for (int c = 0; c < 32; c++) {
            float w = W2[t * 32 + c];
            s += w * a2s[c];
            d += w * a2d[c];
        }
        g_A2s[t] = s;
        g_A2d[t] = d;
    }
    __syncthreads();
    for (int i = t; i < 128 * W1N; i += 512) {
        int k = i / W1N;
        int n = i - k * W1N;
        float v;
        if (n < 128) {
            v = W1[k * 128 + n];
        } else if (n < 132) {
            v = g_A1s[k * 4 + (n - 128)];
        } else {
            v = g_A1d[k * 4 + (n - 132)];
        }
        g_W1aug[i] = __float2half_rn(v);
    }
    for (int i = t; i < 128 * W2N; i += 512) {
        int k = i / W2N;
        int n = i - k * W2N;
        float v = 0.f;
        if (n < 32) {
            v = W2[k * 32 + n];
        } else if (n == 32) {
            v = g_A2s[k];
        } else if (n == 33) {
            v = g_A2d[k];
        }
        g_W2aug[i] = __float2half_rn(v);
    }
}

// degree count only
__global__ void deg_k(const int* __restrict__ ei) {
    int e = blockIdx.x * blockDim.x + threadIdx.x;
    if (e >= Ee) return;
    atomicAdd(&g_deg[ei[Ee + e]], 1.f);
}

// ---- parallel exclusive scan of (deg+1) ----
__global__ void scan1() {
    __shared__ int sh[256];
    int t = threadIdx.x;
    int n = blockIdx.x * 256 + t;
    int val = (n < Nn) ? (int)g_deg[n] + 1 : 0;
    sh[t] = val;
    __syncthreads();
    for (int off = 1; off < 256; off <<= 1) {
        int v = (t >= off) ? sh[t - off] : 0;
        __syncthreads();
        sh[t] += v;
        __syncthreads();
    }
    if (n < Nn) g_pre[n] = sh[t] - val;
    if (t == 255) g_bsum[blockIdx.x] = sh[255];
}
__global__ void scan2() {
    __shared__ int sh[512];
    int t = threadIdx.x;
    int val = (t < NB_SCAN) ? g_bsum[t] : 0;
    sh[t] = val;
    __syncthreads();
    for (int off = 1; off < 512; off <<= 1) {
        int v = (t >= off) ? sh[t - off] : 0;
        __syncthreads();
        sh[t] += v;
        __syncthreads();
    }
    g_boff[t] = sh[t] - val;
}
__global__ void scan3() {
    int n = blockIdx.x * 256 + threadIdx.x;
    if (n >= Nn) return;
    int off = g_boff[blockIdx.x] + g_pre[n];
    g_off[n] = off;
    g_cursor[n] = off;
    if (n == 0) g_off[Nn] = EPt;
}

// [h | als1 | ald1] = x @ W1aug via HMMA. 32 nodes per 256-thread block.
__global__ void gemm1_mma(const float* __restrict__ x) {
    __shared__ __align__(16) __half sW[128 * W1N];  // 34816 B
    __shared__ __align__(16) __half sX[32 * W1N];   //  8704 B (128 cols used)
    int tid = threadIdx.x;
    int n0 = blockIdx.x * 32;
    for (int i = tid; i < 128 * W1N / 8; i += 256) {
        ((uint4*)sW)[i] = ((const uint4*)g_W1aug)[i];
    }
    for (int i = tid; i < 2048; i += 256) {
        int r = i >> 6;
        int cp = i & 63;
        int node = n0 + r;
        float2 f = (node < Nn) ? *(const float2*)(x + (size_t)node * 128 + 2 * cp)
                               : make_float2(0.f, 0.f);
        *(__half2*)&sX[r * W1N + 2 * cp] = __floats2half2_rn(f.x, f.y);
    }
    __syncthreads();

    int w = tid >> 5;
    int lane = tid & 31;
    int mi = w & 1;
    int grp = w >> 1;
    const int baseArr[4] = {0, 5, 9, 13};
    const int cntArr[4] = {5, 4, 4, 4};
    int base = baseArr[grp];
    int cnt = cntArr[grp];

    float c[5][4];
    #pragma unroll
    for (int i = 0; i < 5; i++) {
        #pragma unroll
        for (int j = 0; j < 4; j++) {
            c[i][j] = 0.f;
        }
    }

    int arow = mi * 16 + (lane & 15);
    int acol = (lane >> 4) * 8;
    int brow0 = lane & 15;
    int bcol8 = (lane & 16) ? 8 : 0;

    for (int k0 = 0; k0 < 128; k0 += 16) {
        unsigned int a0, a1, a2, a3;
        ldsm_x4(a0, a1, a2, a3, cvta_s(&sX[arow * W1N + k0 + acol]));
        unsigned int b[5][2];
        #pragma unroll
        for (int tp = 0; tp < 2; tp++) {
            int ncol = (base + 2 * tp) * 8 + bcol8;
            ldsm_x4t(b[2 * tp][0], b[2 * tp][1], b[2 * tp + 1][0], b[2 * tp + 1][1],
                     cvta_s(&sW[(k0 + brow0) * W1N + ncol]));
        }
        if (cnt == 5) {
            int ncol = (base + 4) * 8;
            ldsm_x2t(b[4][0], b[4][1], cvta_s(&sW[(k0 + brow0) * W1N + ncol]));
        }
        #pragma unroll
        for (int t = 0; t < 5; t++) {
            if (t < cnt) {
                mma_16816(c[t], a0, a1, a2, a3, b[t][0], b[t][1]);
            }
        }
    }

    int r0 = n0 + mi * 16 + (lane >> 2);
    #pragma unroll
    for (int t = 0; t < 5; t++) {
        if (t >= cnt) continue;
        int ncol = (base + t) * 8 + 2 * (lane & 3);
        if (ncol < 128) {
            if (r0 < Nn) {
                g_hh[(size_t)r0 * 64 + (ncol >> 1)] = __floats2half2_rn(c[t][0], c[t][1]);
            }
            if (r0 + 8 < Nn) {
                g_hh[(size_t)(r0 + 8) * 64 + (ncol >> 1)] = __floats2half2_rn(c[t][2], c[t][3]);
            }
        } else if (ncol < 132) {
            int hh = ncol - 128;
            if (r0 < Nn) {
                g_als1[r0 * 4 + hh] = c[t][0];
                g_als1[r0 * 4 + hh + 1] = c[t][1];
            }
            if (r0 + 8 < Nn) {
                g_als1[(r0 + 8) * 4 + hh] = c[t][2];
                g_als1[(r0 + 8) * 4 + hh + 1] = c[t][3];
            }
        } else {
            int hh = ncol - 132;
            if (r0 < Nn) {
                g_ald1[r0 * 4 + hh] = c[t][0];
                g_ald1[r0 * 4 + hh + 1] = c[t][1];
            }
            if (r0 + 8 < Nn) {
                g_ald1[(r0 + 8) * 4 + hh] = c[t][2];
                g_ald1[(r0 + 8) * 4 + hh + 1] = c[t][3];
            }
        }
    }
}

// fused: edge features -> s1/s2, node sums, logits, exp, CSR scatter (real edges only)
__global__ void edge_scatter(const int* __restrict__ ei, const float* __restrict__ eattr) {
    int e = blockIdx.x * blockDim.x + threadIdx.x;
    if (e >= Ee) return;
    int src = ei[e];
    int dst = ei[Ee + e];
    float a[16];
    const float4* p = (const float4*)(eattr + (size_t)e * 16);
    #pragma unroll
    for (int q = 0; q < 4; q++) {
        float4 v = p[q];
        a[q * 4 + 0] = v.x;
        a[q * 4 + 1] = v.y;
        a[q * 4 + 2] = v.z;
        a[q * 4 + 3] = v.w;
    }
    float s0 = 0.f, s1 = 0.f, s2c = 0.f, s3 = 0.f, s2v = 0.f;
    #pragma unroll
    for (int ed = 0; ed < 16; ed++) {
        float av = a[ed];
        s0 += av * g_v1e[ed * 4 + 0];
        s1 += av * g_v1e[ed * 4 + 1];
        s2c += av * g_v1e[ed * 4 + 2];
        s3 += av * g_v1e[ed * 4 + 3];
        s2v += av * g_v2e[ed];
    }
    g_s2[e] = s2v;
    atomicAdd(&g_ns1[dst * 4 + 0], s0);
    atomicAdd(&g_ns1[dst * 4 + 1], s1);
    atomicAdd(&g_ns1[dst * 4 + 2], s2c);
    atomicAdd(&g_ns1[dst * 4 + 3], s3);
    atomicAdd(&g_ns2[dst], s2v);
    float4 as = *(const float4*)(g_als1 + (size_t)src * 4);
    float4 ad = *(const float4*)(g_ald1 + (size_t)dst * 4);
    int pos = atomicAdd(&g_cursor[dst], 1);
    float4 pv;
    pv.x = __expf(lrelu_f(as.x + ad.x + s0));
    pv.y = __expf(lrelu_f(as.y + ad.y + s1));
    pv.z = __expf(lrelu_f(as.z + ad.z + s2c));
    pv.w = __expf(lrelu_f(as.w + ad.w + s3));
    *(float4*)(g_cp1 + (size_t)pos * 4) = pv;
    g_csrc[pos] = src;
    g_cs2[pos] = s2v;
}

// self-loop slots (cursor now points at each node's last free slot; single writer)
__global__ void selfloop_k() {
    int n = blockIdx.x * blockDim.x + threadIdx.x;
    if (n >= Nn) return;
    float invd = 1.f / fmaxf(g_deg[n], 1.f);
    float4 as = *(const float4*)(g_als1 + (size_t)n * 4);
    float4 ad = *(const float4*)(g_ald1 + (size_t)n * 4);
    float4 ns = *(const float4*)(g_ns1 + (size_t)n * 4);
    float s2v = g_ns2[n] * invd;
    int pos = g_cursor[n];
    float4 pv;
    pv.x = __expf(lrelu_f(as.x + ad.x + ns.x * invd));
    pv.y = __expf(lrelu_f(as.y + ad.y + ns.y * invd));
    pv.z = __expf(lrelu_f(as.z + ad.z + ns.z * invd));
    pv.w = __expf(lrelu_f(as.w + ad.w + ns.w * invd));
    *(float4*)(g_cp1 + (size_t)pos * 4) = pv;
    g_csrc[pos] = n;
    g_cs2[pos] = s2v;
}

// warp-per-node layer1: 2 edges per inner step via LDG.128 across half-warps.
__global__ void agg1_csr(const float* __restrict__ b1) {
    int n = (blockIdx.x * blockDim.x + threadIdx.x) >> 5;
    if (n >= Nn) return;
    int lane = threadIdx.x & 31;
    int sub = lane >> 2;
    int l15 = lane & 15;
    int hl = l15 >> 2;
    int half = lane >> 4;
    int beg = g_off[n];
    int end = g_off[n + 1];

    float acc0 = 0.f, acc1 = 0.f, acc2 = 0.f, acc3 = 0.f;
    float acc4 = 0.f, acc5 = 0.f, acc6 = 0.f, acc7 = 0.f;
    float zl = 0.f;

    for (int g = beg; g < end; g += 8) {
        int idx = g + sub;
        float p = 0.f;
        int src = 0;
        if (idx < end) {
            p = g_cp1[(size_t)idx * 4 + (lane & 3)];
            src = g_csrc[idx];
        }
        zl += p;
        int lim = end - g;
        #pragma unroll
        for (int t = 0; t < 8; t += 2) {
            if (t >= lim) break;
            int slot = t + half;
            float pe = __shfl_sync(0xffffffffu, p, slot * 4 + hl);
            int se = __shfl_sync(0xffffffffu, src, slot * 4);
            uint4 v = *(const uint4*)((const char*)g_hh + (size_t)se * 256 + l15 * 16);
            float2 f0 = __half22float2(*(__half2*)&v.x);
            float2 f1 = __half22float2(*(__half2*)&v.y);
            float2 f2 = __half22float2(*(__half2*)&v.z);
            float2 f3 = __half22float2(*(__half2*)&v.w);
            acc0 += pe * f0.x;
            acc1 += pe * f0.y;
            acc2 += pe * f1.x;
            acc3 += pe * f1.y;
            acc4 += pe * f2.x;
            acc5 += pe * f2.y;
            acc6 += pe * f3.x;
            acc7 += pe * f3.y;
        }
    }
    acc0 += __shfl_xor_sync(0xffffffffu, acc0, 16);
    acc1 += __shfl_xor_sync(0xffffffffu, acc1, 16);
    acc2 += __shfl_xor_sync(0xffffffffu, acc2, 16);
    acc3 += __shfl_xor_sync(0xffffffffu, acc3, 16);
    acc4 += __shfl_xor_sync(0xffffffffu, acc4, 16);
    acc5 += __shfl_xor_sync(0xffffffffu, acc5, 16);
    acc6 += __shfl_xor_sync(0xffffffffu, acc6, 16);
    acc7 += __shfl_xor_sync(0xffffffffu, acc7, 16);
    zl += __shfl_xor_sync(0xffffffffu, zl, 4);
    zl += __shfl_xor_sync(0xffffffffu, zl, 8);
    zl += __shfl_xor_sync(0xffffffffu, zl, 16);
    float inv = 1.f / __shfl_sync(0xffffffffu, zl, hl);

    if (lane < 16) {
        float4 bA = ((const float4*)b1)[l15 * 2];
        float4 bB = ((const float4*)b1)[l15 * 2 + 1];
        uint4 o;
        *(__half2*)&o.x = __floats2half2_rn(elu_f(acc0 * inv + bA.x), elu_f(acc1 * inv + bA.y));
        *(__half2*)&o.y = __floats2half2_rn(elu_f(acc2 * inv + bA.z), elu_f(acc3 * inv + bA.w));
        *(__half2*)&o.z = __floats2half2_rn(elu_f(acc4 * inv + bB.x), elu_f(acc5 * inv + bB.y));
        *(__half2*)&o.w = __floats2half2_rn(elu_f(acc6 * inv + bB.z), elu_f(acc7 * inv + bB.w));
        *(uint4*)((char*)g_h1h + (size_t)n * 256 + l15 * 16) = o;
    }
}

// [h2f | als2 | ald2] = h1 @ W2aug via HMMA. 64 nodes per 256-thread block.
__global__ void gemm2_mma() {
    __shared__ __align__(16) __half sW[128 * W2N];  // 10240 B
    __shared__ __align__(16) __half sX[64 * W1N];   // 17408 B (128 cols used)
    int tid = threadIdx.x;
    int n0 = blockIdx.x * 64;
    for (int i = tid; i < 128 * W2N / 8; i += 256) {
        ((uint4*)sW)[i] = ((const uint4*)g_W2aug)[i];
    }
    for (int i = tid; i < 1024; i += 256) {
        int r = i >> 4;
        int q = i & 15;
        int node = n0 + r;
        uint4 v = (node < Nn) ? ((const uint4*)(g_h1h + (size_t)node * 64))[q]
                              : make_uint4(0u, 0u, 0u, 0u);
        *(uint4*)&sX[r * W1N + q * 8] = v;
    }
    __syncthreads();

    int w = tid >> 5;
    int lane = tid & 31;
    int mi = w & 3;
    int grp = w >> 2;
    int base = grp ? 3 : 0;
    int cnt = grp ? 2 : 3;

    float c[3][4];
    #pragma unroll
    for (int i = 0; i < 3; i++) {
        #pragma unroll
        for (int j = 0; j < 4; j++) {
            c[i][j] = 0.f;
        }
    }

    int arow = mi * 16 + (lane & 15);
    int acol = (lane >> 4) * 8;
    int brow0 = lane & 15;
    int bcol8 = (lane & 16) ? 8 : 0;

    for (int k0 = 0; k0 < 128; k0 += 16) {
        unsigned int a0, a1, a2, a3;
        ldsm_x4(a0, a1, a2, a3, cvta_s(&sX[arow * W1N + k0 + acol]));
        unsigned int b[3][2];
        {
            int ncol = base * 8 + bcol8;
            ldsm_x4t(b[0][0], b[0][1], b[1][0], b[1][1],
                     cvta_s(&sW[(k0 + brow0) * W2N + ncol]));
        }
        if (cnt == 3) {
            int ncol = (base + 2) * 8;
            ldsm_x2t(b[2][0], b[2][1], cvta_s(&sW[(k0 + brow0) * W2N + ncol]));
        }
        #pragma unroll
        for (int t = 0; t < 3; t++) {
            if (t < cnt) {
                mma_16816(c[t], a0, a1, a2, a3, b[t][0], b[t][1]);
            }
        }
    }

    int r0 = n0 + mi * 16 + (lane >> 2);
    #pragma unroll
    for (int t = 0; t < 3; t++) {
        if (t >= cnt) continue;
        int ncol = (base + t) * 8 + 2 * (lane & 3);
        if (ncol < 32) {
            if (r0 < Nn) {
                g_h2fh[(size_t)r0 * 16 + (ncol >> 1)] = __floats2half2_rn(c[t][0], c[t][1]);
            }
            if (r0 + 8 < Nn) {
                g_h2fh[(size_t)(r0 + 8) * 16 + (ncol >> 1)] = __floats2half2_rn(c[t][2], c[t][3]);
            }
        } else if (ncol == 32) {
            if (r0 < Nn) {
                g_als2[r0] = c[t][0];
                g_ald2[r0] = c[t][1];
            }
            if (r0 + 8 < Nn) {
                g_als2[r0 + 8] = c[t][2];
                g_ald2[r0 + 8] = c[t][3];
            }
        }
    }
}

// warp-per-node layer2: 4 edges per inner step via LDG.64.
__global__ void agg2_csr(const float* __restrict__ b2, float* __restrict__ out) {
    int n = (blockIdx.x * blockDim.x + threadIdx.x) >> 5;
    if (n >= Nn) return;
    int lane = threadIdx.x & 31;
    int grp = lane >> 3;
    int chp = lane & 7;
    int beg = g_off[n];
    int end = g_off[n + 1];
    float ald2n = g_ald2[n];

    float a0 = 0.f;
    float a1 = 0.f;
    float a2 = 0.f;
    float a3 = 0.f;
    float zl = 0.f;
    for (int g = beg; g < end; g += 32) {
        int idx = g + lane;
        float p = 0.f;
        int src = 0;
        if (idx < end) {
            src = g_csrc[idx];
            p = __expf(lrelu_f(g_als2[src] + ald2n + g_cs2[idx]));
        }
        zl += p;
        int lim = min(32, end - g);
        #pragma unroll 4
        for (int t = 0; t < 32; t += 4) {
            if (t >= lim) break;
            int slot = t + grp;
            float pe = __shfl_sync(0xffffffffu, p, slot);
            int se = __shfl_sync(0xffffffffu, src, slot);
            float2 v = *(const float2*)((const char*)g_h2fh + (size_t)se * 64 + chp * 8);
            float2 f0 = __half22float2(*(__half2*)&v.x);
            float2 f1 = __half22float2(*(__half2*)&v.y);
            a0 += pe * f0.x;
            a1 += pe * f0.y;
            a2 += pe * f1.x;
            a3 += pe * f1.y;
        }
    }
    a0 += __shfl_xor_sync(0xffffffffu, a0, 8);
    a0 += __shfl_xor_sync(0xffffffffu, a0, 16);
    a1 += __shfl_xor_sync(0xffffffffu, a1, 8);
    a1 += __shfl_xor_sync(0xffffffffu, a1, 16);
    a2 += __shfl_xor_sync(0xffffffffu, a2, 8);
    a2 += __shfl_xor_sync(0xffffffffu, a2, 16);
    a3 += __shfl_xor_sync(0xffffffffu, a3, 8);
    a3 += __shfl_xor_sync(0xffffffffu, a3, 16);
    #pragma unroll
    for (int off = 16; off; off >>= 1) {
        zl += __shfl_xor_sync(0xffffffffu, zl, off);
    }
    if (lane == 0) g_z2[n] = zl;
    if (lane < 8) {
        float inv = 1.f / zl;
        float4 bv = ((const float4*)b2)[chp];
        float4 o;
        o.x = elu_f(a0 * inv + bv.x);
        o.y = elu_f(a1 * inv + bv.y);
        o.z = elu_f(a2 * inv + bv.z);
        o.w = elu_f(a3 * inv + bv.w);
        *(float4*)(out + (size_t)n * 32 + chp * 4) = o;
    }
}

// edge_index_sl (as float) + alpha2 recomputed in original edge order
__global__ void finalize(const int* __restrict__ ei, float* __restrict__ out) {
    int e = blockIdx.x * blockDim.x + threadIdx.x;
    if (e >= EPt) return;
    int s, d;
    float base;
    if (e < Ee) {
        s = ei[e];
        d = ei[Ee + e];
        base = g_s2[e];
    } else {
        s = e - Ee;
        d = s;
        base = g_ns2[d] / fmaxf(g_deg[d], 1.f);
    }
    float v = lrelu_f(g_als2[s] + g_ald2[d] + base);
    out[OFF_EI + e] = (float)s;
    out[OFF_EI + EPt + e] = (float)d;
    out[OFF_ALPHA + e] = __expf(v) / g_z2[d];
}

extern "C" void kernel_launch(void* const* d_in, const int* in_sizes, int n_in,
                              void* d_out, int out_size) {
    const float* x    = (const float*)d_in[0];
    const int*   ei   = (const int*)  d_in[1];
    const float* eat  = (const float*)d_in[2];
    const float* W1   = (const float*)d_in[3];
    const float* W1e  = (const float*)d_in[4];
    const float* a1s  = (const float*)d_in[5];
    const float* a1d  = (const float*)d_in[6];
    const float* a1e  = (const float*)d_in[7];
    const float* b1   = (const float*)d_in[8];
    const float* W2   = (const float*)d_in[9];
    const float* W2e  = (const float*)d_in[10];
    const float* a2s  = (const float*)d_in[11];
    const float* a2d  = (const float*)d_in[12];
    const float* a2e  = (const float*)d_in[13];
    const float* b2   = (const float*)d_in[14];
    float* out = (float*)d_out;
    (void)in_sizes;
    (void)n_in;
    (void)out_size;

    void* p_deg;
    void* p_ns1;
    void* p_ns2;
    cudaGetSymbolAddress(&p_deg, g_deg);
    cudaGetSymbolAddress(&p_ns1, g_ns1);
    cudaGetSymbolAddress(&p_ns2, g_ns2);
    cudaMemsetAsync(p_deg, 0, (size_t)Nn * 4);
    cudaMemsetAsync(p_ns1, 0, (size_t)Nn * 16);
    cudaMemsetAsync(p_ns2, 0, (size_t)Nn * 4);

    prep_all<<<1, 512>>>(W1e, a1e, W2e, a2e, W1, a1s, a1d, W2, a2s, a2d);
    deg_k<<<(Ee + 255) / 256, 256>>>(ei);
    scan1<<<NB_SCAN, 256>>>();
    scan2<<<1, 512>>>();
    scan3<<<NB_SCAN, 256>>>();
    gemm1_mma<<<(Nn + 31) / 32, 256>>>(x);
    edge_scatter<<<(Ee + 255) / 256, 256>>>(ei, eat);
    selfloop_k<<<(Nn + 255) / 256, 256>>>();
    agg1_csr<<<(Nn + 7) / 8, 256>>>(b1);
    gemm2_mma<<<(Nn + 63) / 64, 256>>>();
    agg2_csr<<<(Nn + 7) / 8, 256>>>(b2, out);
    finalize<<<(EPt + 255) / 256, 256>>>(ei, out);
}

// round 11
// speedup vs baseline: 3.1676x; 1.0417x over previous
#include <cuda_runtime.h>
#include <cuda_fp16.h>
#include <cstdint>
#include <math.h>

#define Nn 100000
#define Ee 1600000
#define EPt (Ee + Nn)                 // 1,700,000 edges incl. self loops
#define OFF_EI (Nn * 32)              // 3,200,000
#define OFF_ALPHA (OFF_EI + 2 * EPt)  // 6,600,000
#define NB_SCAN ((Nn + 255) / 256)    // 391
#define W1N 136                       // 128 h cols + 4 als1 + 4 ald1
#define W2N 40                        // 32 h2f cols + als2 + ald2 + 6 pad

// ---------------- scratch (no allocations allowed) ----------------
__device__ __half2 g_hh[Nn * 64];      // layer1 features h = x@W1 (fp16)
__device__ __half2 g_h1h[Nn * 64];     // layer1 output h1 (fp16)
__device__ __half2 g_h2fh[Nn * 16];    // layer2 transformed features (fp16)
__device__ __align__(16) float g_als1[Nn * 4];
__device__ __align__(16) float g_ald1[Nn * 4];
__device__ float g_deg[Nn];
__device__ __align__(16) float g_ns1[Nn * 4];
__device__ float g_ns2[Nn];
__device__ float g_s2[Ee];
__device__ float g_als2[Nn];
__device__ float g_ald2[Nn];
__device__ float g_z2[Nn];
__device__ float g_v1e[64];
__device__ float g_v2e[16];
__device__ __align__(16) float g_A1s[128 * 4];
__device__ __align__(16) float g_A1d[128 * 4];
__device__ __align__(16) float g_A2s[128];
__device__ __align__(16) float g_A2d[128];
__device__ __align__(16) __half g_W1aug[128 * W1N];
__device__ __align__(16) __half g_W2aug[128 * W2N];
// CSR structures
__device__ int   g_off[Nn + 1];
__device__ int   g_cursor[Nn];
__device__ int   g_csrc[EPt];
__device__ __align__(16) __half g_cp1h[EPt * 4];  // exp(lrelu(logit1)) per head (fp16), CSR order
__device__ float g_cs2[EPt];                      // layer2 logit base, CSR order
// scan scratch
__device__ int g_pre[Nn];
__device__ int g_bsum[512];
__device__ int g_boff[512];

__device__ __forceinline__ float elu_f(float v) { return v > 0.f ? v : expm1f(v); }
__device__ __forceinline__ float lrelu_f(float v) { return v > 0.f ? v : 0.2f * v; }

// ---- mma helpers ----
__device__ __forceinline__ unsigned int cvta_s(const void* p) {
    return (unsigned int)__cvta_generic_to_shared(p);
}
__device__ __forceinline__ void ldsm_x4(unsigned int& r0, unsigned int& r1,
                                        unsigned int& r2, unsigned int& r3,
                                        unsigned int addr) {
    asm volatile("ldmatrix.sync.aligned.m8n8.x4.shared.b16 {%0,%1,%2,%3}, [%4];"
                 : "=r"(r0), "=r"(r1), "=r"(r2), "=r"(r3) : "r"(addr));
}
__device__ __forceinline__ void ldsm_x4t(unsigned int& r0, unsigned int& r1,
                                         unsigned int& r2, unsigned int& r3,
                                         unsigned int addr) {
    asm volatile("ldmatrix.sync.aligned.m8n8.x4.trans.shared.b16 {%0,%1,%2,%3}, [%4];"
                 : "=r"(r0), "=r"(r1), "=r"(r2), "=r"(r3) : "r"(addr));
}
__device__ __forceinline__ void ldsm_x2t(unsigned int& r0, unsigned int& r1,
                                         unsigned int addr) {
    asm volatile("ldmatrix.sync.aligned.m8n8.x2.trans.shared.b16 {%0,%1}, [%2];"
                 : "=r"(r0), "=r"(r1) : "r"(addr));
}
__device__ __forceinline__ void mma_16816(float* c, unsigned int a0, unsigned int a1,
                                          unsigned int a2, unsigned int a3,
                                          unsigned int b0, unsigned int b1) {
    asm volatile(
        "mma.sync.aligned.m16n8k16.row.col.f32.f16.f16.f32 "
        "{%0,%1,%2,%3}, {%4,%5,%6,%7}, {%8,%9}, {%0,%1,%2,%3};"
        : "+f"(c[0]), "+f"(c[1]), "+f"(c[2]), "+f"(c[3])
        : "r"(a0), "r"(a1), "r"(a2), "r"(a3), "r"(b0), "r"(b1));
}

// ---------------- kernels ----------------

// precomputes: v1e/v2e, A1s/A1d/A2s/A2d, then augmented fp16 weight matrices
__global__ void prep_all(const float* __restrict__ W1e, const float* __restrict__ a1e,
                         const float* __restrict__ W2e, const float* __restrict__ a2e,
                         const float* __restrict__ W1, const float* __restrict__ a1s,
                         const float* __restrict__ a1d, const float* __restrict__ W2,
                         const float* __restrict__ a2s, const float* __restrict__ a2d) {
    int t = threadIdx.x;  // 512 threads
    if (t < 64) {
        int ed = t >> 2;
        int h = t & 3;
        float s = 0.f;
        #pragma unroll
        for (int c = 0; c < 32; c++) {
            s += W1e[ed * 128 + h * 32 + c] * a1e[h * 32 + c];
        }
        g_v1e[t] = s;
    }
    if (t < 16) {
        float s = 0.f;
        #pragma unroll
        for (int c = 0; c < 32; c++) {
            s += W2e[t * 32 + c] * a2e[c];
        }
        g_v2e[t] = s;
    }
    {
        int k = t >> 2;
        int h = t & 3;
        float s = 0.f;
        float d = 0.f;
        #pragma unroll
        for (int c = 0; c < 32; c++) {
            float w = W1[k * 128 + h * 32 + c];
            s += w * a1s[h * 32 + c];
            d += w * a1d[h * 32 + c];
        }
        g_A1s[t] = s;
        g_A1d[t] = d;
    }
    if (t < 128) {
        float s = 0.f;
        float d = 0.f;
        #pragma unroll
        for (int c = 0; c < 32; c++) {
            float w = W2[t * 32 + c];
            s += w * a2s[c];
            d += w * a2d[c];
        }
        g_A2s[t] = s;
        g_A2d[t] = d;
    }
    __syncthreads();
    for (int i = t; i < 128 * W1N; i += 512) {
        int k = i / W1N;
        int n = i - k * W1N;
        float v;
        if (n < 128) {
            v = W1[k * 128 + n];
        } else if (n < 132) {
            v = g_A1s[k * 4 + (n - 128)];
        } else {
            v = g_A1d[k * 4 + (n - 132)];
        }
        g_W1aug[i] = __float2half_rn(v);
    }
    for (int i = t; i < 128 * W2N; i += 512) {
        int k = i / W2N;
        int n = i - k * W2N;
        float v = 0.f;
        if (n < 32) {
            v = W2[k * 32 + n];
        } else if (n == 32) {
            v = g_A2s[k];
        } else if (n == 33) {
            v = g_A2d[k];
        }
        g_W2aug[i] = __float2half_rn(v);
    }
}

// degree count only
__global__ void deg_k(const int* __restrict__ ei) {
    int e = blockIdx.x * blockDim.x + threadIdx.x;
    if (e >= Ee) return;
    atomicAdd(&g_deg[ei[Ee + e]], 1.f);
}

// ---- parallel exclusive scan of (deg+1) ----
__global__ void scan1() {
    __shared__ int sh[256];
    int t = threadIdx.x;
    int n = blockIdx.x * 256 + t;
    int val = (n < Nn) ? (int)g_deg[n] + 1 : 0;
    sh[t] = val;
    __syncthreads();
    for (int off = 1; off < 256; off <<= 1) {
        int v = (t >= off) ? sh[t - off] : 0;
        __syncthreads();
        sh[t] += v;
        __syncthreads();
    }
    if (n < Nn) g_pre[n] = sh[t] - val;
    if (t == 255) g_bsum[blockIdx.x] = sh[255];
}
__global__ void scan2() {
    __shared__ int sh[512];
    int t = threadIdx.x;
    int val = (t < NB_SCAN) ? g_bsum[t] : 0;
    sh[t] = val;
    __syncthreads();
    for (int off = 1; off < 512; off <<= 1) {
        int v = (t >= off) ? sh[t - off] : 0;
        __syncthreads();
        sh[t] += v;
        __syncthreads();
    }
    g_boff[t] = sh[t] - val;
}
__global__ void scan3() {
    int n = blockIdx.x * 256 + threadIdx.x;
    if (n >= Nn) return;
    int off = g_boff[blockIdx.x] + g_pre[n];
    g_off[n] = off;
    g_cursor[n] = off;
    if (n == 0) g_off[Nn] = EPt;
}

// [h | als1 | ald1] = x @ W1aug via HMMA. 32 nodes per 256-thread block.
__global__ void gemm1_mma(const float* __restrict__ x) {
    __shared__ __align__(16) __half sW[128 * W1N];  // 34816 B
    __shared__ __align__(16) __half sX[32 * W1N];   //  8704 B (128 cols used)
    int tid = threadIdx.x;
    int n0 = blockIdx.x * 32;
    for (int i = tid; i < 128 * W1N / 8; i += 256) {
        ((uint4*)sW)[i] = ((const uint4*)g_W1aug)[i];
    }
    for (int i = tid; i < 2048; i += 256) {
        int r = i >> 6;
        int cp = i & 63;
        int node = n0 + r;
        float2 f = (node < Nn) ? *(const float2*)(x + (size_t)node * 128 + 2 * cp)
                               : make_float2(0.f, 0.f);
        *(__half2*)&sX[r * W1N + 2 * cp] = __floats2half2_rn(f.x, f.y);
    }
    __syncthreads();

    int w = tid >> 5;
    int lane = tid & 31;
    int mi = w & 1;
    int grp = w >> 1;
    const int baseArr[4] = {0, 5, 9, 13};
    const int cntArr[4] = {5, 4, 4, 4};
    int base = baseArr[grp];
    int cnt = cntArr[grp];

    float c[5][4];
    #pragma unroll
    for (int i = 0; i < 5; i++) {
        #pragma unroll
        for (int j = 0; j < 4; j++) {
            c[i][j] = 0.f;
        }
    }

    int arow = mi * 16 + (lane & 15);
    int acol = (lane >> 4) * 8;
    int brow0 = lane & 15;
    int bcol8 = (lane & 16) ? 8 : 0;

    for (int k0 = 0; k0 < 128; k0 += 16) {
        unsigned int a0, a1, a2, a3;
        ldsm_x4(a0, a1, a2, a3, cvta_s(&sX[arow * W1N + k0 + acol]));
        unsigned int b[5][2];
        #pragma unroll
        for (int tp = 0; tp < 2; tp++) {
            int ncol = (base + 2 * tp) * 8 + bcol8;
            ldsm_x4t(b[2 * tp][0], b[2 * tp][1], b[2 * tp + 1][0], b[2 * tp + 1][1],
                     cvta_s(&sW[(k0 + brow0) * W1N + ncol]));
        }
        if (cnt == 5) {
            int ncol = (base + 4) * 8;
            ldsm_x2t(b[4][0], b[4][1], cvta_s(&sW[(k0 + brow0) * W1N + ncol]));
        }
        #pragma unroll
        for (int t = 0; t < 5; t++) {
            if (t < cnt) {
                mma_16816(c[t], a0, a1, a2, a3, b[t][0], b[t][1]);
            }
        }
    }

    int r0 = n0 + mi * 16 + (lane >> 2);
    #pragma unroll
    for (int t = 0; t < 5; t++) {
        if (t >= cnt) continue;
        int ncol = (base + t) * 8 + 2 * (lane & 3);
        if (ncol < 128) {
            if (r0 < Nn) {
                g_hh[(size_t)r0 * 64 + (ncol >> 1)] = __floats2half2_rn(c[t][0], c[t][1]);
            }
            if (r0 + 8 < Nn) {
                g_hh[(size_t)(r0 + 8) * 64 + (ncol >> 1)] = __floats2half2_rn(c[t][2], c[t][3]);
            }
        } else if (ncol < 132) {
            int hh = ncol - 128;
            if (r0 < Nn) {
                g_als1[r0 * 4 + hh] = c[t][0];
                g_als1[r0 * 4 + hh + 1] = c[t][1];
            }
            if (r0 + 8 < Nn) {
                g_als1[(r0 + 8) * 4 + hh] = c[t][2];
                g_als1[(r0 + 8) * 4 + hh + 1] = c[t][3];
            }
        } else {
            int hh = ncol - 132;
            if (r0 < Nn) {
                g_ald1[r0 * 4 + hh] = c[t][0];
                g_ald1[r0 * 4 + hh + 1] = c[t][1];
            }
            if (r0 + 8 < Nn) {
                g_ald1[(r0 + 8) * 4 + hh] = c[t][2];
                g_ald1[(r0 + 8) * 4 + hh + 1] = c[t][3];
            }
        }
    }
}

// fused: edge features -> s1/s2, node sums, logits, exp(fp16), CSR scatter (real edges only)
__global__ void edge_scatter(const int* __restrict__ ei, const float* __restrict__ eattr) {
    int e = blockIdx.x * blockDim.x + threadIdx.x;
    if (e >= Ee) return;
    int src = ei[e];
    int dst = ei[Ee + e];
    // issue the dependent gathers early
    float4 as = *(const float4*)(g_als1 + (size_t)src * 4);
    float4 ad = *(const float4*)(g_ald1 + (size_t)dst * 4);
    int pos = atomicAdd(&g_cursor[dst], 1);
    float a[16];
    const float4* p = (const float4*)(eattr + (size_t)e * 16);
    #pragma unroll
    for (int q = 0; q < 4; q++) {
        float4 v = p[q];
        a[q * 4 + 0] = v.x;
        a[q * 4 + 1] = v.y;
        a[q * 4 + 2] = v.z;
        a[q * 4 + 3] = v.w;
    }
    float s0 = 0.f, s1 = 0.f, s2c = 0.f, s3 = 0.f, s2v = 0.f;
    #pragma unroll
    for (int ed = 0; ed < 16; ed++) {
        float av = a[ed];
        s0 += av * g_v1e[ed * 4 + 0];
        s1 += av * g_v1e[ed * 4 + 1];
        s2c += av * g_v1e[ed * 4 + 2];
        s3 += av * g_v1e[ed * 4 + 3];
        s2v += av * g_v2e[ed];
    }
    g_s2[e] = s2v;
    atomicAdd(&g_ns1[dst * 4 + 0], s0);
    atomicAdd(&g_ns1[dst * 4 + 1], s1);
    atomicAdd(&g_ns1[dst * 4 + 2], s2c);
    atomicAdd(&g_ns1[dst * 4 + 3], s3);
    atomicAdd(&g_ns2[dst], s2v);
    float p0 = __expf(lrelu_f(as.x + ad.x + s0));
    float p1 = __expf(lrelu_f(as.y + ad.y + s1));
    float p2 = __expf(lrelu_f(as.z + ad.z + s2c));
    float p3 = __expf(lrelu_f(as.w + ad.w + s3));
    union { __half2 h2[2]; uint2 u; } cv;
    cv.h2[0] = __floats2half2_rn(p0, p1);
    cv.h2[1] = __floats2half2_rn(p2, p3);
    *(uint2*)(g_cp1h + (size_t)pos * 4) = cv.u;
    g_csrc[pos] = src;
    g_cs2[pos] = s2v;
}

// self-loop slots (cursor now points at each node's last free slot; single writer)
__global__ void selfloop_k() {
    int n = blockIdx.x * blockDim.x + threadIdx.x;
    if (n >= Nn) return;
    float invd = 1.f / fmaxf(g_deg[n], 1.f);
    float4 as = *(const float4*)(g_als1 + (size_t)n * 4);
    float4 ad = *(const float4*)(g_ald1 + (size_t)n * 4);
    float4 ns = *(const float4*)(g_ns1 + (size_t)n * 4);
    float s2v = g_ns2[n] * invd;
    int pos = g_cursor[n];
    float p0 = __expf(lrelu_f(as.x + ad.x + ns.x * invd));
    float p1 = __expf(lrelu_f(as.y + ad.y + ns.y * invd));
    float p2 = __expf(lrelu_f(as.z + ad.z + ns.z * invd));
    float p3 = __expf(lrelu_f(as.w + ad.w + ns.w * invd));
    union { __half2 h2[2]; uint2 u; } cv;
    cv.h2[0] = __floats2half2_rn(p0, p1);
    cv.h2[1] = __floats2half2_rn(p2, p3);
    *(uint2*)(g_cp1h + (size_t)pos * 4) = cv.u;
    g_csrc[pos] = n;
    g_cs2[pos] = s2v;
}

// warp-per-node layer1: 2 edges per inner step via LDG.128; software-pipelined p/src loads.
__global__ void agg1_csr(const float* __restrict__ b1) {
    int n = (blockIdx.x * blockDim.x + threadIdx.x) >> 5;
    if (n >= Nn) return;
    int lane = threadIdx.x & 31;
    int sub = lane >> 2;
    int l15 = lane & 15;
    int hl = l15 >> 2;
    int half = lane >> 4;
    int beg = g_off[n];
    int end = g_off[n + 1];

    float acc0 = 0.f, acc1 = 0.f, acc2 = 0.f, acc3 = 0.f;
    float acc4 = 0.f, acc5 = 0.f, acc6 = 0.f, acc7 = 0.f;
    float zl = 0.f;

    int idx = beg + sub;
    float p = 0.f;
    int src = 0;
    if (idx < end) {
        p = __half2float(g_cp1h[(size_t)idx * 4 + (lane & 3)]);
        src = g_csrc[idx];
    }
    for (int g = beg; g < end; g += 8) {
        // prefetch next block's p/src while processing this one
        int idxn = g + 8 + sub;
        float pn = 0.f;
        int srcn = 0;
        if (idxn < end) {
            pn = __half2float(g_cp1h[(size_t)idxn * 4 + (lane & 3)]);
            srcn = g_csrc[idxn];
        }
        zl += p;
        int lim = end - g;
        #pragma unroll
        for (int t = 0; t < 8; t += 2) {
            if (t >= lim) break;
            int slot = t + half;
            float pe = __shfl_sync(0xffffffffu, p, slot * 4 + hl);
            int se = __shfl_sync(0xffffffffu, src, slot * 4);
            uint4 v = *(const uint4*)((const char*)g_hh + (size_t)se * 256 + l15 * 16);
            float2 f0 = __half22float2(*(__half2*)&v.x);
            float2 f1 = __half22float2(*(__half2*)&v.y);
            float2 f2 = __half22float2(*(__half2*)&v.z);
            float2 f3 = __half22float2(*(__half2*)&v.w);
            acc0 += pe * f0.x;
            acc1 += pe * f0.y;
            acc2 += pe * f1.x;
            acc3 += pe * f1.y;
            acc4 += pe * f2.x;
            acc5 += pe * f2.y;
            acc6 += pe * f3.x;
            acc7 += pe * f3.y;
        }
        p = pn;
        src = srcn;
    }
    acc0 += __shfl_xor_sync(0xffffffffu, acc0, 16);
    acc1 += __shfl_xor_sync(0xffffffffu, acc1, 16);
    acc2 += __shfl_xor_sync(0xffffffffu, acc2, 16);
    acc3 += __shfl_xor_sync(0xffffffffu, acc3, 16);
    acc4 += __shfl_xor_sync(0xffffffffu, acc4, 16);
    acc5 += __shfl_xor_sync(0xffffffffu, acc5, 16);
    acc6 += __shfl_xor_sync(0xffffffffu, acc6, 16);
    acc7 += __shfl_xor_sync(0xffffffffu, acc7, 16);
    zl += __shfl_xor_sync(0xffffffffu, zl, 4);
    zl += __shfl_xor_sync(0xffffffffu, zl, 8);
    zl += __shfl_xor_sync(0xffffffffu, zl, 16);
    float inv = 1.f / __shfl_sync(0xffffffffu, zl, hl);

    if (lane < 16) {
        float4 bA = ((const float4*)b1)[l15 * 2];
        float4 bB = ((const float4*)b1)[l15 * 2 + 1];
        uint4 o;
        *(__half2*)&o.x = __floats2half2_rn(elu_f(acc0 * inv + bA.x), elu_f(acc1 * inv + bA.y));
        *(__half2*)&o.y = __floats2half2_rn(elu_f(acc2 * inv + bA.z), elu_f(acc3 * inv + bA.w));
        *(__half2*)&o.z = __floats2half2_rn(elu_f(acc4 * inv + bB.x), elu_f(acc5 * inv + bB.y));
        *(__half2*)&o.w = __floats2half2_rn(elu_f(acc6 * inv + bB.z), elu_f(acc7 * inv + bB.w));
        *(uint4*)((char*)g_h1h + (size_t)n * 256 + l15 * 16) = o;
    }
}

// [h2f | als2 | ald2] = h1 @ W2aug via HMMA. 64 nodes per 256-thread block.
__global__ void gemm2_mma() {
    __shared__ __align__(16) __half sW[128 * W2N];  // 10240 B
    __shared__ __align__(16) __half sX[64 * W1N];   // 17408 B (128 cols used)
    int tid = threadIdx.x;
    int n0 = blockIdx.x * 64;
    for (int i = tid; i < 128 * W2N / 8; i += 256) {
        ((uint4*)sW)[i] = ((const uint4*)g_W2aug)[i];
    }
    for (int i = tid; i < 1024; i += 256) {
        int r = i >> 4;
        int q = i & 15;
        int node = n0 + r;
        uint4 v = (node < Nn) ? ((const uint4*)(g_h1h + (size_t)node * 64))[q]
                              : make_uint4(0u, 0u, 0u, 0u);
        *(uint4*)&sX[r * W1N + q * 8] = v;
    }
    __syncthreads();

    int w = tid >> 5;
    int lane = tid & 31;
    int mi = w & 3;
    int grp = w >> 2;
    int base = grp ? 3 : 0;
    int cnt = grp ? 2 : 3;

    float c[3][4];
    #pragma unroll
    for (int i = 0; i < 3; i++) {
        #pragma unroll
        for (int j = 0; j < 4; j++) {
            c[i][j] = 0.f;
        }
    }

    int arow = mi * 16 + (lane & 15);
    int acol = (lane >> 4) * 8;
    int brow0 = lane & 15;
    int bcol8 = (lane & 16) ? 8 : 0;

    for (int k0 = 0; k0 < 128; k0 += 16) {
        unsigned int a0, a1, a2, a3;
        ldsm_x4(a0, a1, a2, a3, cvta_s(&sX[arow * W1N + k0 + acol]));
        unsigned int b[3][2];
        {
            int ncol = base * 8 + bcol8;
            ldsm_x4t(b[0][0], b[0][1], b[1][0], b[1][1],
                     cvta_s(&sW[(k0 + brow0) * W2N + ncol]));
        }
        if (cnt == 3) {
            int ncol = (base + 2) * 8;
            ldsm_x2t(b[2][0], b[2][1], cvta_s(&sW[(k0 + brow0) * W2N + ncol]));
        }
        #pragma unroll
        for (int t = 0; t < 3; t++) {
            if (t < cnt) {
                mma_16816(c[t], a0, a1, a2, a3, b[t][0], b[t][1]);
            }
        }
    }

    int r0 = n0 + mi * 16 + (lane >> 2);
    #pragma unroll
    for (int t = 0; t < 3; t++) {
        if (t >= cnt) continue;
        int ncol = (base + t) * 8 + 2 * (lane & 3);
        if (ncol < 32) {
            if (r0 < Nn) {
                g_h2fh[(size_t)r0 * 16 + (ncol >> 1)] = __floats2half2_rn(c[t][0], c[t][1]);
            }
            if (r0 + 8 < Nn) {
                g_h2fh[(size_t)(r0 + 8) * 16 + (ncol >> 1)] = __floats2half2_rn(c[t][2], c[t][3]);
            }
        } else if (ncol == 32) {
            if (r0 < Nn) {
                g_als2[r0] = c[t][0];
                g_ald2[r0] = c[t][1];
            }
            if (r0 + 8 < Nn) {
                g_als2[r0 + 8] = c[t][2];
                g_ald2[r0 + 8] = c[t][3];
            }
        }
    }
}

// warp-per-node layer2: 4 edges per inner step via LDG.64; pipelined src/cs2/als2 loads.
__global__ void agg2_csr(const float* __restrict__ b2, float* __restrict__ out) {
    int n = (blockIdx.x * blockDim.x + threadIdx.x) >> 5;
    if (n >= Nn) return;
    int lane = threadIdx.x & 31;
    int grp = lane >> 3;
    int chp = lane & 7;
    int beg = g_off[n];
    int end = g_off[n + 1];
    float ald2n = g_ald2[n];

    float a0 = 0.f;
    float a1 = 0.f;
    float a2 = 0.f;
    float a3 = 0.f;
    float zl = 0.f;

    int idx = beg + lane;
    int src = 0;
    float cs = 0.f;
    float als = 0.f;
    if (idx < end) {
        src = g_csrc[idx];
        cs = g_cs2[idx];
        als = g_als2[src];
    }
    for (int g = beg; g < end; g += 32) {
        // prefetch next block's src/cs2 and the dependent als2 gather
        int idxn = g + 32 + lane;
        int srcn = 0;
        float csn = 0.f;
        float alsn = 0.f;
        if (idxn < end) {
            srcn = g_csrc[idxn];
            csn = g_cs2[idxn];
            alsn = g_als2[srcn];
        }
        float p = (g + lane < end) ? __expf(lrelu_f(als + ald2n + cs)) : 0.f;
        zl += p;
        int lim = min(32, end - g);
        #pragma unroll 4
        for (int t = 0; t < 32; t += 4) {
            if (t >= lim) break;
            int slot = t + grp;
            float pe = __shfl_sync(0xffffffffu, p, slot);
            int se = __shfl_sync(0xffffffffu, src, slot);
            float2 v = *(const float2*)((const char*)g_h2fh + (size_t)se * 64 + chp * 8);
            float2 f0 = __half22float2(*(__half2*)&v.x);
            float2 f1 = __half22float2(*(__half2*)&v.y);
            a0 += pe * f0.x;
            a1 += pe * f0.y;
            a2 += pe * f1.x;
            a3 += pe * f1.y;
        }
        src = srcn;
        cs = csn;
        als = alsn;
    }
    a0 += __shfl_xor_sync(0xffffffffu, a0, 8);
    a0 += __shfl_xor_sync(0xffffffffu, a0, 16);
    a1 += __shfl_xor_sync(0xffffffffu, a1, 8);
    a1 += __shfl_xor_sync(0xffffffffu, a1, 16);
    a2 += __shfl_xor_sync(0xffffffffu, a2, 8);
    a2 += __shfl_xor_sync(0xffffffffu, a2, 16);
    a3 += __shfl_xor_sync(0xffffffffu, a3, 8);
    a3 += __shfl_xor_sync(0xffffffffu, a3, 16);
    #pragma unroll
    for (int off = 16; off; off >>= 1) {
        zl += __shfl_xor_sync(0xffffffffu, zl, off);
    }
    if (lane == 0) g_z2[n] = zl;
    if (lane < 8) {
        float inv = 1.f / zl;
        float4 bv = ((const float4*)b2)[chp];
        float4 o;
        o.x = elu_f(a0 * inv + bv.x);
        o.y = elu_f(a1 * inv + bv.y);
        o.z = elu_f(a2 * inv + bv.z);
        o.w = elu_f(a3 * inv + bv.w);
        *(float4*)(out + (size_t)n * 32 + chp * 4) = o;
    }
}

// edge_index_sl (as float) + alpha2 recomputed in original edge order
__global__ void finalize(const int* __restrict__ ei, float* __restrict__ out) {
    int e = blockIdx.x * blockDim.x + threadIdx.x;
    if (e >= EPt) return;
    int s, d;
    float base;
    if (e < Ee) {
        s = ei[e];
        d = ei[Ee + e];
        base = g_s2[e];
    } else {
        s = e - Ee;
        d = s;
        base = g_ns2[d] / fmaxf(g_deg[d], 1.f);
    }
    float v = lrelu_f(g_als2[s] + g_ald2[d] + base);
    out[OFF_EI + e] = (float)s;
    out[OFF_EI + EPt + e] = (float)d;
    out[OFF_ALPHA + e] = __expf(v) / g_z2[d];
}

extern "C" void kernel_launch(void* const* d_in, const int* in_sizes, int n_in,
                              void* d_out, int out_size) {
    const float* x    = (const float*)d_in[0];
    const int*   ei   = (const int*)  d_in[1];
    const float* eat  = (const float*)d_in[2];
    const float* W1   = (const float*)d_in[3];
    const float* W1e  = (const float*)d_in[4];
    const float* a1s  = (const float*)d_in[5];
    const float* a1d  = (const float*)d_in[6];
    const float* a1e  = (const float*)d_in[7];
    const float* b1   = (const float*)d_in[8];
    const float* W2   = (const float*)d_in[9];
    const float* W2e  = (const float*)d_in[10];
    const float* a2s  = (const float*)d_in[11];
    const float* a2d  = (const float*)d_in[12];
    const float* a2e  = (const float*)d_in[13];
    const float* b2   = (const float*)d_in[14];
    float* out = (float*)d_out;
    (void)in_sizes;
    (void)n_in;
    (void)out_size;

    void* p_deg;
    void* p_ns1;
    void* p_ns2;
    cudaGetSymbolAddress(&p_deg, g_deg);
    cudaGetSymbolAddress(&p_ns1, g_ns1);
    cudaGetSymbolAddress(&p_ns2, g_ns2);

    // fork-join: side stream runs the deg/scan chain concurrently with prep+gemm1
    cudaStream_t sB;
    cudaStreamCreateWithFlags(&sB, cudaStreamNonBlocking);
    cudaEvent_t evF, evJ;
    cudaEventCreateWithFlags(&evF, cudaEventDisableTiming);
    cudaEventCreateWithFlags(&evJ, cudaEventDisableTiming);

    cudaEventRecord(evF, 0);
    cudaStreamWaitEvent(sB, evF, 0);

    // branch B: memsets + degree + scan
    cudaMemsetAsync(p_deg, 0, (size_t)Nn * 4, sB);
    cudaMemsetAsync(p_ns1, 0, (size_t)Nn * 16, sB);
    cudaMemsetAsync(p_ns2, 0, (size_t)Nn * 4, sB);
    deg_k<<<(Ee + 255) / 256, 256, 0, sB>>>(ei);
    scan1<<<NB_SCAN, 256, 0, sB>>>();
    scan2<<<1, 512, 0, sB>>>();
    scan3<<<NB_SCAN, 256, 0, sB>>>();

    // branch A (legacy stream): weight prep + layer1 GEMM
    prep_all<<<1, 512>>>(W1e, a1e, W2e, a2e, W1, a1s, a1d, W2, a2s, a2d);
    gemm1_mma<<<(Nn + 31) / 32, 256>>>(x);

    cudaEventRecord(evJ, sB);
    cudaStreamWaitEvent(0, evJ, 0);

    edge_scatter<<<(Ee + 255) / 256, 256>>>(ei, eat);
    selfloop_k<<<(Nn + 255) / 256, 256>>>();
    agg1_csr<<<(Nn + 7) / 8, 256>>>(b1);
    gemm2_mma<<<(Nn + 63) / 64, 256>>>();
    agg2_csr<<<(Nn + 7) / 8, 256>>>(b2, out);
    finalize<<<(EPt + 255) / 256, 256>>>(ei, out);

    cudaStreamDestroy(sB);
    cudaEventDestroy(evF);
    cudaEventDestroy(evJ);
}

// round 12
// speedup vs baseline: 3.2795x; 1.0353x over previous
#include <cuda_runtime.h>
#include <cuda_fp16.h>
#include <cstdint>
#include <math.h>

#define Nn 100000
#define Ee 1600000
#define EPt (Ee + Nn)                 // 1,700,000 edges incl. self loops
#define OFF_EI (Nn * 32)              // 3,200,000
#define OFF_ALPHA (OFF_EI + 2 * EPt)  // 6,600,000
#define NB_SCAN ((Nn + 255) / 256)    // 391
#define W1N 136                       // 128 h cols + 4 als1 + 4 ald1
#define W2N 40                        // 32 h2f cols + als2 + ald2 + 6 pad

// ---------------- scratch (no allocations allowed) ----------------
__device__ __half2 g_hh[Nn * 64];      // layer1 features h = x@W1 (fp16)
__device__ __half2 g_h1h[Nn * 64];     // layer1 output h1 (fp16)
__device__ __half2 g_h2fh[Nn * 16];    // layer2 transformed features (fp16)
__device__ __align__(16) float g_als1[Nn * 4];
__device__ __align__(16) float g_ald1[Nn * 4];
__device__ float g_deg[Nn];
__device__ __align__(16) float g_ns1[Nn * 4];
__device__ float g_ns2[Nn];
__device__ float g_s2[Ee];
__device__ float g_als2[Nn];
__device__ float g_ald2[Nn];
__device__ float g_z2[Nn];
__device__ float g_v1e[64];
__device__ float g_v2e[16];
__device__ __align__(16) float g_A1s[128 * 4];
__device__ __align__(16) float g_A1d[128 * 4];
__device__ __align__(16) float g_A2s[128];
__device__ __align__(16) float g_A2d[128];
__device__ __align__(16) __half g_W1aug[128 * W1N];
__device__ __align__(16) __half g_W2aug[128 * W2N];
// CSR structures: packed 16-byte record per slot: {half p[4]; int src; float cs2}
__device__ int   g_off[Nn + 1];
__device__ int   g_cursor[Nn];
__device__ __align__(16) uint4 g_edge[EPt];
// scan scratch
__device__ int g_pre[Nn];
__device__ int g_bsum[512];
__device__ int g_boff[512];

__device__ __forceinline__ float elu_f(float v) { return v > 0.f ? v : expm1f(v); }
__device__ __forceinline__ float lrelu_f(float v) { return v > 0.f ? v : 0.2f * v; }

// ---- mma helpers ----
__device__ __forceinline__ unsigned int cvta_s(const void* p) {
    return (unsigned int)__cvta_generic_to_shared(p);
}
__device__ __forceinline__ void ldsm_x4(unsigned int& r0, unsigned int& r1,
                                        unsigned int& r2, unsigned int& r3,
                                        unsigned int addr) {
    asm volatile("ldmatrix.sync.aligned.m8n8.x4.shared.b16 {%0,%1,%2,%3}, [%4];"
                 : "=r"(r0), "=r"(r1), "=r"(r2), "=r"(r3) : "r"(addr));
}
__device__ __forceinline__ void ldsm_x4t(unsigned int& r0, unsigned int& r1,
                                         unsigned int& r2, unsigned int& r3,
                                         unsigned int addr) {
    asm volatile("ldmatrix.sync.aligned.m8n8.x4.trans.shared.b16 {%0,%1,%2,%3}, [%4];"
                 : "=r"(r0), "=r"(r1), "=r"(r2), "=r"(r3) : "r"(addr));
}
__device__ __forceinline__ void ldsm_x2t(unsigned int& r0, unsigned int& r1,
                                         unsigned int addr) {
    asm volatile("ldmatrix.sync.aligned.m8n8.x2.trans.shared.b16 {%0,%1}, [%2];"
                 : "=r"(r0), "=r"(r1) : "r"(addr));
}
__device__ __forceinline__ void mma_16816(float* c, unsigned int a0, unsigned int a1,
                                          unsigned int a2, unsigned int a3,
                                          unsigned int b0, unsigned int b1) {
    asm volatile(
        "mma.sync.aligned.m16n8k16.row.col.f32.f16.f16.f32 "
        "{%0,%1,%2,%3}, {%4,%5,%6,%7}, {%8,%9}, {%0,%1,%2,%3};"
        : "+f"(c[0]), "+f"(c[1]), "+f"(c[2]), "+f"(c[3])
        : "r"(a0), "r"(a1), "r"(a2), "r"(a3), "r"(b0), "r"(b1));
}

// ---------------- kernels ----------------

// precomputes: v1e/v2e, A1s/A1d/A2s/A2d, then augmented fp16 weight matrices
__global__ void prep_all(const float* __restrict__ W1e, const float* __restrict__ a1e,
                         const float* __restrict__ W2e, const float* __restrict__ a2e,
                         const float* __restrict__ W1, const float* __restrict__ a1s,
                         const float* __restrict__ a1d, const float* __restrict__ W2,
                         const float* __restrict__ a2s, const float* __restrict__ a2d) {
    int t = threadIdx.x;  // 512 threads
    if (t < 64) {
        int ed = t >> 2;
        int h = t & 3;
        float s = 0.f;
        #pragma unroll
        for (int c = 0; c < 32; c++) {
            s += W1e[ed * 128 + h * 32 + c] * a1e[h * 32 + c];
        }
        g_v1e[t] = s;
    }
    if (t < 16) {
        float s = 0.f;
        #pragma unroll
        for (int c = 0; c < 32; c++) {
            s += W2e[t * 32 + c] * a2e[c];
        }
        g_v2e[t] = s;
    }
    {
        int k = t >> 2;
        int h = t & 3;
        float s = 0.f;
        float d = 0.f;
        #pragma unroll
        for (int c = 0; c < 32; c++) {
            float w = W1[k * 128 + h * 32 + c];
            s += w * a1s[h * 32 + c];
            d += w * a1d[h * 32 + c];
        }
        g_A1s[t] = s;
        g_A1d[t] = d;
    }
    if (t < 128) {
        float s = 0.f;
        float d = 0.f;
        #pragma unroll
        for (int c = 0; c < 32; c++) {
            float w = W2[t * 32 + c];
            s += w * a2s[c];
            d += w * a2d[c];
        }
        g_A2s[t] = s;
        g_A2d[t] = d;
    }
    __syncthreads();
    for (int i = t; i < 128 * W1N; i += 512) {
        int k = i / W1N;
        int n = i - k * W1N;
        float v;
        if (n < 128) {
            v = W1[k * 128 + n];
        } else if (n < 132) {
            v = g_A1s[k * 4 + (n - 128)];
        } else {
            v = g_A1d[k * 4 + (n - 132)];
        }
        g_W1aug[i] = __float2half_rn(v);
    }
    for (int i = t; i < 128 * W2N; i += 512) {
        int k = i / W2N;
        int n = i - k * W2N;
        float v = 0.f;
        if (n < 32) {
            v = W2[k * 32 + n];
        } else if (n == 32) {
            v = g_A2s[k];
        } else if (n == 33) {
            v = g_A2d[k];
        }
        g_W2aug[i] = __float2half_rn(v);
    }
}

// degree count only
__global__ void deg_k(const int* __restrict__ ei) {
    int e = blockIdx.x * blockDim.x + threadIdx.x;
    if (e >= Ee) return;
    atomicAdd(&g_deg[ei[Ee + e]], 1.f);
}

// ---- parallel exclusive scan of (deg+1) ----
__global__ void scan1() {
    __shared__ int sh[256];
    int t = threadIdx.x;
    int n = blockIdx.x * 256 + t;
    int val = (n < Nn) ? (int)g_deg[n] + 1 : 0;
    sh[t] = val;
    __syncthreads();
    for (int off = 1; off < 256; off <<= 1) {
        int v = (t >= off) ? sh[t - off] : 0;
        __syncthreads();
        sh[t] += v;
        __syncthreads();
    }
    if (n < Nn) g_pre[n] = sh[t] - val;
    if (t == 255) g_bsum[blockIdx.x] = sh[255];
}
__global__ void scan2() {
    __shared__ int sh[512];
    int t = threadIdx.x;
    int val = (t < NB_SCAN) ? g_bsum[t] : 0;
    sh[t] = val;
    __syncthreads();
    for (int off = 1; off < 512; off <<= 1) {
        int v = (t >= off) ? sh[t - off] : 0;
        __syncthreads();
        sh[t] += v;
        __syncthreads();
    }
    g_boff[t] = sh[t] - val;
}
__global__ void scan3() {
    int n = blockIdx.x * 256 + threadIdx.x;
    if (n >= Nn) return;
    int off = g_boff[blockIdx.x] + g_pre[n];
    g_off[n] = off;
    g_cursor[n] = off;
    if (n == 0) g_off[Nn] = EPt;
}

// [h | als1 | ald1] = x @ W1aug via HMMA. 32 nodes per 256-thread block.
__global__ void gemm1_mma(const float* __restrict__ x) {
    __shared__ __align__(16) __half sW[128 * W1N];  // 34816 B
    __shared__ __align__(16) __half sX[32 * W1N];   //  8704 B (128 cols used)
    int tid = threadIdx.x;
    int n0 = blockIdx.x * 32;
    for (int i = tid; i < 128 * W1N / 8; i += 256) {
        ((uint4*)sW)[i] = ((const uint4*)g_W1aug)[i];
    }
    for (int i = tid; i < 2048; i += 256) {
        int r = i >> 6;
        int cp = i & 63;
        int node = n0 + r;
        float2 f = (node < Nn) ? *(const float2*)(x + (size_t)node * 128 + 2 * cp)
                               : make_float2(0.f, 0.f);
        *(__half2*)&sX[r * W1N + 2 * cp] = __floats2half2_rn(f.x, f.y);
    }
    __syncthreads();

    int w = tid >> 5;
    int lane = tid & 31;
    int mi = w & 1;
    int grp = w >> 1;
    const int baseArr[4] = {0, 5, 9, 13};
    const int cntArr[4] = {5, 4, 4, 4};
    int base = baseArr[grp];
    int cnt = cntArr[grp];

    float c[5][4];
    #pragma unroll
    for (int i = 0; i < 5; i++) {
        #pragma unroll
        for (int j = 0; j < 4; j++) {
            c[i][j] = 0.f;
        }
    }

    int arow = mi * 16 + (lane & 15);
    int acol = (lane >> 4) * 8;
    int brow0 = lane & 15;
    int bcol8 = (lane & 16) ? 8 : 0;

    for (int k0 = 0; k0 < 128; k0 += 16) {
        unsigned int a0, a1, a2, a3;
        ldsm_x4(a0, a1, a2, a3, cvta_s(&sX[arow * W1N + k0 + acol]));
        unsigned int b[5][2];
        #pragma unroll
        for (int tp = 0; tp < 2; tp++) {
            int ncol = (base + 2 * tp) * 8 + bcol8;
            ldsm_x4t(b[2 * tp][0], b[2 * tp][1], b[2 * tp + 1][0], b[2 * tp + 1][1],
                     cvta_s(&sW[(k0 + brow0) * W1N + ncol]));
        }
        if (cnt == 5) {
            int ncol = (base + 4) * 8;
            ldsm_x2t(b[4][0], b[4][1], cvta_s(&sW[(k0 + brow0) * W1N + ncol]));
        }
        #pragma unroll
        for (int t = 0; t < 5; t++) {
            if (t < cnt) {
                mma_16816(c[t], a0, a1, a2, a3, b[t][0], b[t][1]);
            }
        }
    }

    int r0 = n0 + mi * 16 + (lane >> 2);
    #pragma unroll
    for (int t = 0; t < 5; t++) {
        if (t >= cnt) continue;
        int ncol = (base + t) * 8 + 2 * (lane & 3);
        if (ncol < 128) {
            if (r0 < Nn) {
                g_hh[(size_t)r0 * 64 + (ncol >> 1)] = __floats2half2_rn(c[t][0], c[t][1]);
            }
            if (r0 + 8 < Nn) {
                g_hh[(size_t)(r0 + 8) * 64 + (ncol >> 1)] = __floats2half2_rn(c[t][2], c[t][3]);
            }
        } else if (ncol < 132) {
            int hh = ncol - 128;
            if (r0 < Nn) {
                g_als1[r0 * 4 + hh] = c[t][0];
                g_als1[r0 * 4 + hh + 1] = c[t][1];
            }
            if (r0 + 8 < Nn) {
                g_als1[(r0 + 8) * 4 + hh] = c[t][2];
                g_als1[(r0 + 8) * 4 + hh + 1] = c[t][3];
            }
        } else {
            int hh = ncol - 132;
            if (r0 < Nn) {
                g_ald1[r0 * 4 + hh] = c[t][0];
                g_ald1[r0 * 4 + hh + 1] = c[t][1];
            }
            if (r0 + 8 < Nn) {
                g_ald1[(r0 + 8) * 4 + hh] = c[t][2];
                g_ald1[(r0 + 8) * 4 + hh + 1] = c[t][3];
            }
        }
    }
}

// fused: edge features -> s1/s2, node sums, logits, exp(fp16), packed CSR scatter
__global__ void edge_scatter(const int* __restrict__ ei, const float* __restrict__ eattr) {
    int e = blockIdx.x * blockDim.x + threadIdx.x;
    if (e >= Ee) return;
    int src = ei[e];
    int dst = ei[Ee + e];
    // issue the dependent gathers early
    float4 as = *(const float4*)(g_als1 + (size_t)src * 4);
    float4 ad = *(const float4*)(g_ald1 + (size_t)dst * 4);
    int pos = atomicAdd(&g_cursor[dst], 1);
    float a[16];
    const float4* p = (const float4*)(eattr + (size_t)e * 16);
    #pragma unroll
    for (int q = 0; q < 4; q++) {
        float4 v = p[q];
        a[q * 4 + 0] = v.x;
        a[q * 4 + 1] = v.y;
        a[q * 4 + 2] = v.z;
        a[q * 4 + 3] = v.w;
    }
    float s0 = 0.f, s1 = 0.f, s2c = 0.f, s3 = 0.f, s2v = 0.f;
    #pragma unroll
    for (int ed = 0; ed < 16; ed++) {
        float av = a[ed];
        s0 += av * g_v1e[ed * 4 + 0];
        s1 += av * g_v1e[ed * 4 + 1];
        s2c += av * g_v1e[ed * 4 + 2];
        s3 += av * g_v1e[ed * 4 + 3];
        s2v += av * g_v2e[ed];
    }
    g_s2[e] = s2v;
    atomicAdd(&g_ns1[dst * 4 + 0], s0);
    atomicAdd(&g_ns1[dst * 4 + 1], s1);
    atomicAdd(&g_ns1[dst * 4 + 2], s2c);
    atomicAdd(&g_ns1[dst * 4 + 3], s3);
    atomicAdd(&g_ns2[dst], s2v);
    float p0 = __expf(lrelu_f(as.x + ad.x + s0));
    float p1 = __expf(lrelu_f(as.y + ad.y + s1));
    float p2 = __expf(lrelu_f(as.z + ad.z + s2c));
    float p3 = __expf(lrelu_f(as.w + ad.w + s3));
    union { struct { __half2 pa; __half2 pb; int src; float cs2; } rec; uint4 u; } cv;
    cv.rec.pa = __floats2half2_rn(p0, p1);
    cv.rec.pb = __floats2half2_rn(p2, p3);
    cv.rec.src = src;
    cv.rec.cs2 = s2v;
    g_edge[pos] = cv.u;
}

// self-loop slots (cursor now points at each node's last free slot; single writer)
__global__ void selfloop_k() {
    int n = blockIdx.x * blockDim.x + threadIdx.x;
    if (n >= Nn) return;
    float invd = 1.f / fmaxf(g_deg[n], 1.f);
    float4 as = *(const float4*)(g_als1 + (size_t)n * 4);
    float4 ad = *(const float4*)(g_ald1 + (size_t)n * 4);
    float4 ns = *(const float4*)(g_ns1 + (size_t)n * 4);
    float s2v = g_ns2[n] * invd;
    int pos = g_cursor[n];
    float p0 = __expf(lrelu_f(as.x + ad.x + ns.x * invd));
    float p1 = __expf(lrelu_f(as.y + ad.y + ns.y * invd));
    float p2 = __expf(lrelu_f(as.z + ad.z + ns.z * invd));
    float p3 = __expf(lrelu_f(as.w + ad.w + ns.w * invd));
    union { struct { __half2 pa; __half2 pb; int src; float cs2; } rec; uint4 u; } cv;
    cv.rec.pa = __floats2half2_rn(p0, p1);
    cv.rec.pb = __floats2half2_rn(p2, p3);
    cv.rec.src = n;
    cv.rec.cs2 = s2v;
    g_edge[pos] = cv.u;
}

// warp-per-node layer1: packed edge record (1 coalesced LDG.128 per 8 edges), pipelined.
__global__ void agg1_csr(const float* __restrict__ b1) {
    int n = (blockIdx.x * blockDim.x + threadIdx.x) >> 5;
    if (n >= Nn) return;
    int lane = threadIdx.x & 31;
    int sub = lane >> 2;          // edge slot within 8-block
    int hq = lane & 3;            // head for z accumulation
    int l15 = lane & 15;
    int hl = l15 >> 2;            // head owning this lane's 8 channels
    int half = lane >> 4;
    int beg = g_off[n];
    int end = g_off[n + 1];

    float acc0 = 0.f, acc1 = 0.f, acc2 = 0.f, acc3 = 0.f;
    float acc4 = 0.f, acc5 = 0.f, acc6 = 0.f, acc7 = 0.f;
    float zl = 0.f;

    int idx = beg + sub;
    float p = 0.f;
    int src = 0;
    if (idx < end) {
        uint4 r = g_edge[idx];
        const __half* ph = (const __half*)&r;
        p = __half2float(ph[hq]);
        src = ((const int*)&r)[2];
    }
    for (int g = beg; g < end; g += 8) {
        int idxn = g + 8 + sub;
        float pn = 0.f;
        int srcn = 0;
        if (idxn < end) {
            uint4 r = g_edge[idxn];
            const __half* ph = (const __half*)&r;
            pn = __half2float(ph[hq]);
            srcn = ((const int*)&r)[2];
        }
        zl += p;
        int lim = end - g;
        #pragma unroll
        for (int t = 0; t < 8; t += 2) {
            if (t >= lim) break;
            int slot = t + half;
            float pe = __shfl_sync(0xffffffffu, p, slot * 4 + hl);
            int se = __shfl_sync(0xffffffffu, src, slot * 4);
            uint4 v = *(const uint4*)((const char*)g_hh + (size_t)se * 256 + l15 * 16);
            float2 f0 = __half22float2(*(__half2*)&v.x);
            float2 f1 = __half22float2(*(__half2*)&v.y);
            float2 f2 = __half22float2(*(__half2*)&v.z);
            float2 f3 = __half22float2(*(__half2*)&v.w);
            acc0 += pe * f0.x;
            acc1 += pe * f0.y;
            acc2 += pe * f1.x;
            acc3 += pe * f1.y;
            acc4 += pe * f2.x;
            acc5 += pe * f2.y;
            acc6 += pe * f3.x;
            acc7 += pe * f3.y;
        }
        p = pn;
        src = srcn;
    }
    acc0 += __shfl_xor_sync(0xffffffffu, acc0, 16);
    acc1 += __shfl_xor_sync(0xffffffffu, acc1, 16);
    acc2 += __shfl_xor_sync(0xffffffffu, acc2, 16);
    acc3 += __shfl_xor_sync(0xffffffffu, acc3, 16);
    acc4 += __shfl_xor_sync(0xffffffffu, acc4, 16);
    acc5 += __shfl_xor_sync(0xffffffffu, acc5, 16);
    acc6 += __shfl_xor_sync(0xffffffffu, acc6, 16);
    acc7 += __shfl_xor_sync(0xffffffffu, acc7, 16);
    zl += __shfl_xor_sync(0xffffffffu, zl, 4);
    zl += __shfl_xor_sync(0xffffffffu, zl, 8);
    zl += __shfl_xor_sync(0xffffffffu, zl, 16);
    float inv = 1.f / __shfl_sync(0xffffffffu, zl, hl);

    if (lane < 16) {
        float4 bA = ((const float4*)b1)[l15 * 2];
        float4 bB = ((const float4*)b1)[l15 * 2 + 1];
        uint4 o;
        *(__half2*)&o.x = __floats2half2_rn(elu_f(acc0 * inv + bA.x), elu_f(acc1 * inv + bA.y));
        *(__half2*)&o.y = __floats2half2_rn(elu_f(acc2 * inv + bA.z), elu_f(acc3 * inv + bA.w));
        *(__half2*)&o.z = __floats2half2_rn(elu_f(acc4 * inv + bB.x), elu_f(acc5 * inv + bB.y));
        *(__half2*)&o.w = __floats2half2_rn(elu_f(acc6 * inv + bB.z), elu_f(acc7 * inv + bB.w));
        *(uint4*)((char*)g_h1h + (size_t)n * 256 + l15 * 16) = o;
    }
}

// [h2f | als2 | ald2] = h1 @ W2aug via HMMA. 64 nodes per 256-thread block.
__global__ void gemm2_mma() {
    __shared__ __align__(16) __half sW[128 * W2N];  // 10240 B
    __shared__ __align__(16) __half sX[64 * W1N];   // 17408 B (128 cols used)
    int tid = threadIdx.x;
    int n0 = blockIdx.x * 64;
    for (int i = tid; i < 128 * W2N / 8; i += 256) {
        ((uint4*)sW)[i] = ((const uint4*)g_W2aug)[i];
    }
    for (int i = tid; i < 1024; i += 256) {
        int r = i >> 4;
        int q = i & 15;
        int node = n0 + r;
        uint4 v = (node < Nn) ? ((const uint4*)(g_h1h + (size_t)node * 64))[q]
                              : make_uint4(0u, 0u, 0u, 0u);
        *(uint4*)&sX[r * W1N + q * 8] = v;
    }
    __syncthreads();

    int w = tid >> 5;
    int lane = tid & 31;
    int mi = w & 3;
    int grp = w >> 2;
    int base = grp ? 3 : 0;
    int cnt = grp ? 2 : 3;

    float c[3][4];
    #pragma unroll
    for (int i = 0; i < 3; i++) {
        #pragma unroll
        for (int j = 0; j < 4; j++) {
            c[i][j] = 0.f;
        }
    }

    int arow = mi * 16 + (lane & 15);
    int acol = (lane >> 4) * 8;
    int brow0 = lane & 15;
    int bcol8 = (lane & 16) ? 8 : 0;

    for (int k0 = 0; k0 < 128; k0 += 16) {
        unsigned int a0, a1, a2, a3;
        ldsm_x4(a0, a1, a2, a3, cvta_s(&sX[arow * W1N + k0 + acol]));
        unsigned int b[3][2];
        {
            int ncol = base * 8 + bcol8;
            ldsm_x4t(b[0][0], b[0][1], b[1][0], b[1][1],
                     cvta_s(&sW[(k0 + brow0) * W2N + ncol]));
        }
        if (cnt == 3) {
            int ncol = (base + 2) * 8;
            ldsm_x2t(b[2][0], b[2][1], cvta_s(&sW[(k0 + brow0) * W2N + ncol]));
        }
        #pragma unroll
        for (int t = 0; t < 3; t++) {
            if (t < cnt) {
                mma_16816(c[t], a0, a1, a2, a3, b[t][0], b[t][1]);
            }
        }
    }

    int r0 = n0 + mi * 16 + (lane >> 2);
    #pragma unroll
    for (int t = 0; t < 3; t++) {
        if (t >= cnt) continue;
        int ncol = (base + t) * 8 + 2 * (lane & 3);
        if (ncol < 32) {
            if (r0 < Nn) {
                g_h2fh[(size_t)r0 * 16 + (ncol >> 1)] = __floats2half2_rn(c[t][0], c[t][1]);
            }
            if (r0 + 8 < Nn) {
                g_h2fh[(size_t)(r0 + 8) * 16 + (ncol >> 1)] = __floats2half2_rn(c[t][2], c[t][3]);
            }
        } else if (ncol == 32) {
            if (r0 < Nn) {
                g_als2[r0] = c[t][0];
                g_ald2[r0] = c[t][1];
            }
            if (r0 + 8 < Nn) {
                g_als2[r0 + 8] = c[t][2];
                g_ald2[r0 + 8] = c[t][3];
            }
        }
    }
}

// warp-per-node layer2: packed edge record, pipelined src/cs2/als2 loads.
__global__ void agg2_csr(const float* __restrict__ b2, float* __restrict__ out) {
    int n = (blockIdx.x * blockDim.x + threadIdx.x) >> 5;
    if (n >= Nn) return;
    int lane = threadIdx.x & 31;
    int grp = lane >> 3;
    int chp = lane & 7;
    int beg = g_off[n];
    int end = g_off[n + 1];
    float ald2n = g_ald2[n];

    float a0 = 0.f;
    float a1 = 0.f;
    float a2 = 0.f;
    float a3 = 0.f;
    float zl = 0.f;

    int idx = beg + lane;
    int src = 0;
    float cs = 0.f;
    float als = 0.f;
    if (idx < end) {
        uint4 r = g_edge[idx];
        src = ((const int*)&r)[2];
        cs = ((const float*)&r)[3];
        als = g_als2[src];
    }
    for (int g = beg; g < end; g += 32) {
        int idxn = g + 32 + lane;
        int srcn = 0;
        float csn = 0.f;
        float alsn = 0.f;
        if (idxn < end) {
            uint4 r = g_edge[idxn];
            srcn = ((const int*)&r)[2];
            csn = ((const float*)&r)[3];
            alsn = g_als2[srcn];
        }
        float p = (g + lane < end) ? __expf(lrelu_f(als + ald2n + cs)) : 0.f;
        zl += p;
        int lim = min(32, end - g);
        #pragma unroll 4
        for (int t = 0; t < 32; t += 4) {
            if (t >= lim) break;
            int slot = t + grp;
            float pe = __shfl_sync(0xffffffffu, p, slot);
            int se = __shfl_sync(0xffffffffu, src, slot);
            float2 v = *(const float2*)((const char*)g_h2fh + (size_t)se * 64 + chp * 8);
            float2 f0 = __half22float2(*(__half2*)&v.x);
            float2 f1 = __half22float2(*(__half2*)&v.y);
            a0 += pe * f0.x;
            a1 += pe * f0.y;
            a2 += pe * f1.x;
            a3 += pe * f1.y;
        }
        src = srcn;
        cs = csn;
        als = alsn;
    }
    a0 += __shfl_xor_sync(0xffffffffu, a0, 8);
    a0 += __shfl_xor_sync(0xffffffffu, a0, 16);
    a1 += __shfl_xor_sync(0xffffffffu, a1, 8);
    a1 += __shfl_xor_sync(0xffffffffu, a1, 16);
    a2 += __shfl_xor_sync(0xffffffffu, a2, 8);
    a2 += __shfl_xor_sync(0xffffffffu, a2, 16);
    a3 += __shfl_xor_sync(0xffffffffu, a3, 8);
    a3 += __shfl_xor_sync(0xffffffffu, a3, 16);
    #pragma unroll
    for (int off = 16; off; off >>= 1) {
        zl += __shfl_xor_sync(0xffffffffu, zl, off);
    }
    if (lane == 0) g_z2[n] = zl;
    if (lane < 8) {
        float inv = 1.f / zl;
        float4 bv = ((const float4*)b2)[chp];
        float4 o;
        o.x = elu_f(a0 * inv + bv.x);
        o.y = elu_f(a1 * inv + bv.y);
        o.z = elu_f(a2 * inv + bv.z);
        o.w = elu_f(a3 * inv + bv.w);
        *(float4*)(out + (size_t)n * 32 + chp * 4) = o;
    }
}

// edge_index_sl (as float) + alpha2 recomputed in original edge order
__global__ void finalize(const int* __restrict__ ei, float* __restrict__ out) {
    int e = blockIdx.x * blockDim.x + threadIdx.x;
    if (e >= EPt) return;
    int s, d;
    float base;
    if (e < Ee) {
        s = ei[e];
        d = ei[Ee + e];
        base = g_s2[e];
    } else {
        s = e - Ee;
        d = s;
        base = g_ns2[d] / fmaxf(g_deg[d], 1.f);
    }
    float v = lrelu_f(g_als2[s] + g_ald2[d] + base);
    out[OFF_EI + e] = (float)s;
    out[OFF_EI + EPt + e] = (float)d;
    out[OFF_ALPHA + e] = __expf(v) / g_z2[d];
}

extern "C" void kernel_launch(void* const* d_in, const int* in_sizes, int n_in,
                              void* d_out, int out_size) {
    const float* x    = (const float*)d_in[0];
    const int*   ei   = (const int*)  d_in[1];
    const float* eat  = (const float*)d_in[2];
    const float* W1   = (const float*)d_in[3];
    const float* W1e  = (const float*)d_in[4];
    const float* a1s  = (const float*)d_in[5];
    const float* a1d  = (const float*)d_in[6];
    const float* a1e  = (const float*)d_in[7];
    const float* b1   = (const float*)d_in[8];
    const float* W2   = (const float*)d_in[9];
    const float* W2e  = (const float*)d_in[10];
    const float* a2s  = (const float*)d_in[11];
    const float* a2d  = (const float*)d_in[12];
    const float* a2e  = (const float*)d_in[13];
    const float* b2   = (const float*)d_in[14];
    float* out = (float*)d_out;
    (void)in_sizes;
    (void)n_in;
    (void)out_size;

    void* p_deg;
    void* p_ns1;
    void* p_ns2;
    cudaGetSymbolAddress(&p_deg, g_deg);
    cudaGetSymbolAddress(&p_ns1, g_ns1);
    cudaGetSymbolAddress(&p_ns2, g_ns2);

    // fork-join: side stream runs the deg/scan chain concurrently with prep+gemm1
    cudaStream_t sB;
    cudaStreamCreateWithFlags(&sB, cudaStreamNonBlocking);
    cudaEvent_t evF, evJ;
    cudaEventCreateWithFlags(&evF, cudaEventDisableTiming);
    cudaEventCreateWithFlags(&evJ, cudaEventDisableTiming);

    cudaEventRecord(evF, 0);
    cudaStreamWaitEvent(sB, evF, 0);

    // branch B: memsets + degree + scan
    cudaMemsetAsync(p_deg, 0, (size_t)Nn * 4, sB);
    cudaMemsetAsync(p_ns1, 0, (size_t)Nn * 16, sB);
    cudaMemsetAsync(p_ns2, 0, (size_t)Nn * 4, sB);
    deg_k<<<(Ee + 255) / 256, 256, 0, sB>>>(ei);
    scan1<<<NB_SCAN, 256, 0, sB>>>();
    scan2<<<1, 512, 0, sB>>>();
    scan3<<<NB_SCAN, 256, 0, sB>>>();

    // branch A (legacy stream): weight prep + layer1 GEMM
    prep_all<<<1, 512>>>(W1e, a1e, W2e, a2e, W1, a1s, a1d, W2, a2s, a2d);
    gemm1_mma<<<(Nn + 31) / 32, 256>>>(x);

    cudaEventRecord(evJ, sB);
    cudaStreamWaitEvent(0, evJ, 0);

    edge_scatter<<<(Ee + 255) / 256, 256>>>(ei, eat);
    selfloop_k<<<(Nn + 255) / 256, 256>>>();
    agg1_csr<<<(Nn + 7) / 8, 256>>>(b1);
    gemm2_mma<<<(Nn + 63) / 64, 256>>>();
    agg2_csr<<<(Nn + 7) / 8, 256>>>(b2, out);
    finalize<<<(EPt + 255) / 256, 256>>>(ei, out);

    cudaStreamDestroy(sB);
    cudaEventDestroy(evF);
    cudaEventDestroy(evJ);
}

// round 13
// speedup vs baseline: 3.3465x; 1.0205x over previous
#include <cuda_runtime.h>
#include <cuda_fp16.h>
#include <cstdint>
#include <math.h>

#define Nn 100000
#define Ee 1600000
#define EPt (Ee + Nn)                 // 1,700,000 edges incl. self loops
#define OFF_EI (Nn * 32)              // 3,200,000
#define OFF_ALPHA (OFF_EI + 2 * EPt)  // 6,600,000
#define NB_SCAN ((Nn + 255) / 256)    // 391
#define W1N 136                       // 128 h cols + 4 als1 + 4 ald1
#define W2N 40                        // 32 h2f cols + als2 + ald2 + 6 pad

// ---------------- scratch (no allocations allowed) ----------------
__device__ __half2 g_hh[Nn * 64];      // layer1 features h = x@W1 (fp16)
__device__ __half2 g_h1h[Nn * 64];     // layer1 output h1 (fp16)
__device__ __half2 g_h2fh[Nn * 16];    // layer2 transformed features (fp16)
__device__ __align__(16) float g_als1[Nn * 4];
__device__ __align__(16) float g_ald1[Nn * 4];
__device__ float g_deg[Nn];
__device__ float g_ns2[Nn];            // per-node sum of s2 (written by agg1)
__device__ float g_s2[Ee];
__device__ float g_als2[Nn];
__device__ float g_ald2[Nn];
__device__ float g_z2[Nn];
__device__ float g_v1e[64];
__device__ float g_v2e[16];
__device__ __align__(16) float g_A1s[128 * 4];
__device__ __align__(16) float g_A1d[128 * 4];
__device__ __align__(16) float g_A2s[128];
__device__ __align__(16) float g_A2d[128];
__device__ __align__(16) __half g_W1aug[128 * W1N];
__device__ __align__(16) __half g_W2aug[128 * W2N];
// CSR structures: packed 16-byte record per slot: {half s1[4]; int src; float cs2}
__device__ int   g_off[Nn + 1];
__device__ int   g_cursor[Nn];
__device__ __align__(16) uint4 g_edge[EPt];
// scan scratch
__device__ int g_pre[Nn];
__device__ int g_bsum[512];
__device__ int g_boff[512];

__device__ __forceinline__ float elu_f(float v) { return v > 0.f ? v : expm1f(v); }
__device__ __forceinline__ float lrelu_f(float v) { return v > 0.f ? v : 0.2f * v; }

// ---- mma helpers ----
__device__ __forceinline__ unsigned int cvta_s(const void* p) {
    return (unsigned int)__cvta_generic_to_shared(p);
}
__device__ __forceinline__ void ldsm_x4(unsigned int& r0, unsigned int& r1,
                                        unsigned int& r2, unsigned int& r3,
                                        unsigned int addr) {
    asm volatile("ldmatrix.sync.aligned.m8n8.x4.shared.b16 {%0,%1,%2,%3}, [%4];"
                 : "=r"(r0), "=r"(r1), "=r"(r2), "=r"(r3) : "r"(addr));
}
__device__ __forceinline__ void ldsm_x4t(unsigned int& r0, unsigned int& r1,
                                         unsigned int& r2, unsigned int& r3,
                                         unsigned int addr) {
    asm volatile("ldmatrix.sync.aligned.m8n8.x4.trans.shared.b16 {%0,%1,%2,%3}, [%4];"
                 : "=r"(r0), "=r"(r1), "=r"(r2), "=r"(r3) : "r"(addr));
}
__device__ __forceinline__ void ldsm_x2t(unsigned int& r0, unsigned int& r1,
                                         unsigned int addr) {
    asm volatile("ldmatrix.sync.aligned.m8n8.x2.trans.shared.b16 {%0,%1}, [%2];"
                 : "=r"(r0), "=r"(r1) : "r"(addr));
}
__device__ __forceinline__ void mma_16816(float* c, unsigned int a0, unsigned int a1,
                                          unsigned int a2, unsigned int a3,
                                          unsigned int b0, unsigned int b1) {
    asm volatile(
        "mma.sync.aligned.m16n8k16.row.col.f32.f16.f16.f32 "
        "{%0,%1,%2,%3}, {%4,%5,%6,%7}, {%8,%9}, {%0,%1,%2,%3};"
        : "+f"(c[0]), "+f"(c[1]), "+f"(c[2]), "+f"(c[3])
        : "r"(a0), "r"(a1), "r"(a2), "r"(a3), "r"(b0), "r"(b1));
}

// ---------------- kernels ----------------

// precomputes: v1e/v2e, A1s/A1d/A2s/A2d, then augmented fp16 weight matrices
__global__ void prep_all(const float* __restrict__ W1e, const float* __restrict__ a1e,
                         const float* __restrict__ W2e, const float* __restrict__ a2e,
                         const float* __restrict__ W1, const float* __restrict__ a1s,
                         const float* __restrict__ a1d, const float* __restrict__ W2,
                         const float* __restrict__ a2s, const float* __restrict__ a2d) {
    int t = threadIdx.x;  // 512 threads
    if (t < 64) {
        int ed = t >> 2;
        int h = t & 3;
        float s = 0.f;
        #pragma unroll
        for (int c = 0; c < 32; c++) {
            s += W1e[ed * 128 + h * 32 + c] * a1e[h * 32 + c];
        }
        g_v1e[t] = s;
    }
    if (t < 16) {
        float s = 0.f;
        #pragma unroll
        for (int c = 0; c < 32; c++) {
            s += W2e[t * 32 + c] * a2e[c];
        }
        g_v2e[t] = s;
    }
    {
        int k = t >> 2;
        int h = t & 3;
        float s = 0.f;
        float d = 0.f;
        #pragma unroll
        for (int c = 0; c < 32; c++) {
            float w = W1[k * 128 + h * 32 + c];
            s += w * a1s[h * 32 + c];
            d += w * a1d[h * 32 + c];
        }
        g_A1s[t] = s;
        g_A1d[t] = d;
    }
    if (t < 128) {
        float s = 0.f;
        float d = 0.f;
        #pragma unroll
        for (int c = 0; c < 32; c++) {
            float w = W2[t * 32 + c];
            s += w * a2s[c];
            d += w * a2d[c];
        }
        g_A2s[t] = s;
        g_A2d[t] = d;
    }
    __syncthreads();
    for (int i = t; i < 128 * W1N; i += 512) {
        int k = i / W1N;
        int n = i - k * W1N;
        float v;
        if (n < 128) {
            v = W1[k * 128 + n];
        } else if (n < 132) {
            v = g_A1s[k * 4 + (n - 128)];
        } else {
            v = g_A1d[k * 4 + (n - 132)];
        }
        g_W1aug[i] = __float2half_rn(v);
    }
    for (int i = t; i < 128 * W2N; i += 512) {
        int k = i / W2N;
        int n = i - k * W2N;
        float v = 0.f;
        if (n < 32) {
            v = W2[k * 32 + n];
        } else if (n == 32) {
            v = g_A2s[k];
        } else if (n == 33) {
            v = g_A2d[k];
        }
        g_W2aug[i] = __float2half_rn(v);
    }
}

// degree count only
__global__ void deg_k(const int* __restrict__ ei) {
    int e = blockIdx.x * blockDim.x + threadIdx.x;
    if (e >= Ee) return;
    atomicAdd(&g_deg[ei[Ee + e]], 1.f);
}

// ---- parallel exclusive scan of deg (real edges only; self loops handled inline) ----
__global__ void scan1() {
    __shared__ int sh[256];
    int t = threadIdx.x;
    int n = blockIdx.x * 256 + t;
    int val = (n < Nn) ? (int)g_deg[n] : 0;
    sh[t] = val;
    __syncthreads();
    for (int off = 1; off < 256; off <<= 1) {
        int v = (t >= off) ? sh[t - off] : 0;
        __syncthreads();
        sh[t] += v;
        __syncthreads();
    }
    if (n < Nn) g_pre[n] = sh[t] - val;
    if (t == 255) g_bsum[blockIdx.x] = sh[255];
}
__global__ void scan2() {
    __shared__ int sh[512];
    int t = threadIdx.x;
    int val = (t < NB_SCAN) ? g_bsum[t] : 0;
    sh[t] = val;
    __syncthreads();
    for (int off = 1; off < 512; off <<= 1) {
        int v = (t >= off) ? sh[t - off] : 0;
        __syncthreads();
        sh[t] += v;
        __syncthreads();
    }
    g_boff[t] = sh[t] - val;
}
__global__ void scan3() {
    int n = blockIdx.x * 256 + threadIdx.x;
    if (n >= Nn) return;
    int off = g_boff[blockIdx.x] + g_pre[n];
    g_off[n] = off;
    g_cursor[n] = off;
    if (n == 0) g_off[Nn] = Ee;
}

// [h | als1 | ald1] = x @ W1aug via HMMA. 32 nodes per 256-thread block.
__global__ void gemm1_mma(const float* __restrict__ x) {
    __shared__ __align__(16) __half sW[128 * W1N];  // 34816 B
    __shared__ __align__(16) __half sX[32 * W1N];   //  8704 B (128 cols used)
    int tid = threadIdx.x;
    int n0 = blockIdx.x * 32;
    for (int i = tid; i < 128 * W1N / 8; i += 256) {
        ((uint4*)sW)[i] = ((const uint4*)g_W1aug)[i];
    }
    for (int i = tid; i < 2048; i += 256) {
        int r = i >> 6;
        int cp = i & 63;
        int node = n0 + r;
        float2 f = (node < Nn) ? *(const float2*)(x + (size_t)node * 128 + 2 * cp)
                               : make_float2(0.f, 0.f);
        *(__half2*)&sX[r * W1N + 2 * cp] = __floats2half2_rn(f.x, f.y);
    }
    __syncthreads();

    int w = tid >> 5;
    int lane = tid & 31;
    int mi = w & 1;
    int grp = w >> 1;
    const int baseArr[4] = {0, 5, 9, 13};
    const int cntArr[4] = {5, 4, 4, 4};
    int base = baseArr[grp];
    int cnt = cntArr[grp];

    float c[5][4];
    #pragma unroll
    for (int i = 0; i < 5; i++) {
        #pragma unroll
        for (int j = 0; j < 4; j++) {
            c[i][j] = 0.f;
        }
    }

    int arow = mi * 16 + (lane & 15);
    int acol = (lane >> 4) * 8;
    int brow0 = lane & 15;
    int bcol8 = (lane & 16) ? 8 : 0;

    for (int k0 = 0; k0 < 128; k0 += 16) {
        unsigned int a0, a1, a2, a3;
        ldsm_x4(a0, a1, a2, a3, cvta_s(&sX[arow * W1N + k0 + acol]));
        unsigned int b[5][2];
        #pragma unroll
        for (int tp = 0; tp < 2; tp++) {
            int ncol = (base + 2 * tp) * 8 + bcol8;
            ldsm_x4t(b[2 * tp][0], b[2 * tp][1], b[2 * tp + 1][0], b[2 * tp + 1][1],
                     cvta_s(&sW[(k0 + brow0) * W1N + ncol]));
        }
        if (cnt == 5) {
            int ncol = (base + 4) * 8;
            ldsm_x2t(b[4][0], b[4][1], cvta_s(&sW[(k0 + brow0) * W1N + ncol]));
        }
        #pragma unroll
        for (int t = 0; t < 5; t++) {
            if (t < cnt) {
                mma_16816(c[t], a0, a1, a2, a3, b[t][0], b[t][1]);
            }
        }
    }

    int r0 = n0 + mi * 16 + (lane >> 2);
    #pragma unroll
    for (int t = 0; t < 5; t++) {
        if (t >= cnt) continue;
        int ncol = (base + t) * 8 + 2 * (lane & 3);
        if (ncol < 128) {
            if (r0 < Nn) {
                g_hh[(size_t)r0 * 64 + (ncol >> 1)] = __floats2half2_rn(c[t][0], c[t][1]);
            }
            if (r0 + 8 < Nn) {
                g_hh[(size_t)(r0 + 8) * 64 + (ncol >> 1)] = __floats2half2_rn(c[t][2], c[t][3]);
            }
        } else if (ncol < 132) {
            int hh = ncol - 128;
            if (r0 < Nn) {
                g_als1[r0 * 4 + hh] = c[t][0];
                g_als1[r0 * 4 + hh + 1] = c[t][1];
            }
            if (r0 + 8 < Nn) {
                g_als1[(r0 + 8) * 4 + hh] = c[t][2];
                g_als1[(r0 + 8) * 4 + hh + 1] = c[t][3];
            }
        } else {
            int hh = ncol - 132;
            if (r0 < Nn) {
                g_ald1[r0 * 4 + hh] = c[t][0];
                g_ald1[r0 * 4 + hh + 1] = c[t][1];
            }
            if (r0 + 8 < Nn) {
                g_ald1[(r0 + 8) * 4 + hh] = c[t][2];
                g_ald1[(r0 + 8) * 4 + hh + 1] = c[t][3];
            }
        }
    }
}

// slim scatter: edge features -> s1 (fp16) / s2, packed CSR record. One atomic per edge.
__global__ void edge_scatter(const int* __restrict__ ei, const float* __restrict__ eattr) {
    int e = blockIdx.x * blockDim.x + threadIdx.x;
    if (e >= Ee) return;
    int src = ei[e];
    int dst = ei[Ee + e];
    int pos = atomicAdd(&g_cursor[dst], 1);
    float a[16];
    const float4* p = (const float4*)(eattr + (size_t)e * 16);
    #pragma unroll
    for (int q = 0; q < 4; q++) {
        float4 v = p[q];
        a[q * 4 + 0] = v.x;
        a[q * 4 + 1] = v.y;
        a[q * 4 + 2] = v.z;
        a[q * 4 + 3] = v.w;
    }
    float s0 = 0.f, s1 = 0.f, s2c = 0.f, s3 = 0.f, s2v = 0.f;
    #pragma unroll
    for (int ed = 0; ed < 16; ed++) {
        float av = a[ed];
        s0 += av * g_v1e[ed * 4 + 0];
        s1 += av * g_v1e[ed * 4 + 1];
        s2c += av * g_v1e[ed * 4 + 2];
        s3 += av * g_v1e[ed * 4 + 3];
        s2v += av * g_v2e[ed];
    }
    g_s2[e] = s2v;
    union { struct { __half2 sa; __half2 sb; int src; float cs2; } rec; uint4 u; } cv;
    cv.rec.sa = __floats2half2_rn(s0, s1);
    cv.rec.sb = __floats2half2_rn(s2c, s3);
    cv.rec.src = src;
    cv.rec.cs2 = s2v;
    g_edge[pos] = cv.u;
}

// warp-per-node layer1: logits+exp computed here; self-loop handled inline; writes ns2.
__global__ void agg1_csr(const float* __restrict__ b1) {
    int n = (blockIdx.x * blockDim.x + threadIdx.x) >> 5;
    if (n >= Nn) return;
    int lane = threadIdx.x & 31;
    int sub = lane >> 2;          // edge slot within 8-block
    int hq = lane & 3;            // head this lane evaluates logits for
    int l15 = lane & 15;
    int hl = l15 >> 2;            // head owning this lane's 8 channels
    int half_ = lane >> 4;
    int beg = g_off[n];
    int end = g_off[n + 1];

    float ald1n = g_ald1[n * 4 + hq];
    float als1n = g_als1[n * 4 + hq];

    float acc0 = 0.f, acc1 = 0.f, acc2 = 0.f, acc3 = 0.f;
    float acc4 = 0.f, acc5 = 0.f, acc6 = 0.f, acc7 = 0.f;
    float zl = 0.f, ss1 = 0.f, scs = 0.f;

    int idx = beg + sub;
    uint4 rec = make_uint4(0u, 0u, 0u, 0u);
    float als = 0.f;
    if (idx < end) {
        rec = g_edge[idx];
        als = g_als1[((const int*)&rec)[2] * 4 + hq];
    }
    for (int g = beg; g < end; g += 8) {
        int idxn = g + 8 + sub;
        uint4 recn = make_uint4(0u, 0u, 0u, 0u);
        if (idxn < end) {
            recn = g_edge[idxn];
        }
        // compute current block's p from (rec, als)
        float p = 0.f;
        int src = ((const int*)&rec)[2];
        if (g + sub < end) {
            float s1h = __half2float(((const __half*)&rec)[hq]);
            ss1 += s1h;
            if (hq == 0) {
                scs += ((const float*)&rec)[3];
            }
            p = __expf(lrelu_f(als + ald1n + s1h));
        }
        zl += p;
        int lim = end - g;
        #pragma unroll
        for (int t = 0; t < 8; t += 2) {
            if (t >= lim) break;
            int slot = t + half_;
            float pe = __shfl_sync(0xffffffffu, p, slot * 4 + hl);
            int se = __shfl_sync(0xffffffffu, src, slot * 4);
            uint4 v = *(const uint4*)((const char*)g_hh + (size_t)se * 256 + l15 * 16);
            float2 f0 = __half22float2(*(__half2*)&v.x);
            float2 f1 = __half22float2(*(__half2*)&v.y);
            float2 f2 = __half22float2(*(__half2*)&v.z);
            float2 f3 = __half22float2(*(__half2*)&v.w);
            acc0 += pe * f0.x;
            acc1 += pe * f0.y;
            acc2 += pe * f1.x;
            acc3 += pe * f1.y;
            acc4 += pe * f2.x;
            acc5 += pe * f2.y;
            acc6 += pe * f3.x;
            acc7 += pe * f3.y;
        }
        // dependent gather for the next block, issued after the compute
        float alsn = 0.f;
        if (idxn < end) {
            alsn = g_als1[((const int*)&recn)[2] * 4 + hq];
        }
        rec = recn;
        als = alsn;
    }
    // reductions over edge sub-slots (preserve head lanes)
    zl += __shfl_xor_sync(0xffffffffu, zl, 4);
    zl += __shfl_xor_sync(0xffffffffu, zl, 8);
    zl += __shfl_xor_sync(0xffffffffu, zl, 16);
    ss1 += __shfl_xor_sync(0xffffffffu, ss1, 4);
    ss1 += __shfl_xor_sync(0xffffffffu, ss1, 8);
    ss1 += __shfl_xor_sync(0xffffffffu, ss1, 16);
    scs += __shfl_xor_sync(0xffffffffu, scs, 4);
    scs += __shfl_xor_sync(0xffffffffu, scs, 8);
    scs += __shfl_xor_sync(0xffffffffu, scs, 16);

    float degf = (float)(end - beg);
    float invd = 1.f / fmaxf(degf, 1.f);
    // self-loop logit per head (this lane's head hq)
    float p_self = __expf(lrelu_f(als1n + ald1n + ss1 * invd));
    zl += p_self;  // zl now = z total for head hq

    // combine the two edge-parity halves of acc
    acc0 += __shfl_xor_sync(0xffffffffu, acc0, 16);
    acc1 += __shfl_xor_sync(0xffffffffu, acc1, 16);
    acc2 += __shfl_xor_sync(0xffffffffu, acc2, 16);
    acc3 += __shfl_xor_sync(0xffffffffu, acc3, 16);
    acc4 += __shfl_xor_sync(0xffffffffu, acc4, 16);
    acc5 += __shfl_xor_sync(0xffffffffu, acc5, 16);
    acc6 += __shfl_xor_sync(0xffffffffu, acc6, 16);
    acc7 += __shfl_xor_sync(0xffffffffu, acc7, 16);

    // add self-loop contribution (replicated in both halves consistently)
    {
        float pe = __shfl_sync(0xffffffffu, p_self, hl);
        uint4 v = *(const uint4*)((const char*)g_hh + (size_t)n * 256 + l15 * 16);
        float2 f0 = __half22float2(*(__half2*)&v.x);
        float2 f1 = __half22float2(*(__half2*)&v.y);
        float2 f2 = __half22float2(*(__half2*)&v.z);
        float2 f3 = __half22float2(*(__half2*)&v.w);
        acc0 += pe * f0.x;
        acc1 += pe * f0.y;
        acc2 += pe * f1.x;
        acc3 += pe * f1.y;
        acc4 += pe * f2.x;
        acc5 += pe * f2.y;
        acc6 += pe * f3.x;
        acc7 += pe * f3.y;
    }
    float inv = 1.f / __shfl_sync(0xffffffffu, zl, hl);

    if (lane == 0) {
        g_ns2[n] = scs;
    }
    if (lane < 16) {
        float4 bA = ((const float4*)b1)[l15 * 2];
        float4 bB = ((const float4*)b1)[l15 * 2 + 1];
        uint4 o;
        *(__half2*)&o.x = __floats2half2_rn(elu_f(acc0 * inv + bA.x), elu_f(acc1 * inv + bA.y));
        *(__half2*)&o.y = __floats2half2_rn(elu_f(acc2 * inv + bA.z), elu_f(acc3 * inv + bA.w));
        *(__half2*)&o.z = __floats2half2_rn(elu_f(acc4 * inv + bB.x), elu_f(acc5 * inv + bB.y));
        *(__half2*)&o.w = __floats2half2_rn(elu_f(acc6 * inv + bB.z), elu_f(acc7 * inv + bB.w));
        *(uint4*)((char*)g_h1h + (size_t)n * 256 + l15 * 16) = o;
    }
}

// [h2f | als2 | ald2] = h1 @ W2aug via HMMA. 64 nodes per 256-thread block.
__global__ void gemm2_mma() {
    __shared__ __align__(16) __half sW[128 * W2N];  // 10240 B
    __shared__ __align__(16) __half sX[64 * W1N];   // 17408 B (128 cols used)
    int tid = threadIdx.x;
    int n0 = blockIdx.x * 64;
    for (int i = tid; i < 128 * W2N / 8; i += 256) {
        ((uint4*)sW)[i] = ((const uint4*)g_W2aug)[i];
    }
    for (int i = tid; i < 1024; i += 256) {
        int r = i >> 4;
        int q = i & 15;
        int node = n0 + r;
        uint4 v = (node < Nn) ? ((const uint4*)(g_h1h + (size_t)node * 64))[q]
                              : make_uint4(0u, 0u, 0u, 0u);
        *(uint4*)&sX[r * W1N + q * 8] = v;
    }
    __syncthreads();

    int w = tid >> 5;
    int lane = tid & 31;
    int mi = w & 3;
    int grp = w >> 2;
    int base = grp ? 3 : 0;
    int cnt = grp ? 2 : 3;

    float c[3][4];
    #pragma unroll
    for (int i = 0; i < 3; i++) {
        #pragma unroll
        for (int j = 0; j < 4; j++) {
            c[i][j] = 0.f;
        }
    }

    int arow = mi * 16 + (lane & 15);
    int acol = (lane >> 4) * 8;
    int brow0 = lane & 15;
    int bcol8 = (lane & 16) ? 8 : 0;

    for (int k0 = 0; k0 < 128; k0 += 16) {
        unsigned int a0, a1, a2, a3;
        ldsm_x4(a0, a1, a2, a3, cvta_s(&sX[arow * W1N + k0 + acol]));
        unsigned int b[3][2];
        {
            int ncol = base * 8 + bcol8;
            ldsm_x4t(b[0][0], b[0][1], b[1][0], b[1][1],
                     cvta_s(&sW[(k0 + brow0) * W2N + ncol]));
        }
        if (cnt == 3) {
            int ncol = (base + 2) * 8;
            ldsm_x2t(b[2][0], b[2][1], cvta_s(&sW[(k0 + brow0) * W2N + ncol]));
        }
        #pragma unroll
        for (int t = 0; t < 3; t++) {
            if (t < cnt) {
                mma_16816(c[t], a0, a1, a2, a3, b[t][0], b[t][1]);
            }
        }
    }

    int r0 = n0 + mi * 16 + (lane >> 2);
    #pragma unroll
    for (int t = 0; t < 3; t++) {
        if (t >= cnt) continue;
        int ncol = (base + t) * 8 + 2 * (lane & 3);
        if (ncol < 32) {
            if (r0 < Nn) {
                g_h2fh[(size_t)r0 * 16 + (ncol >> 1)] = __floats2half2_rn(c[t][0], c[t][1]);
            }
            if (r0 + 8 < Nn) {
                g_h2fh[(size_t)(r0 + 8) * 16 + (ncol >> 1)] = __floats2half2_rn(c[t][2], c[t][3]);
            }
        } else if (ncol == 32) {
            if (r0 < Nn) {
                g_als2[r0] = c[t][0];
                g_ald2[r0] = c[t][1];
            }
            if (r0 + 8 < Nn) {
                g_als2[r0 + 8] = c[t][2];
                g_ald2[r0 + 8] = c[t][3];
            }
        }
    }
}

// warp-per-node layer2: packed edge record, pipelined; self-loop inline.
__global__ void agg2_csr(const float* __restrict__ b2, float* __restrict__ out) {
    int n = (blockIdx.x * blockDim.x + threadIdx.x) >> 5;
    if (n >= Nn) return;
    int lane = threadIdx.x & 31;
    int grp = lane >> 3;
    int chp = lane & 7;
    int beg = g_off[n];
    int end = g_off[n + 1];
    float ald2n = g_ald2[n];

    float a0 = 0.f;
    float a1 = 0.f;
    float a2 = 0.f;
    float a3 = 0.f;
    float zl = 0.f;

    int idx = beg + lane;
    int src = 0;
    float cs = 0.f;
    float als = 0.f;
    if (idx < end) {
        uint4 r = g_edge[idx];
        src = ((const int*)&r)[2];
        cs = ((const float*)&r)[3];
        als = g_als2[src];
    }
    for (int g = beg; g < end; g += 32) {
        int idxn = g + 32 + lane;
        int srcn = 0;
        float csn = 0.f;
        if (idxn < end) {
            uint4 r = g_edge[idxn];
            srcn = ((const int*)&r)[2];
            csn = ((const float*)&r)[3];
        }
        float p = (g + lane < end) ? __expf(lrelu_f(als + ald2n + cs)) : 0.f;
        zl += p;
        int lim = min(32, end - g);
        #pragma unroll 4
        for (int t = 0; t < 32; t += 4) {
            if (t >= lim) break;
            int slot = t + grp;
            float pe = __shfl_sync(0xffffffffu, p, slot);
            int se = __shfl_sync(0xffffffffu, src, slot);
            float2 v = *(const float2*)((const char*)g_h2fh + (size_t)se * 64 + chp * 8);
            float2 f0 = __half22float2(*(__half2*)&v.x);
            float2 f1 = __half22float2(*(__half2*)&v.y);
            a0 += pe * f0.x;
            a1 += pe * f0.y;
            a2 += pe * f1.x;
            a3 += pe * f1.y;
        }
        float alsn = 0.f;
        if (idxn < end) {
            alsn = g_als2[srcn];
        }
        src = srcn;
        cs = csn;
        als = alsn;
    }
    // combine 4 edge groups
    a0 += __shfl_xor_sync(0xffffffffu, a0, 8);
    a0 += __shfl_xor_sync(0xffffffffu, a0, 16);
    a1 += __shfl_xor_sync(0xffffffffu, a1, 8);
    a1 += __shfl_xor_sync(0xffffffffu, a1, 16);
    a2 += __shfl_xor_sync(0xffffffffu, a2, 8);
    a2 += __shfl_xor_sync(0xffffffffu, a2, 16);
    a3 += __shfl_xor_sync(0xffffffffu, a3, 8);
    a3 += __shfl_xor_sync(0xffffffffu, a3, 16);
    #pragma unroll
    for (int off = 16; off; off >>= 1) {
        zl += __shfl_xor_sync(0xffffffffu, zl, off);
    }
    // self-loop inline
    float degf = (float)(end - beg);
    float invd = 1.f / fmaxf(degf, 1.f);
    float p_self = __expf(lrelu_f(g_als2[n] + ald2n + g_ns2[n] * invd));
    zl += p_self;
    {
        float2 v = *(const float2*)((const char*)g_h2fh + (size_t)n * 64 + chp * 8);
        float2 f0 = __half22float2(*(__half2*)&v.x);
        float2 f1 = __half22float2(*(__half2*)&v.y);
        a0 += p_self * f0.x;
        a1 += p_self * f0.y;
        a2 += p_self * f1.x;
        a3 += p_self * f1.y;
    }
    if (lane == 0) g_z2[n] = zl;
    if (lane < 8) {
        float inv = 1.f / zl;
        float4 bv = ((const float4*)b2)[chp];
        float4 o;
        o.x = elu_f(a0 * inv + bv.x);
        o.y = elu_f(a1 * inv + bv.y);
        o.z = elu_f(a2 * inv + bv.z);
        o.w = elu_f(a3 * inv + bv.w);
        *(float4*)(out + (size_t)n * 32 + chp * 4) = o;
    }
}

// edge_index_sl (as float) + alpha2 recomputed in original edge order
__global__ void finalize(const int* __restrict__ ei, float* __restrict__ out) {
    int e = blockIdx.x * blockDim.x + threadIdx.x;
    if (e >= EPt) return;
    int s, d;
    float base;
    if (e < Ee) {
        s = ei[e];
        d = ei[Ee + e];
        base = g_s2[e];
    } else {
        s = e - Ee;
        d = s;
        base = g_ns2[d] / fmaxf(g_deg[d], 1.f);
    }
    float v = lrelu_f(g_als2[s] + g_ald2[d] + base);
    out[OFF_EI + e] = (float)s;
    out[OFF_EI + EPt + e] = (float)d;
    out[OFF_ALPHA + e] = __expf(v) / g_z2[d];
}

extern "C" void kernel_launch(void* const* d_in, const int* in_sizes, int n_in,
                              void* d_out, int out_size) {
    const float* x    = (const float*)d_in[0];
    const int*   ei   = (const int*)  d_in[1];
    const float* eat  = (const float*)d_in[2];
    const float* W1   = (const float*)d_in[3];
    const float* W1e  = (const float*)d_in[4];
    const float* a1s  = (const float*)d_in[5];
    const float* a1d  = (const float*)d_in[6];
    const float* a1e  = (const float*)d_in[7];
    const float* b1   = (const float*)d_in[8];
    const float* W2   = (const float*)d_in[9];
    const float* W2e  = (const float*)d_in[10];
    const float* a2s  = (const float*)d_in[11];
    const float* a2d  = (const float*)d_in[12];
    const float* a2e  = (const float*)d_in[13];
    const float* b2   = (const float*)d_in[14];
    float* out = (float*)d_out;
    (void)in_sizes;
    (void)n_in;
    (void)out_size;

    void* p_deg;
    cudaGetSymbolAddress(&p_deg, g_deg);

    // fork-join: side stream runs the deg/scan chain concurrently with prep+gemm1
    cudaStream_t sB;
    cudaStreamCreateWithFlags(&sB, cudaStreamNonBlocking);
    cudaEvent_t evF, evJ;
    cudaEventCreateWithFlags(&evF, cudaEventDisableTiming);
    cudaEventCreateWithFlags(&evJ, cudaEventDisableTiming);

    cudaEventRecord(evF, 0);
    cudaStreamWaitEvent(sB, evF, 0);

    // branch B: memset + degree + scan
    cudaMemsetAsync(p_deg, 0, (size_t)Nn * 4, sB);
    deg_k<<<(Ee + 255) / 256, 256, 0, sB>>>(ei);
    scan1<<<NB_SCAN, 256, 0, sB>>>();
    scan2<<<1, 512, 0, sB>>>();
    scan3<<<NB_SCAN, 256, 0, sB>>>();

    // branch A (legacy stream): weight prep + layer1 GEMM
    prep_all<<<1, 512>>>(W1e, a1e, W2e, a2e, W1, a1s, a1d, W2, a2s, a2d);
    gemm1_mma<<<(Nn + 31) / 32, 256>>>(x);

    cudaEventRecord(evJ, sB);
    cudaStreamWaitEvent(0, evJ, 0);

    edge_scatter<<<(Ee + 255) / 256, 256>>>(ei, eat);
    agg1_csr<<<(Nn + 7) / 8, 256>>>(b1);
    gemm2_mma<<<(Nn + 63) / 64, 256>>>();
    agg2_csr<<<(Nn + 7) / 8, 256>>>(b2, out);
    finalize<<<(EPt + 255) / 256, 256>>>(ei, out);

    cudaStreamDestroy(sB);
    cudaEventDestroy(evF);
    cudaEventDestroy(evJ);
}

// round 14
// speedup vs baseline: 3.3953x; 1.0146x over previous
#include <cuda_runtime.h>
#include <cuda_fp16.h>
#include <cstdint>
#include <math.h>

#define Nn 100000
#define Ee 1600000
#define EPt (Ee + Nn)                 // 1,700,000 edges incl. self loops
#define OFF_EI (Nn * 32)              // 3,200,000
#define OFF_ALPHA (OFF_EI + 2 * EPt)  // 6,600,000
#define NB_SCAN ((Nn + 255) / 256)    // 391
#define W1N 136                       // 128 h cols + 4 als1 + 4 ald1
#define W2N 40                        // 32 h2f cols + als2 + ald2 + 6 pad

// ---------------- scratch (no allocations allowed) ----------------
__device__ __half2 g_hh[Nn * 64];      // layer1 features h = x@W1 (fp16)
__device__ __half2 g_h1h[Nn * 64];     // layer1 output h1 (fp16)
__device__ __half2 g_h2fh[Nn * 16];    // layer2 transformed features (fp16)
__device__ __align__(16) float g_als1[Nn * 4];
__device__ __align__(16) float g_ald1[Nn * 4];
__device__ float g_deg[Nn];
__device__ float g_ns2[Nn];            // per-node sum of s2 (written by agg1)
__device__ float g_s2[Ee];
__device__ float g_als2[Nn];
__device__ float g_ald2[Nn];
__device__ __align__(8) float2 g_adz[Nn];  // (ald2, z2) packed, written by agg2
__device__ float g_v1e[64];
__device__ float g_v2e[16];
__device__ __align__(16) float g_A1s[128 * 4];
__device__ __align__(16) float g_A1d[128 * 4];
__device__ __align__(16) float g_A2s[128];
__device__ __align__(16) float g_A2d[128];
__device__ __align__(16) __half g_W1aug[128 * W1N];
__device__ __align__(16) __half g_W2aug[128 * W2N];
// CSR structures: packed 16-byte record per slot: {half s1[4]; int src; float cs2}
__device__ int   g_off[Nn + 1];
__device__ int   g_cursor[Nn];
__device__ __align__(16) uint4 g_edge[EPt];
// decoupled-lookback scan tiles: bits[63:62] = status (0 invalid, 1 aggregate, 2 prefix)
__device__ unsigned long long g_tile[NB_SCAN];

__device__ __forceinline__ float elu_f(float v) { return v > 0.f ? v : expm1f(v); }
__device__ __forceinline__ float lrelu_f(float v) { return v > 0.f ? v : 0.2f * v; }

// ---- mma helpers ----
__device__ __forceinline__ unsigned int cvta_s(const void* p) {
    return (unsigned int)__cvta_generic_to_shared(p);
}
__device__ __forceinline__ void ldsm_x4(unsigned int& r0, unsigned int& r1,
                                        unsigned int& r2, unsigned int& r3,
                                        unsigned int addr) {
    asm volatile("ldmatrix.sync.aligned.m8n8.x4.shared.b16 {%0,%1,%2,%3}, [%4];"
                 : "=r"(r0), "=r"(r1), "=r"(r2), "=r"(r3) : "r"(addr));
}
__device__ __forceinline__ void ldsm_x4t(unsigned int& r0, unsigned int& r1,
                                         unsigned int& r2, unsigned int& r3,
                                         unsigned int addr) {
    asm volatile("ldmatrix.sync.aligned.m8n8.x4.trans.shared.b16 {%0,%1,%2,%3}, [%4];"
                 : "=r"(r0), "=r"(r1), "=r"(r2), "=r"(r3) : "r"(addr));
}
__device__ __forceinline__ void ldsm_x2t(unsigned int& r0, unsigned int& r1,
                                         unsigned int addr) {
    asm volatile("ldmatrix.sync.aligned.m8n8.x2.trans.shared.b16 {%0,%1}, [%2];"
                 : "=r"(r0), "=r"(r1) : "r"(addr));
}
__device__ __forceinline__ void mma_16816(float* c, unsigned int a0, unsigned int a1,
                                          unsigned int a2, unsigned int a3,
                                          unsigned int b0, unsigned int b1) {
    asm volatile(
        "mma.sync.aligned.m16n8k16.row.col.f32.f16.f16.f32 "
        "{%0,%1,%2,%3}, {%4,%5,%6,%7}, {%8,%9}, {%0,%1,%2,%3};"
        : "+f"(c[0]), "+f"(c[1]), "+f"(c[2]), "+f"(c[3])
        : "r"(a0), "r"(a1), "r"(a2), "r"(a3), "r"(b0), "r"(b1));
}

// ---------------- kernels ----------------

// precomputes: v1e/v2e, A1s/A1d/A2s/A2d, then augmented fp16 weight matrices
__global__ void prep_all(const float* __restrict__ W1e, const float* __restrict__ a1e,
                         const float* __restrict__ W2e, const float* __restrict__ a2e,
                         const float* __restrict__ W1, const float* __restrict__ a1s,
                         const float* __restrict__ a1d, const float* __restrict__ W2,
                         const float* __restrict__ a2s, const float* __restrict__ a2d) {
    int t = threadIdx.x;  // 512 threads
    if (t < 64) {
        int ed = t >> 2;
        int h = t & 3;
        float s = 0.f;
        #pragma unroll
        for (int c = 0; c < 32; c++) {
            s += W1e[ed * 128 + h * 32 + c] * a1e[h * 32 + c];
        }
        g_v1e[t] = s;
    }
    if (t < 16) {
        float s = 0.f;
        #pragma unroll
        for (int c = 0; c < 32; c++) {
            s += W2e[t * 32 + c] * a2e[c];
        }
        g_v2e[t] = s;
    }
    {
        int k = t >> 2;
        int h = t & 3;
        float s = 0.f;
        float d = 0.f;
        #pragma unroll
        for (int c = 0; c < 32; c++) {
            float w = W1[k * 128 + h * 32 + c];
            s += w * a1s[h * 32 + c];
            d += w * a1d[h * 32 + c];
        }
        g_A1s[t] = s;
        g_A1d[t] = d;
    }
    if (t < 128) {
        float s = 0.f;
        float d = 0.f;
        #pragma unroll
        for (int c = 0; c < 32; c++) {
            float w = W2[t * 32 + c];
            s += w * a2s[c];
            d += w * a2d[c];
        }
        g_A2s[t] = s;
        g_A2d[t] = d;
    }
    __syncthreads();
    for (int i = t; i < 128 * W1N; i += 512) {
        int k = i / W1N;
        int n = i - k * W1N;
        float v;
        if (n < 128) {
            v = W1[k * 128 + n];
        } else if (n < 132) {
            v = g_A1s[k * 4 + (n - 128)];
        } else {
            v = g_A1d[k * 4 + (n - 132)];
        }
        g_W1aug[i] = __float2half_rn(v);
    }
    for (int i = t; i < 128 * W2N; i += 512) {
        int k = i / W2N;
        int n = i - k * W2N;
        float v = 0.f;
        if (n < 32) {
            v = W2[k * 32 + n];
        } else if (n == 32) {
            v = g_A2s[k];
        } else if (n == 33) {
            v = g_A2d[k];
        }
        g_W2aug[i] = __float2half_rn(v);
    }
}

// degree count only
__global__ void deg_k(const int* __restrict__ ei) {
    int e = blockIdx.x * blockDim.x + threadIdx.x;
    if (e >= Ee) return;
    atomicAdd(&g_deg[ei[Ee + e]], 1.f);
}

// single-pass decoupled-lookback exclusive scan of deg -> g_off, g_cursor
__global__ void scan_lookback() {
    __shared__ int sh[256];
    __shared__ int s_prev;
    int b = blockIdx.x;
    int t = threadIdx.x;
    int n = b * 256 + t;
    int val = (n < Nn) ? (int)g_deg[n] : 0;
    sh[t] = val;
    __syncthreads();
    for (int off = 1; off < 256; off <<= 1) {
        int v = (t >= off) ? sh[t - off] : 0;
        __syncthreads();
        sh[t] += v;
        __syncthreads();
    }
    int total = sh[255];
    if (t == 0) {
        // publish aggregate
        atomicExch(&g_tile[b], (1ull << 62) | (unsigned int)total);
        // lookback
        int prev = 0;
        for (int i = b - 1; i >= 0;) {
            unsigned long long v;
            do {
                v = atomicAdd(&g_tile[i], 0ull);
            } while ((v >> 62) == 0ull);
            prev += (int)(v & 0xffffffffull);
            if ((v >> 62) == 2ull) break;
            i--;
        }
        // publish inclusive prefix
        atomicExch(&g_tile[b], (2ull << 62) | (unsigned int)(prev + total));
        s_prev = prev;
    }
    __syncthreads();
    int off = s_prev + sh[t] - val;
    if (n < Nn) {
        g_off[n] = off;
        g_cursor[n] = off;
    }
    if (n == 0) g_off[Nn] = Ee;
}

// edge_index_sl (as float) — no dependencies, runs early overlapped
__global__ void ei_out(const int* __restrict__ ei, float* __restrict__ out) {
    int e = blockIdx.x * blockDim.x + threadIdx.x;
    if (e >= EPt) return;
    int s, d;
    if (e < Ee) {
        s = ei[e];
        d = ei[Ee + e];
    } else {
        s = e - Ee;
        d = s;
    }
    out[OFF_EI + e] = (float)s;
    out[OFF_EI + EPt + e] = (float)d;
}

// [h | als1 | ald1] = x @ W1aug via HMMA. 32 nodes per 256-thread block.
__global__ void gemm1_mma(const float* __restrict__ x) {
    __shared__ __align__(16) __half sW[128 * W1N];  // 34816 B
    __shared__ __align__(16) __half sX[32 * W1N];   //  8704 B (128 cols used)
    int tid = threadIdx.x;
    int n0 = blockIdx.x * 32;
    for (int i = tid; i < 128 * W1N / 8; i += 256) {
        ((uint4*)sW)[i] = ((const uint4*)g_W1aug)[i];
    }
    for (int i = tid; i < 2048; i += 256) {
        int r = i >> 6;
        int cp = i & 63;
        int node = n0 + r;
        float2 f = (node < Nn) ? *(const float2*)(x + (size_t)node * 128 + 2 * cp)
                               : make_float2(0.f, 0.f);
        *(__half2*)&sX[r * W1N + 2 * cp] = __floats2half2_rn(f.x, f.y);
    }
    __syncthreads();

    int w = tid >> 5;
    int lane = tid & 31;
    int mi = w & 1;
    int grp = w >> 1;
    const int baseArr[4] = {0, 5, 9, 13};
    const int cntArr[4] = {5, 4, 4, 4};
    int base = baseArr[grp];
    int cnt = cntArr[grp];

    float c[5][4];
    #pragma unroll
    for (int i = 0; i < 5; i++) {
        #pragma unroll
        for (int j = 0; j < 4; j++) {
            c[i][j] = 0.f;
        }
    }

    int arow = mi * 16 + (lane & 15);
    int acol = (lane >> 4) * 8;
    int brow0 = lane & 15;
    int bcol8 = (lane & 16) ? 8 : 0;

    for (int k0 = 0; k0 < 128; k0 += 16) {
        unsigned int a0, a1, a2, a3;
        ldsm_x4(a0, a1, a2, a3, cvta_s(&sX[arow * W1N + k0 + acol]));
        unsigned int b[5][2];
        #pragma unroll
        for (int tp = 0; tp < 2; tp++) {
            int ncol = (base + 2 * tp) * 8 + bcol8;
            ldsm_x4t(b[2 * tp][0], b[2 * tp][1], b[2 * tp + 1][0], b[2 * tp + 1][1],
                     cvta_s(&sW[(k0 + brow0) * W1N + ncol]));
        }
        if (cnt == 5) {
            int ncol = (base + 4) * 8;
            ldsm_x2t(b[4][0], b[4][1], cvta_s(&sW[(k0 + brow0) * W1N + ncol]));
        }
        #pragma unroll
        for (int t = 0; t < 5; t++) {
            if (t < cnt) {
                mma_16816(c[t], a0, a1, a2, a3, b[t][0], b[t][1]);
            }
        }
    }

    int r0 = n0 + mi * 16 + (lane >> 2);
    #pragma unroll
    for (int t = 0; t < 5; t++) {
        if (t >= cnt) continue;
        int ncol = (base + t) * 8 + 2 * (lane & 3);
        if (ncol < 128) {
            if (r0 < Nn) {
                g_hh[(size_t)r0 * 64 + (ncol >> 1)] = __floats2half2_rn(c[t][0], c[t][1]);
            }
            if (r0 + 8 < Nn) {
                g_hh[(size_t)(r0 + 8) * 64 + (ncol >> 1)] = __floats2half2_rn(c[t][2], c[t][3]);
            }
        } else if (ncol < 132) {
            int hh = ncol - 128;
            if (r0 < Nn) {
                g_als1[r0 * 4 + hh] = c[t][0];
                g_als1[r0 * 4 + hh + 1] = c[t][1];
            }
            if (r0 + 8 < Nn) {
                g_als1[(r0 + 8) * 4 + hh] = c[t][2];
                g_als1[(r0 + 8) * 4 + hh + 1] = c[t][3];
            }
        } else {
            int hh = ncol - 132;
            if (r0 < Nn) {
                g_ald1[r0 * 4 + hh] = c[t][0];
                g_ald1[r0 * 4 + hh + 1] = c[t][1];
            }
            if (r0 + 8 < Nn) {
                g_ald1[(r0 + 8) * 4 + hh] = c[t][2];
                g_ald1[(r0 + 8) * 4 + hh + 1] = c[t][3];
            }
        }
    }
}

// slim scatter: edge features -> s1 (fp16) / s2, packed CSR record. One atomic per edge.
__global__ void edge_scatter(const int* __restrict__ ei, const float* __restrict__ eattr) {
    int e = blockIdx.x * blockDim.x + threadIdx.x;
    if (e >= Ee) return;
    int src = ei[e];
    int dst = ei[Ee + e];
    int pos = atomicAdd(&g_cursor[dst], 1);
    float a[16];
    const float4* p = (const float4*)(eattr + (size_t)e * 16);
    #pragma unroll
    for (int q = 0; q < 4; q++) {
        float4 v = p[q];
        a[q * 4 + 0] = v.x;
        a[q * 4 + 1] = v.y;
        a[q * 4 + 2] = v.z;
        a[q * 4 + 3] = v.w;
    }
    float s0 = 0.f, s1 = 0.f, s2c = 0.f, s3 = 0.f, s2v = 0.f;
    #pragma unroll
    for (int ed = 0; ed < 16; ed++) {
        float av = a[ed];
        s0 += av * g_v1e[ed * 4 + 0];
        s1 += av * g_v1e[ed * 4 + 1];
        s2c += av * g_v1e[ed * 4 + 2];
        s3 += av * g_v1e[ed * 4 + 3];
        s2v += av * g_v2e[ed];
    }
    g_s2[e] = s2v;
    union { struct { __half2 sa; __half2 sb; int src; float cs2; } rec; uint4 u; } cv;
    cv.rec.sa = __floats2half2_rn(s0, s1);
    cv.rec.sb = __floats2half2_rn(s2c, s3);
    cv.rec.src = src;
    cv.rec.cs2 = s2v;
    g_edge[pos] = cv.u;
}

// warp-per-node layer1: logits+exp computed here; self-loop handled inline; writes ns2.
__global__ void agg1_csr(const float* __restrict__ b1) {
    int n = (blockIdx.x * blockDim.x + threadIdx.x) >> 5;
    if (n >= Nn) return;
    int lane = threadIdx.x & 31;
    int sub = lane >> 2;          // edge slot within 8-block
    int hq = lane & 3;            // head this lane evaluates logits for
    int l15 = lane & 15;
    int hl = l15 >> 2;            // head owning this lane's 8 channels
    int half_ = lane >> 4;
    int beg = g_off[n];
    int end = g_off[n + 1];

    float ald1n = g_ald1[n * 4 + hq];
    float als1n = g_als1[n * 4 + hq];

    float acc0 = 0.f, acc1 = 0.f, acc2 = 0.f, acc3 = 0.f;
    float acc4 = 0.f, acc5 = 0.f, acc6 = 0.f, acc7 = 0.f;
    float zl = 0.f, ss1 = 0.f, scs = 0.f;

    int idx = beg + sub;
    uint4 rec = make_uint4(0u, 0u, 0u, 0u);
    float als = 0.f;
    if (idx < end) {
        rec = g_edge[idx];
        als = g_als1[((const int*)&rec)[2] * 4 + hq];
    }
    for (int g = beg; g < end; g += 8) {
        int idxn = g + 8 + sub;
        uint4 recn = make_uint4(0u, 0u, 0u, 0u);
        if (idxn < end) {
            recn = g_edge[idxn];
        }
        float p = 0.f;
        int src = ((const int*)&rec)[2];
        if (g + sub < end) {
            float s1h = __half2float(((const __half*)&rec)[hq]);
            ss1 += s1h;
            if (hq == 0) {
                scs += ((const float*)&rec)[3];
            }
            p = __expf(lrelu_f(als + ald1n + s1h));
        }
        zl += p;
        int lim = end - g;
        #pragma unroll
        for (int t = 0; t < 8; t += 2) {
            if (t >= lim) break;
            int slot = t + half_;
            float pe = __shfl_sync(0xffffffffu, p, slot * 4 + hl);
            int se = __shfl_sync(0xffffffffu, src, slot * 4);
            uint4 v = *(const uint4*)((const char*)g_hh + (size_t)se * 256 + l15 * 16);
            float2 f0 = __half22float2(*(__half2*)&v.x);
            float2 f1 = __half22float2(*(__half2*)&v.y);
            float2 f2 = __half22float2(*(__half2*)&v.z);
            float2 f3 = __half22float2(*(__half2*)&v.w);
            acc0 += pe * f0.x;
            acc1 += pe * f0.y;
            acc2 += pe * f1.x;
            acc3 += pe * f1.y;
            acc4 += pe * f2.x;
            acc5 += pe * f2.y;
            acc6 += pe * f3.x;
            acc7 += pe * f3.y;
        }
        float alsn = 0.f;
        if (idxn < end) {
            alsn = g_als1[((const int*)&recn)[2] * 4 + hq];
        }
        rec = recn;
        als = alsn;
    }
    // reductions over edge sub-slots (preserve head lanes)
    zl += __shfl_xor_sync(0xffffffffu, zl, 4);
    zl += __shfl_xor_sync(0xffffffffu, zl, 8);
    zl += __shfl_xor_sync(0xffffffffu, zl, 16);
    ss1 += __shfl_xor_sync(0xffffffffu, ss1, 4);
    ss1 += __shfl_xor_sync(0xffffffffu, ss1, 8);
    ss1 += __shfl_xor_sync(0xffffffffu, ss1, 16);
    scs += __shfl_xor_sync(0xffffffffu, scs, 4);
    scs += __shfl_xor_sync(0xffffffffu, scs, 8);
    scs += __shfl_xor_sync(0xffffffffu, scs, 16);

    float degf = (float)(end - beg);
    float invd = 1.f / fmaxf(degf, 1.f);
    float p_self = __expf(lrelu_f(als1n + ald1n + ss1 * invd));
    zl += p_self;

    acc0 += __shfl_xor_sync(0xffffffffu, acc0, 16);
    acc1 += __shfl_xor_sync(0xffffffffu, acc1, 16);
    acc2 += __shfl_xor_sync(0xffffffffu, acc2, 16);
    acc3 += __shfl_xor_sync(0xffffffffu, acc3, 16);
    acc4 += __shfl_xor_sync(0xffffffffu, acc4, 16);
    acc5 += __shfl_xor_sync(0xffffffffu, acc5, 16);
    acc6 += __shfl_xor_sync(0xffffffffu, acc6, 16);
    acc7 += __shfl_xor_sync(0xffffffffu, acc7, 16);

    {
        float pe = __shfl_sync(0xffffffffu, p_self, hl);
        uint4 v = *(const uint4*)((const char*)g_hh + (size_t)n * 256 + l15 * 16);
        float2 f0 = __half22float2(*(__half2*)&v.x);
        float2 f1 = __half22float2(*(__half2*)&v.y);
        float2 f2 = __half22float2(*(__half2*)&v.z);
        float2 f3 = __half22float2(*(__half2*)&v.w);
        acc0 += pe * f0.x;
        acc1 += pe * f0.y;
        acc2 += pe * f1.x;
        acc3 += pe * f1.y;
        acc4 += pe * f2.x;
        acc5 += pe * f2.y;
        acc6 += pe * f3.x;
        acc7 += pe * f3.y;
    }
    float inv = 1.f / __shfl_sync(0xffffffffu, zl, hl);

    if (lane == 0) {
        g_ns2[n] = scs;
    }
    if (lane < 16) {
        float4 bA = ((const float4*)b1)[l15 * 2];
        float4 bB = ((const float4*)b1)[l15 * 2 + 1];
        uint4 o;
        *(__half2*)&o.x = __floats2half2_rn(elu_f(acc0 * inv + bA.x), elu_f(acc1 * inv + bA.y));
        *(__half2*)&o.y = __floats2half2_rn(elu_f(acc2 * inv + bA.z), elu_f(acc3 * inv + bA.w));
        *(__half2*)&o.z = __floats2half2_rn(elu_f(acc4 * inv + bB.x), elu_f(acc5 * inv + bB.y));
        *(__half2*)&o.w = __floats2half2_rn(elu_f(acc6 * inv + bB.z), elu_f(acc7 * inv + bB.w));
        *(uint4*)((char*)g_h1h + (size_t)n * 256 + l15 * 16) = o;
    }
}

// [h2f | als2 | ald2] = h1 @ W2aug via HMMA. 64 nodes per 256-thread block.
__global__ void gemm2_mma() {
    __shared__ __align__(16) __half sW[128 * W2N];  // 10240 B
    __shared__ __align__(16) __half sX[64 * W1N];   // 17408 B (128 cols used)
    int tid = threadIdx.x;
    int n0 = blockIdx.x * 64;
    for (int i = tid; i < 128 * W2N / 8; i += 256) {
        ((uint4*)sW)[i] = ((const uint4*)g_W2aug)[i];
    }
    for (int i = tid; i < 1024; i += 256) {
        int r = i >> 4;
        int q = i & 15;
        int node = n0 + r;
        uint4 v = (node < Nn) ? ((const uint4*)(g_h1h + (size_t)node * 64))[q]
                              : make_uint4(0u, 0u, 0u, 0u);
        *(uint4*)&sX[r * W1N + q * 8] = v;
    }
    __syncthreads();

    int w = tid >> 5;
    int lane = tid & 31;
    int mi = w & 3;
    int grp = w >> 2;
    int base = grp ? 3 : 0;
    int cnt = grp ? 2 : 3;

    float c[3][4];
    #pragma unroll
    for (int i = 0; i < 3; i++) {
        #pragma unroll
        for (int j = 0; j < 4; j++) {
            c[i][j] = 0.f;
        }
    }

    int arow = mi * 16 + (lane & 15);
    int acol = (lane >> 4) * 8;
    int brow0 = lane & 15;
    int bcol8 = (lane & 16) ? 8 : 0;

    for (int k0 = 0; k0 < 128; k0 += 16) {
        unsigned int a0, a1, a2, a3;
        ldsm_x4(a0, a1, a2, a3, cvta_s(&sX[arow * W1N + k0 + acol]));
        unsigned int b[3][2];
        {
            int ncol = base * 8 + bcol8;
            ldsm_x4t(b[0][0], b[0][1], b[1][0], b[1][1],
                     cvta_s(&sW[(k0 + brow0) * W2N + ncol]));
        }
        if (cnt == 3) {
            int ncol = (base + 2) * 8;
            ldsm_x2t(b[2][0], b[2][1], cvta_s(&sW[(k0 + brow0) * W2N + ncol]));
        }
        #pragma unroll
        for (int t = 0; t < 3; t++) {
            if (t < cnt) {
                mma_16816(c[t], a0, a1, a2, a3, b[t][0], b[t][1]);
            }
        }
    }

    int r0 = n0 + mi * 16 + (lane >> 2);
    #pragma unroll
    for (int t = 0; t < 3; t++) {
        if (t >= cnt) continue;
        int ncol = (base + t) * 8 + 2 * (lane & 3);
        if (ncol < 32) {
            if (r0 < Nn) {
                g_h2fh[(size_t)r0 * 16 + (ncol >> 1)] = __floats2half2_rn(c[t][0], c[t][1]);
            }
            if (r0 + 8 < Nn) {
                g_h2fh[(size_t)(r0 + 8) * 16 + (ncol >> 1)] = __floats2half2_rn(c[t][2], c[t][3]);
            }
        } else if (ncol == 32) {
            if (r0 < Nn) {
                g_als2[r0] = c[t][0];
                g_ald2[r0] = c[t][1];
            }
            if (r0 + 8 < Nn) {
                g_als2[r0 + 8] = c[t][2];
                g_ald2[r0 + 8] = c[t][3];
            }
        }
    }
}

// warp-per-node layer2: packed edge record, pipelined; self-loop inline; writes (ald2,z2).
__global__ void agg2_csr(const float* __restrict__ b2, float* __restrict__ out) {
    int n = (blockIdx.x * blockDim.x + threadIdx.x) >> 5;
    if (n >= Nn) return;
    int lane = threadIdx.x & 31;
    int grp = lane >> 3;
    int chp = lane & 7;
    int beg = g_off[n];
    int end = g_off[n + 1];
    float ald2n = g_ald2[n];

    float a0 = 0.f;
    float a1 = 0.f;
    float a2 = 0.f;
    float a3 = 0.f;
    float zl = 0.f;

    int idx = beg + lane;
    int src = 0;
    float cs = 0.f;
    float als = 0.f;
    if (idx < end) {
        uint4 r = g_edge[idx];
        src = ((const int*)&r)[2];
        cs = ((const float*)&r)[3];
        als = g_als2[src];
    }
    for (int g = beg; g < end; g += 32) {
        int idxn = g + 32 + lane;
        int srcn = 0;
        float csn = 0.f;
        if (idxn < end) {
            uint4 r = g_edge[idxn];
            srcn = ((const int*)&r)[2];
            csn = ((const float*)&r)[3];
        }
        float p = (g + lane < end) ? __expf(lrelu_f(als + ald2n + cs)) : 0.f;
        zl += p;
        int lim = min(32, end - g);
        #pragma unroll 4
        for (int t = 0; t < 32; t += 4) {
            if (t >= lim) break;
            int slot = t + grp;
            float pe = __shfl_sync(0xffffffffu, p, slot);
            int se = __shfl_sync(0xffffffffu, src, slot);
            float2 v = *(const float2*)((const char*)g_h2fh + (size_t)se * 64 + chp * 8);
            float2 f0 = __half22float2(*(__half2*)&v.x);
            float2 f1 = __half22float2(*(__half2*)&v.y);
            a0 += pe * f0.x;
            a1 += pe * f0.y;
            a2 += pe * f1.x;
            a3 += pe * f1.y;
        }
        float alsn = 0.f;
        if (idxn < end) {
            alsn = g_als2[srcn];
        }
        src = srcn;
        cs = csn;
        als = alsn;
    }
    a0 += __shfl_xor_sync(0xffffffffu, a0, 8);
    a0 += __shfl_xor_sync(0xffffffffu, a0, 16);
    a1 += __shfl_xor_sync(0xffffffffu, a1, 8);
    a1 += __shfl_xor_sync(0xffffffffu, a1, 16);
    a2 += __shfl_xor_sync(0xffffffffu, a2, 8);
    a2 += __shfl_xor_sync(0xffffffffu, a2, 16);
    a3 += __shfl_xor_sync(0xffffffffu, a3, 8);
    a3 += __shfl_xor_sync(0xffffffffu, a3, 16);
    #pragma unroll
    for (int off = 16; off; off >>= 1) {
        zl += __shfl_xor_sync(0xffffffffu, zl, off);
    }
    // self-loop inline
    float degf = (float)(end - beg);
    float invd = 1.f / fmaxf(degf, 1.f);
    float p_self = __expf(lrelu_f(g_als2[n] + ald2n + g_ns2[n] * invd));
    zl += p_self;
    {
        float2 v = *(const float2*)((const char*)g_h2fh + (size_t)n * 64 + chp * 8);
        float2 f0 = __half22float2(*(__half2*)&v.x);
        float2 f1 = __half22float2(*(__half2*)&v.y);
        a0 += p_self * f0.x;
        a1 += p_self * f0.y;
        a2 += p_self * f1.x;
        a3 += p_self * f1.y;
    }
    if (lane == 0) g_adz[n] = make_float2(ald2n, zl);
    if (lane < 8) {
        float inv = 1.f / zl;
        float4 bv = ((const float4*)b2)[chp];
        float4 o;
        o.x = elu_f(a0 * inv + bv.x);
        o.y = elu_f(a1 * inv + bv.y);
        o.z = elu_f(a2 * inv + bv.z);
        o.w = elu_f(a3 * inv + bv.w);
        *(float4*)(out + (size_t)n * 32 + chp * 4) = o;
    }
}

// alpha2 in original edge order (2 random gathers per edge: als2[s], adz[d])
__global__ void alpha_k(const int* __restrict__ ei, float* __restrict__ out) {
    int e = blockIdx.x * blockDim.x + threadIdx.x;
    if (e >= EPt) return;
    int s, d;
    float base;
    if (e < Ee) {
        s = ei[e];
        d = ei[Ee + e];
        base = g_s2[e];
    } else {
        s = e - Ee;
        d = s;
        base = g_ns2[d] / fmaxf(g_deg[d], 1.f);
    }
    float2 adz = g_adz[d];
    float v = lrelu_f(g_als2[s] + adz.x + base);
    out[OFF_ALPHA + e] = __expf(v) / adz.y;
}

extern "C" void kernel_launch(void* const* d_in, const int* in_sizes, int n_in,
                              void* d_out, int out_size) {
    const float* x    = (const float*)d_in[0];
    const int*   ei   = (const int*)  d_in[1];
    const float* eat  = (const float*)d_in[2];
    const float* W1   = (const float*)d_in[3];
    const float* W1e  = (const float*)d_in[4];
    const float* a1s  = (const float*)d_in[5];
    const float* a1d  = (const float*)d_in[6];
    const float* a1e  = (const float*)d_in[7];
    const float* b1   = (const float*)d_in[8];
    const float* W2   = (const float*)d_in[9];
    const float* W2e  = (const float*)d_in[10];
    const float* a2s  = (const float*)d_in[11];
    const float* a2d  = (const float*)d_in[12];
    const float* a2e  = (const float*)d_in[13];
    const float* b2   = (const float*)d_in[14];
    float* out = (float*)d_out;
    (void)in_sizes;
    (void)n_in;
    (void)out_size;

    void* p_deg;
    void* p_tile;
    cudaGetSymbolAddress(&p_deg, g_deg);
    cudaGetSymbolAddress(&p_tile, g_tile);

    // fork-join: side stream runs ei_out + deg/scan chain concurrently with prep+gemm1
    cudaStream_t sB;
    cudaStreamCreateWithFlags(&sB, cudaStreamNonBlocking);
    cudaEvent_t evF, evJ;
    cudaEventCreateWithFlags(&evF, cudaEventDisableTiming);
    cudaEventCreateWithFlags(&evJ, cudaEventDisableTiming);

    cudaEventRecord(evF, 0);
    cudaStreamWaitEvent(sB, evF, 0);

    // branch B: memsets + ei_out + degree + single-pass scan
    cudaMemsetAsync(p_deg, 0, (size_t)Nn * 4, sB);
    cudaMemsetAsync(p_tile, 0, (size_t)NB_SCAN * 8, sB);
    ei_out<<<(EPt + 255) / 256, 256, 0, sB>>>(ei, out);
    deg_k<<<(Ee + 255) / 256, 256, 0, sB>>>(ei);
    scan_lookback<<<NB_SCAN, 256, 0, sB>>>();

    // branch A (legacy stream): weight prep + layer1 GEMM
    prep_all<<<1, 512>>>(W1e, a1e, W2e, a2e, W1, a1s, a1d, W2, a2s, a2d);
    gemm1_mma<<<(Nn + 31) / 32, 256>>>(x);

    cudaEventRecord(evJ, sB);
    cudaStreamWaitEvent(0, evJ, 0);

    edge_scatter<<<(Ee + 255) / 256, 256>>>(ei, eat);
    agg1_csr<<<(Nn + 7) / 8, 256>>>(b1);
    gemm2_mma<<<(Nn + 63) / 64, 256>>>();
    agg2_csr<<<(Nn + 7) / 8, 256>>>(b2, out);
    alpha_k<<<(EPt + 255) / 256, 256>>>(ei, out);

    cudaStreamDestroy(sB);
    cudaEventDestroy(evF);
    cudaEventDestroy(evJ);
}